// round 12
// baseline (speedup 1.0000x reference)
#include <cuda_runtime.h>
#include <cuda_fp16.h>
#include <math.h>
#include <stdint.h>

// ---------------- Problem constants ----------------
static constexpr int BB = 2;
static constexpr int TT = 1024;
static constexpr int EE = 1024;
static constexpr int HH = 16;
static constexpr int DD = 64;
static constexpr int LL = 12;
static constexpr int VV = 50257;
static constexpr int MM = BB * TT;
static constexpr long long NBTV = (long long)MM * VV;
static constexpr int NU = 40;
static constexpr float L2E = 1.44269504088896340736f;

// ---------------- Scratch ----------------
__device__ float g_h   [(size_t)MM * EE];
__device__ __half g_xh  [(size_t)MM * EE];
__device__ __half g_qkvh[(size_t)MM * 3 * EE];
__device__ __half g_attnh[(size_t)MM * EE];
__device__ __half g_mlph [(size_t)MM * 4 * EE];
__device__ float g_nll [MM];
__device__ float g_logits[(size_t)MM * VV];
__device__ float g_pO[(size_t)BB * HH * NU * 64 * 64];
__device__ float g_pm[(size_t)BB * HH * NU * 64];
__device__ float g_pl[(size_t)BB * HH * NU * 64];
__device__ __half g_qkvT [(size_t)LL * 3 * EE * EE];
__device__ __half g_oT   [(size_t)LL * EE * EE];
__device__ __half g_upT  [(size_t)LL * 4 * EE * EE];
__device__ __half g_downT[(size_t)LL * 4 * EE * EE];
__device__ __half g_wteH [(size_t)VV * EE];

__constant__ int c_qi[NU] = {15,15,15,15, 14,14,14,14, 13,13,13,13, 12,12,12,12,
                             11,11,11, 10,10,10, 9,9,9, 8,8,8, 7,7, 6,6, 5,5, 4,4,
                             3, 2, 1, 0};
__constant__ int c_sp[NU] = {0,1,2,3, 0,1,2,3, 0,1,2,3, 0,1,2,3,
                             0,1,2, 0,1,2, 0,1,2, 0,1,2, 0,1, 0,1, 0,1, 0,1,
                             0, 0, 0, 0};
__constant__ int c_u0[16] = {39,38,37,36, 34,32,30,28, 25,22,19,16, 12,8,4,0};
__constant__ int c_ns[16] = {1,1,1,1, 2,2,2,2, 3,3,3,3, 4,4,4,4};

// ---------------- Helpers ----------------
__device__ __forceinline__ uint32_t smem_u32(const void* p) {
    uint32_t r;
    asm("{ .reg .u64 t; cvta.to.shared.u64 t, %1; cvt.u32.u64 %0, t; }" : "=r"(r) : "l"(p));
    return r;
}

__device__ __forceinline__ void mma_f16(float c[4], const uint32_t a[4], const uint32_t b[2]) {
    asm volatile(
        "mma.sync.aligned.m16n8k16.row.col.f32.f16.f16.f32 "
        "{%0,%1,%2,%3}, {%4,%5,%6,%7}, {%8,%9}, {%0,%1,%2,%3};"
        : "+f"(c[0]), "+f"(c[1]), "+f"(c[2]), "+f"(c[3])
        : "r"(a[0]), "r"(a[1]), "r"(a[2]), "r"(a[3]), "r"(b[0]), "r"(b[1]));
}

__device__ __forceinline__ void ldsm_x4(uint32_t r[4], uint32_t addr) {
    asm volatile("ldmatrix.sync.aligned.m8n8.x4.shared.b16 {%0,%1,%2,%3}, [%4];"
        : "=r"(r[0]), "=r"(r[1]), "=r"(r[2]), "=r"(r[3]) : "r"(addr));
}

__device__ __forceinline__ void st_half4(__half* p, float a, float b, float c, float d) {
    __half2 lo = __floats2half2_rn(a, b);
    __half2 hi = __floats2half2_rn(c, d);
    uint2 v = make_uint2(*(uint32_t*)&lo, *(uint32_t*)&hi);
    *(uint2*)p = v;
}

// two exps via one MUFU op: returns packed half2 {exp2(a), exp2(b)} for fp32 args
__device__ __forceinline__ uint32_t ex2_h2(float a, float b) {
    __half2 h = __floats2half2_rn(a, b);
    uint32_t u = *(uint32_t*)&h, o;
    asm("ex2.approx.f16x2 %0, %1;" : "=r"(o) : "r"(u));
    return o;
}

// ---------------- Weight prep: W[K,N] fp32 -> WT[N,K] half ----------------
__global__ void transh_k(const float* __restrict__ W, __half* __restrict__ WT,
                         int K, int N) {
    __shared__ float tl[32][33];
    size_t off = (size_t)blockIdx.z * K * N;
    int n0 = blockIdx.x * 32, k0 = blockIdx.y * 32;
    int lx = threadIdx.x, ly = threadIdx.y;
#pragma unroll
    for (int i = 0; i < 4; i++)
        tl[ly + 8 * i][lx] = W[off + (size_t)(k0 + ly + 8 * i) * N + n0 + lx];
    __syncthreads();
#pragma unroll
    for (int i = 0; i < 4; i++)
        WT[off + (size_t)(n0 + ly + 8 * i) * K + k0 + lx] =
            __float2half_rn(tl[lx][ly + 8 * i]);
}

__global__ void halfcpy_k(const float* __restrict__ src, __half* __restrict__ dst, int n4) {
    int i = blockIdx.x * 256 + threadIdx.x;
    if (i < n4) {
        float4 v = *(const float4*)(src + (size_t)i * 4);
        st_half4(dst + (size_t)i * 4, v.x, v.y, v.z, v.w);
    }
}

// ---------------- Embedding ----------------
__global__ void embed_k(const int* __restrict__ idx, const float* __restrict__ wte,
                        const float* __restrict__ wpe, float* __restrict__ h) {
    int bt = blockIdx.x;
    int t  = bt % TT;
    int tok = idx[bt];
    int i = threadIdx.x * 4;
    float4 a = *(const float4*)(wte + (size_t)tok * EE + i);
    float4 p = *(const float4*)(wpe + (size_t)t   * EE + i);
    a.x += p.x; a.y += p.y; a.z += p.z; a.w += p.w;
    *(float4*)(h + (size_t)bt * EE + i) = a;
}

// ---------------- LayerNorm: fp32 in, half out ----------------
__global__ void layernorm_k(const float* __restrict__ xin, const float* __restrict__ g,
                            const float* __restrict__ bb, __half* __restrict__ y) {
    __shared__ float rs[8], rq[8];
    int row = blockIdx.x, tid = threadIdx.x;
    const float* xr = xin + (size_t)row * EE;
    float4 v = *(const float4*)(xr + tid * 4);
    float s = v.x + v.y + v.z + v.w;
    float q = v.x * v.x + v.y * v.y + v.z * v.z + v.w * v.w;
#pragma unroll
    for (int o = 16; o; o >>= 1) {
        s += __shfl_xor_sync(0xffffffffu, s, o);
        q += __shfl_xor_sync(0xffffffffu, q, o);
    }
    if ((tid & 31) == 0) { rs[tid >> 5] = s; rq[tid >> 5] = q; }
    __syncthreads();
    if (tid == 0) {
        float S = 0.f, Q = 0.f;
#pragma unroll
        for (int i = 0; i < 8; i++) { S += rs[i]; Q += rq[i]; }
        rs[0] = S; rq[0] = Q;
    }
    __syncthreads();
    float mean = rs[0] * (1.f / EE);
    float var  = rq[0] * (1.f / EE) - mean * mean;
    float rstd = rsqrtf(var + 1e-5f);
    float4 gg = *(const float4*)(g  + tid * 4);
    float4 be = *(const float4*)(bb + tid * 4);
    st_half4(y + (size_t)row * EE + tid * 4,
             (v.x - mean) * rstd * gg.x + be.x,
             (v.y - mean) * rstd * gg.y + be.y,
             (v.z - mean) * rstd * gg.z + be.z,
             (v.w - mean) * rstd * gg.w + be.w);
}

// ---------------- cp.async 3-stage fp16 GEMM, M-tile templated ----------------
static constexpr int H_AST = 72;
template<int MT> struct HStg { static constexpr int v = (MT + 128) * H_AST; };
static constexpr int HSMEM128 = 3 * HStg<128>::v * 2;   // 110592
static constexpr int HSMEM64  = 3 * HStg<64>::v * 2;    // 82944

template<int MT, int ACT, bool RES, bool GUARD, bool OUT_HALF>
__global__ __launch_bounds__(256, 2)
void hgemm_k(const __half* __restrict__ A, const __half* __restrict__ Bw,
             const float* __restrict__ bias, const float* __restrict__ Res,
             void* __restrict__ Cv, int M, int N, int K) {
    extern __shared__ __half smh[];
    constexpr int STG = HStg<MT>::v;
    constexpr int MFR = MT / 32;      // m16 fragments per warp
    const uint32_t sb = smem_u32(smh);
    const int tid  = threadIdx.x;
    const int lane = tid & 31;
    const int wid  = tid >> 5;
    const int wm   = wid >> 2;
    const int wn   = wid & 3;
    const int g    = lane >> 2;
    const int t    = lane & 3;
    const int la16  = lane & 15;
    const int lac8  = (lane >> 4) << 3;
    const int lbrow = ((lane >> 4) << 3) + (lane & 7);
    const int lbcol = ((lane >> 3) & 1) << 3;

    const int row0 = blockIdx.x * MT;
    const int col0 = blockIdx.y * 128;
    const int iters = K >> 6;

    auto issue_stage = [&](int it) {
        const int k0 = it << 6;
        const int s = it % 3;
        const uint32_t stA = sb + (uint32_t)(s * STG) * 2;
        const uint32_t stB = stA + (uint32_t)(MT * H_AST) * 2;
#pragma unroll
        for (int u = 0; u < MT / 32; u++) {
            int ca = u * 256 + tid;
            int r = ca >> 3, c16 = ca & 7;
            const __half* gs = A + (size_t)(row0 + r) * K + k0 + c16 * 8;
            uint32_t sd = stA + (uint32_t)(r * H_AST + c16 * 8) * 2;
            asm volatile("cp.async.cg.shared.global [%0], [%1], 16;" :: "r"(sd), "l"(gs));
        }
#pragma unroll
        for (int u = 0; u < 4; u++) {
            int cb = u * 256 + tid;
            int n = cb >> 3, c16 = cb & 7;
            const __half* gs = Bw + (size_t)(col0 + n) * K + k0 + c16 * 8;
            uint32_t sd = stB + (uint32_t)(n * H_AST + c16 * 8) * 2;
            if (GUARD) {
                int sz = (col0 + n < N) ? 16 : 0;
                asm volatile("cp.async.cg.shared.global [%0], [%1], 16, %2;"
                             :: "r"(sd), "l"(gs), "r"(sz));
            } else {
                asm volatile("cp.async.cg.shared.global [%0], [%1], 16;" :: "r"(sd), "l"(gs));
            }
        }
        asm volatile("cp.async.commit_group;" ::: "memory");
    };

    float acc[MFR][4][4] = {};

    issue_stage(0);
    issue_stage(1);

    for (int it = 0; it < iters; ++it) {
        if (it == iters - 1) {
            asm volatile("cp.async.wait_group 0;" ::: "memory");
        } else {
            asm volatile("cp.async.wait_group 1;" ::: "memory");
        }
        __syncthreads();
        if (it + 2 < iters) issue_stage(it + 2);

        const uint32_t stA = sb + (uint32_t)((it % 3) * STG) * 2;
        const uint32_t stB = stA + (uint32_t)(MT * H_AST) * 2;
        const uint32_t aBase = stA + (uint32_t)((wm * (MT / 2) + la16) * H_AST + lac8) * 2;
        const uint32_t bBase = stB + (uint32_t)((wn * 32 + lbrow) * H_AST + lbcol) * 2;
#pragma unroll
        for (int ks = 0; ks < 4; ks++) {
            uint32_t afr[MFR][4];
            uint32_t bfr[4][2];
#pragma unroll
            for (int mt = 0; mt < MFR; mt++)
                ldsm_x4(afr[mt], aBase + (uint32_t)(mt * 16 * H_AST + ks * 16) * 2);
#pragma unroll
            for (int ntp = 0; ntp < 2; ntp++) {
                uint32_t bp[4];
                ldsm_x4(bp, bBase + (uint32_t)(ntp * 16 * H_AST + ks * 16) * 2);
                bfr[2 * ntp][0]     = bp[0]; bfr[2 * ntp][1]     = bp[1];
                bfr[2 * ntp + 1][0] = bp[2]; bfr[2 * ntp + 1][1] = bp[3];
            }
#pragma unroll
            for (int mt = 0; mt < MFR; mt++)
#pragma unroll
                for (int nt = 0; nt < 4; nt++)
                    mma_f16(acc[mt][nt], afr[mt], bfr[nt]);
        }
    }

#pragma unroll
    for (int mt = 0; mt < MFR; mt++) {
        int r0 = row0 + wm * (MT / 2) + mt * 16 + g;
#pragma unroll
        for (int nt = 0; nt < 4; nt++) {
            int c = col0 + wn * 32 + nt * 8 + t * 2;
#pragma unroll
            for (int half_i = 0; half_i < 2; half_i++) {
                int r = r0 + half_i * 8;
                float v0 = acc[mt][nt][half_i * 2 + 0];
                float v1 = acc[mt][nt][half_i * 2 + 1];
                if (GUARD) {
                    float* C = (float*)Cv;
                    if (c < N)     C[(size_t)r * N + c]     = v0 + bias[c];
                    if (c + 1 < N) C[(size_t)r * N + c + 1] = v1 + bias[c + 1];
                } else {
                    v0 += bias[c]; v1 += bias[c + 1];
                    if (ACT == 1) {
                        v0 = 0.5f * v0 * (1.f + erff(v0 * 0.70710678118654752f));
                        v1 = 0.5f * v1 * (1.f + erff(v1 * 0.70710678118654752f));
                    }
                    if (RES) {
                        v0 += Res[(size_t)r * N + c];
                        v1 += Res[(size_t)r * N + c + 1];
                    }
                    if (OUT_HALF) {
                        __half2 hv = __floats2half2_rn(v0, v1);
                        *(__half2*)((__half*)Cv + (size_t)r * N + c) = hv;
                    } else {
                        *(float2*)((float*)Cv + (size_t)r * N + c) = make_float2(v0, v1);
                    }
                }
            }
        }
    }
}

// ---------------- Tensor-core split-KV flash attention ----------------
static constexpr int FH_PAD = 72;

__global__ __launch_bounds__(128)
void flash_attn_k(const __half* __restrict__ qkv, float* __restrict__ pO,
                  float* __restrict__ pm, float* __restrict__ pl) {
    __shared__ __half Qh[64 * FH_PAD];
    __shared__ __half Kh[64 * FH_PAD];
    __shared__ __half Vt[64 * FH_PAD];

    const int tid  = threadIdx.x;
    const int lane = tid & 31;
    const int wid  = tid >> 5;
    const int g    = lane >> 2;
    const int t    = lane & 3;
    const int wr   = wid * 16;

    const int u  = blockIdx.x;
    const int bh = blockIdx.y;
    const int qi = c_qi[u];
    const int sp = c_sp[u];
    const int q0 = qi * 64;
    const int b = bh / HH, h = bh % HH;

    const __half* base = qkv + (size_t)b * TT * 3 * EE + h * DD;

    {
        int r = tid >> 1, cpart = tid & 1;
        const __half* qp = base + (size_t)(q0 + r) * 3 * EE + cpart * 32;
#pragma unroll
        for (int i = 0; i < 4; i++)
            *(uint4*)(Qh + r * FH_PAD + cpart * 32 + i * 8) = *(const uint4*)(qp + i * 8);
    }

    float m_old[2] = {-1e30f, -1e30f};
    float lsum[2]  = {0.f, 0.f};
    float oacc[8][4] = {};
    const int c0 = sp * 4;
    const int c1 = min(c0 + 4, qi + 1);

    for (int ch = c0; ch < c1; ch++) {
        const int kt = ch * 64;
        __syncthreads();
        {
            int r = tid >> 1, cpart = tid & 1;
            const __half* kp = base + (size_t)(kt + r) * 3 * EE + EE + cpart * 32;
            const __half* vp = base + (size_t)(kt + r) * 3 * EE + 2 * EE + cpart * 32;
#pragma unroll
            for (int i = 0; i < 4; i++) {
                *(uint4*)(Kh + r * FH_PAD + cpart * 32 + i * 8) = *(const uint4*)(kp + i * 8);
                uint4 vv = *(const uint4*)(vp + i * 8);
                const __half* hv = (const __half*)&vv;
                int d = cpart * 32 + i * 8;
#pragma unroll
                for (int j = 0; j < 8; j++)
                    Vt[(d + j) * FH_PAD + r] = hv[j];
            }
        }
        __syncthreads();

        // ---- S = Q @ K^T ----
        float sacc[8][4] = {};
#pragma unroll
        for (int j = 0; j < 4; j++) {
            const int kk = j * 16 + t * 2;
            uint32_t a[4];
            a[0] = *(const uint32_t*)&Qh[(wr + g)     * FH_PAD + kk];
            a[1] = *(const uint32_t*)&Qh[(wr + g + 8) * FH_PAD + kk];
            a[2] = *(const uint32_t*)&Qh[(wr + g)     * FH_PAD + kk + 8];
            a[3] = *(const uint32_t*)&Qh[(wr + g + 8) * FH_PAD + kk + 8];
#pragma unroll
            for (int nt = 0; nt < 8; nt++) {
                uint32_t bfr[2];
                bfr[0] = *(const uint32_t*)&Kh[(nt * 8 + g) * FH_PAD + kk];
                bfr[1] = *(const uint32_t*)&Kh[(nt * 8 + g) * FH_PAD + kk + 8];
                mma_f16(sacc[nt], a, bfr);
            }
        }

        // ---- online softmax; P via f16x2 ex2 directly into A-fragments ----
        const bool diag = (ch == qi);
        uint32_t ap[4][4];
        float al[2];
#pragma unroll
        for (int rh = 0; rh < 2; rh++) {
            int row = q0 + wr + g + rh * 8;
            float pv[16];
            float lm = -1e30f;
#pragma unroll
            for (int nt = 0; nt < 8; nt++) {
#pragma unroll
                for (int jj = 0; jj < 2; jj++) {
                    float s = sacc[nt][rh * 2 + jj] * 0.125f;
                    if (diag && (kt + nt * 8 + t * 2 + jj > row)) s = -1e30f;
                    pv[nt * 2 + jj] = s;
                    lm = fmaxf(lm, s);
                }
            }
            lm = fmaxf(lm, __shfl_xor_sync(0xffffffffu, lm, 1));
            lm = fmaxf(lm, __shfl_xor_sync(0xffffffffu, lm, 2));
            float mnew = fmaxf(m_old[rh], lm);
            al[rh] = __expf(m_old[rh] - mnew);
            m_old[rh] = mnew;
            const float mb = mnew * L2E;
            float ls = 0.f;
#pragma unroll
            for (int j = 0; j < 4; j++) {
                uint32_t p01 = ex2_h2(fmaf(pv[4 * j + 0], L2E, -mb),
                                      fmaf(pv[4 * j + 1], L2E, -mb));
                uint32_t p23 = ex2_h2(fmaf(pv[4 * j + 2], L2E, -mb),
                                      fmaf(pv[4 * j + 3], L2E, -mb));
                ap[j][rh]     = p01;
                ap[j][rh + 2] = p23;
                float2 f0 = __half22float2(*(__half2*)&p01);
                float2 f1 = __half22float2(*(__half2*)&p23);
                ls += (f0.x + f0.y) + (f1.x + f1.y);
            }
            ls += __shfl_xor_sync(0xffffffffu, ls, 1);
            ls += __shfl_xor_sync(0xffffffffu, ls, 2);
            lsum[rh] = lsum[rh] * al[rh] + ls;
        }

        // ---- O = O*alpha + P @ V ----
#pragma unroll
        for (int dt = 0; dt < 8; dt++) {
            oacc[dt][0] *= al[0]; oacc[dt][1] *= al[0];
            oacc[dt][2] *= al[1]; oacc[dt][3] *= al[1];
        }
#pragma unroll
        for (int j = 0; j < 4; j++) {
            const int kk = j * 16 + t * 2;
#pragma unroll
            for (int dt = 0; dt < 8; dt++) {
                uint32_t bfr[2];
                bfr[0] = *(const uint32_t*)&Vt[(dt * 8 + g) * FH_PAD + kk];
                bfr[1] = *(const uint32_t*)&Vt[(dt * 8 + g) * FH_PAD + kk + 8];
                mma_f16(oacc[dt], ap[j], bfr);
            }
        }
    }

    float* po = pO + ((size_t)(bh * NU + u) * 64) * 64;
    int r0 = wr + g;
#pragma unroll
    for (int dt = 0; dt < 8; dt++) {
        *(float2*)(po + (size_t)r0 * 64 + dt * 8 + t * 2)       = make_float2(oacc[dt][0], oacc[dt][1]);
        *(float2*)(po + (size_t)(r0 + 8) * 64 + dt * 8 + t * 2) = make_float2(oacc[dt][2], oacc[dt][3]);
    }
    if (t == 0) {
        pm[(size_t)(bh * NU + u) * 64 + r0]     = m_old[0];
        pm[(size_t)(bh * NU + u) * 64 + r0 + 8] = m_old[1];
        pl[(size_t)(bh * NU + u) * 64 + r0]     = lsum[0];
        pl[(size_t)(bh * NU + u) * 64 + r0 + 8] = lsum[1];
    }
}

// Combine split partials; half output
__global__ __launch_bounds__(256)
void fa_combine_k(const float* __restrict__ pO, const float* __restrict__ pm,
                  const float* __restrict__ pl, __half* __restrict__ out) {
    const int qi = blockIdx.x;
    const int bh = blockIdx.y;
    const int b = bh / HH, h = bh % HH;
    const int ns = c_ns[qi];
    const int u0 = c_u0[qi];
    const int tid = threadIdx.x;
    const int r4 = tid >> 6;
    const int d  = tid & 63;
    for (int p = 0; p < 16; p++) {
        int row = p * 4 + r4;
        float M = -1e30f;
        for (int s = 0; s < ns; s++)
            M = fmaxf(M, pm[(size_t)(bh * NU + u0 + s) * 64 + row]);
        float L = 0.f, O = 0.f;
        for (int s = 0; s < ns; s++) {
            size_t ub = (size_t)(bh * NU + u0 + s);
            float w = __expf(pm[ub * 64 + row] - M);
            L += w * pl[ub * 64 + row];
            O += w * pO[(ub * 64 + row) * 64 + d];
        }
        out[((size_t)(b * TT + qi * 64 + row)) * EE + h * DD + d] = __float2half_rn(O / L);
    }
}

// ---------------- Per-row NLL (pairwise f16x2 ex2) ----------------
__global__ void nll_k(const float* __restrict__ logits, const int* __restrict__ tgt,
                      float* __restrict__ nll) {
    int row = blockIdx.x;
    const float* lr = logits + (size_t)row * VV;
    int tid = threadIdx.x;
    __shared__ float sh[256];
    float m = -1e30f;
    for (int i = tid; i < VV; i += 256) m = fmaxf(m, lr[i]);
    sh[tid] = m; __syncthreads();
    for (int o = 128; o; o >>= 1) { if (tid < o) sh[tid] = fmaxf(sh[tid], sh[tid + o]); __syncthreads(); }
    m = sh[0]; __syncthreads();
    const float mb = m * L2E;
    float s = 0.f;
    for (int i = tid * 2; i + 1 < VV; i += 512) {
        float a = lr[i], b = lr[i + 1];
        uint32_t e = ex2_h2(fmaf(a, L2E, -mb), fmaf(b, L2E, -mb));
        float2 f = __half22float2(*(__half2*)&e);
        s += f.x + f.y;
    }
    if (tid == 0) s += __expf(lr[VV - 1] - m);   // VV is odd; last element
    sh[tid] = s; __syncthreads();
    for (int o = 128; o; o >>= 1) { if (tid < o) sh[tid] += sh[tid + o]; __syncthreads(); }
    if (tid == 0) nll[row] = logf(sh[0]) + m - lr[tgt[row]];
}

__global__ void loss_reduce_k(const float* __restrict__ nll, float* __restrict__ dst, int count) {
    __shared__ float sh[256];
    float s = 0.f;
    for (int i = threadIdx.x; i < MM; i += 256) s += nll[i];
    sh[threadIdx.x] = s; __syncthreads();
    for (int o = 128; o; o >>= 1) { if (threadIdx.x < o) sh[threadIdx.x] += sh[threadIdx.x + o]; __syncthreads(); }
    if (threadIdx.x == 0) {
        float loss = sh[0] * (1.f / (float)MM);
        for (int i = 0; i < count; i++) dst[i] = loss;
    }
}

// ---------------- Launch ----------------
extern "C" void kernel_launch(void* const* d_in, const int* in_sizes, int n_in,
                              void* d_out, int out_size) {
    const int*   idx     = (const int*)  d_in[0];
    const int*   targets = (const int*)  d_in[1];
    const float* wte     = (const float*)d_in[2];
    const float* wpe     = (const float*)d_in[3];
    const float* ln1_g   = (const float*)d_in[4];
    const float* ln1_b   = (const float*)d_in[5];
    const float* qkv_w   = (const float*)d_in[6];
    const float* qkv_b   = (const float*)d_in[7];
    const float* o_w     = (const float*)d_in[8];
    const float* o_b     = (const float*)d_in[9];
    const float* ln2_g   = (const float*)d_in[10];
    const float* ln2_b   = (const float*)d_in[11];
    const float* up_w    = (const float*)d_in[12];
    const float* up_b    = (const float*)d_in[13];
    const float* down_w  = (const float*)d_in[14];
    const float* down_b  = (const float*)d_in[15];
    const float* lnf_g   = (const float*)d_in[16];
    const float* lnf_b   = (const float*)d_in[17];
    const float* lm_b    = (const float*)d_in[18];

    float *h, *nll, *logits_scratch, *pO, *pm, *pl;
    __half *xh, *qkvh, *attnh, *mlph, *qkvT, *oT, *upT, *downT, *wteH;
    cudaGetSymbolAddress((void**)&h,    g_h);
    cudaGetSymbolAddress((void**)&xh,   g_xh);
    cudaGetSymbolAddress((void**)&qkvh, g_qkvh);
    cudaGetSymbolAddress((void**)&attnh, g_attnh);
    cudaGetSymbolAddress((void**)&mlph, g_mlph);
    cudaGetSymbolAddress((void**)&nll,  g_nll);
    cudaGetSymbolAddress((void**)&logits_scratch, g_logits);
    cudaGetSymbolAddress((void**)&pO,   g_pO);
    cudaGetSymbolAddress((void**)&pm,   g_pm);
    cudaGetSymbolAddress((void**)&pl,   g_pl);
    cudaGetSymbolAddress((void**)&qkvT,  g_qkvT);
    cudaGetSymbolAddress((void**)&oT,    g_oT);
    cudaGetSymbolAddress((void**)&upT,   g_upT);
    cudaGetSymbolAddress((void**)&downT, g_downT);
    cudaGetSymbolAddress((void**)&wteH,  g_wteH);

    static bool attr_set = false;
    if (!attr_set) {
        cudaFuncSetAttribute(hgemm_k<64,  0, false, false, true >, cudaFuncAttributeMaxDynamicSharedMemorySize, HSMEM64);
        cudaFuncSetAttribute(hgemm_k<64,  0, true,  false, false>, cudaFuncAttributeMaxDynamicSharedMemorySize, HSMEM64);
        cudaFuncSetAttribute(hgemm_k<128, 1, false, false, true >, cudaFuncAttributeMaxDynamicSharedMemorySize, HSMEM128);
        cudaFuncSetAttribute(hgemm_k<128, 0, false, true,  false>, cudaFuncAttributeMaxDynamicSharedMemorySize, HSMEM128);
        attr_set = true;
    }

    float* logits = ((long long)out_size >= NBTV) ? (float*)d_out : logits_scratch;

    transh_k<<<dim3(3 * EE / 32, EE / 32, LL), dim3(32, 8)>>>(qkv_w, qkvT, EE, 3 * EE);
    transh_k<<<dim3(EE / 32, EE / 32, LL), dim3(32, 8)>>>(o_w, oT, EE, EE);
    transh_k<<<dim3(4 * EE / 32, EE / 32, LL), dim3(32, 8)>>>(up_w, upT, EE, 4 * EE);
    transh_k<<<dim3(EE / 32, 4 * EE / 32, LL), dim3(32, 8)>>>(down_w, downT, 4 * EE, EE);
    {
        int n = VV * EE / 4;
        halfcpy_k<<<(n + 255) / 256, 256>>>(wte, wteH, n);
    }

    embed_k<<<MM, 256>>>(idx, wte, wpe, h);

    for (int l = 0; l < LL; l++) {
        layernorm_k<<<MM, 256>>>(h, ln1_g + (size_t)l * EE, ln1_b + (size_t)l * EE, xh);
        hgemm_k<64, 0, false, false, true><<<dim3(MM / 64, 3 * EE / 128), 256, HSMEM64>>>(
            xh, qkvT + (size_t)l * 3 * EE * EE, qkv_b + (size_t)l * 3 * EE, nullptr,
            qkvh, MM, 3 * EE, EE);
        flash_attn_k<<<dim3(NU, BB * HH), 128>>>(qkvh, pO, pm, pl);
        fa_combine_k<<<dim3(TT / 64, BB * HH), 256>>>(pO, pm, pl, attnh);
        hgemm_k<64, 0, true, false, false><<<dim3(MM / 64, EE / 128), 256, HSMEM64>>>(
            attnh, oT + (size_t)l * EE * EE, o_b + (size_t)l * EE, h,
            h, MM, EE, EE);
        layernorm_k<<<MM, 256>>>(h, ln2_g + (size_t)l * EE, ln2_b + (size_t)l * EE, xh);
        hgemm_k<128, 1, false, false, true><<<dim3(MM / 128, 4 * EE / 128), 256, HSMEM128>>>(
            xh, upT + (size_t)l * 4 * EE * EE, up_b + (size_t)l * 4 * EE, nullptr,
            mlph, MM, 4 * EE, EE);
        hgemm_k<64, 0, true, false, false><<<dim3(MM / 64, EE / 128), 256, HSMEM64>>>(
            mlph, downT + (size_t)l * 4 * EE * EE, down_b + (size_t)l * EE, h,
            h, MM, EE, 4 * EE);
    }

    layernorm_k<<<MM, 256>>>(h, lnf_g, lnf_b, xh);
    hgemm_k<128, 0, false, true, false><<<dim3(MM / 128, (VV + 127) / 128), 256, HSMEM128>>>(
        xh, wteH, lm_b, nullptr, logits, MM, VV, EE);

    nll_k<<<MM, 256>>>(logits, targets, nll);

    long long extra = (long long)out_size - NBTV;
    if (extra > 0) {
        loss_reduce_k<<<1, 256>>>(nll, (float*)d_out + NBTV, (int)extra);
    } else if ((long long)out_size < NBTV) {
        loss_reduce_k<<<1, 256>>>(nll, (float*)d_out, out_size);
    }
}

// round 13
// speedup vs baseline: 1.0483x; 1.0483x over previous
#include <cuda_runtime.h>
#include <cuda_fp16.h>
#include <math.h>
#include <stdint.h>

// ---------------- Problem constants ----------------
static constexpr int BB = 2;
static constexpr int TT = 1024;
static constexpr int EE = 1024;
static constexpr int HH = 16;
static constexpr int DD = 64;
static constexpr int LL = 12;
static constexpr int VV = 50257;
static constexpr int MM = BB * TT;
static constexpr long long NBTV = (long long)MM * VV;
static constexpr int NU = 40;
static constexpr float L2E = 1.44269504088896340736f;

// ---------------- Scratch ----------------
__device__ float g_h   [(size_t)MM * EE];
__device__ __half g_xh  [(size_t)MM * EE];
__device__ __half g_qkvh[(size_t)MM * 3 * EE];
__device__ __half g_attnh[(size_t)MM * EE];
__device__ __half g_mlph [(size_t)MM * 4 * EE];
__device__ float g_nll [MM];
__device__ float g_logits[(size_t)MM * VV];
__device__ float g_pO[(size_t)BB * HH * NU * 64 * 64];
__device__ float g_pm[(size_t)BB * HH * NU * 64];
__device__ float g_pl[(size_t)BB * HH * NU * 64];
__device__ __half g_qkvT [(size_t)LL * 3 * EE * EE];
__device__ __half g_oT   [(size_t)LL * EE * EE];
__device__ __half g_upT  [(size_t)LL * 4 * EE * EE];
__device__ __half g_downT[(size_t)LL * 4 * EE * EE];
__device__ __half g_wteH [(size_t)VV * EE];

__constant__ int c_qi[NU] = {15,15,15,15, 14,14,14,14, 13,13,13,13, 12,12,12,12,
                             11,11,11, 10,10,10, 9,9,9, 8,8,8, 7,7, 6,6, 5,5, 4,4,
                             3, 2, 1, 0};
__constant__ int c_sp[NU] = {0,1,2,3, 0,1,2,3, 0,1,2,3, 0,1,2,3,
                             0,1,2, 0,1,2, 0,1,2, 0,1,2, 0,1, 0,1, 0,1, 0,1,
                             0, 0, 0, 0};
__constant__ int c_u0[16] = {39,38,37,36, 34,32,30,28, 25,22,19,16, 12,8,4,0};
__constant__ int c_ns[16] = {1,1,1,1, 2,2,2,2, 3,3,3,3, 4,4,4,4};

// ---------------- Helpers ----------------
__device__ __forceinline__ uint32_t smem_u32(const void* p) {
    uint32_t r;
    asm("{ .reg .u64 t; cvta.to.shared.u64 t, %1; cvt.u32.u64 %0, t; }" : "=r"(r) : "l"(p));
    return r;
}

__device__ __forceinline__ void mma_f16(float c[4], const uint32_t a[4], const uint32_t b[2]) {
    asm volatile(
        "mma.sync.aligned.m16n8k16.row.col.f32.f16.f16.f32 "
        "{%0,%1,%2,%3}, {%4,%5,%6,%7}, {%8,%9}, {%0,%1,%2,%3};"
        : "+f"(c[0]), "+f"(c[1]), "+f"(c[2]), "+f"(c[3])
        : "r"(a[0]), "r"(a[1]), "r"(a[2]), "r"(a[3]), "r"(b[0]), "r"(b[1]));
}

__device__ __forceinline__ void ldsm_x4(uint32_t r[4], uint32_t addr) {
    asm volatile("ldmatrix.sync.aligned.m8n8.x4.shared.b16 {%0,%1,%2,%3}, [%4];"
        : "=r"(r[0]), "=r"(r[1]), "=r"(r[2]), "=r"(r[3]) : "r"(addr));
}

__device__ __forceinline__ void st_half4(__half* p, float a, float b, float c, float d) {
    __half2 lo = __floats2half2_rn(a, b);
    __half2 hi = __floats2half2_rn(c, d);
    uint2 v = make_uint2(*(uint32_t*)&lo, *(uint32_t*)&hi);
    *(uint2*)p = v;
}

// two exps via one MUFU op: returns packed half2 {exp2(a), exp2(b)} for fp32 args
__device__ __forceinline__ uint32_t ex2_h2(float a, float b) {
    __half2 h = __floats2half2_rn(a, b);
    uint32_t u = *(uint32_t*)&h, o;
    asm("ex2.approx.f16x2 %0, %1;" : "=r"(o) : "r"(u));
    return o;
}

// ---------------- Weight prep: W[K,N] fp32 -> WT[N,K] half ----------------
__global__ void transh_k(const float* __restrict__ W, __half* __restrict__ WT,
                         int K, int N) {
    __shared__ float tl[32][33];
    size_t off = (size_t)blockIdx.z * K * N;
    int n0 = blockIdx.x * 32, k0 = blockIdx.y * 32;
    int lx = threadIdx.x, ly = threadIdx.y;
#pragma unroll
    for (int i = 0; i < 4; i++)
        tl[ly + 8 * i][lx] = W[off + (size_t)(k0 + ly + 8 * i) * N + n0 + lx];
    __syncthreads();
#pragma unroll
    for (int i = 0; i < 4; i++)
        WT[off + (size_t)(n0 + ly + 8 * i) * K + k0 + lx] =
            __float2half_rn(tl[lx][ly + 8 * i]);
}

__global__ void halfcpy_k(const float* __restrict__ src, __half* __restrict__ dst, int n4) {
    int i = blockIdx.x * 256 + threadIdx.x;
    if (i < n4) {
        float4 v = *(const float4*)(src + (size_t)i * 4);
        st_half4(dst + (size_t)i * 4, v.x, v.y, v.z, v.w);
    }
}

// ---------------- Embedding ----------------
__global__ void embed_k(const int* __restrict__ idx, const float* __restrict__ wte,
                        const float* __restrict__ wpe, float* __restrict__ h) {
    int bt = blockIdx.x;
    int t  = bt % TT;
    int tok = idx[bt];
    int i = threadIdx.x * 4;
    float4 a = *(const float4*)(wte + (size_t)tok * EE + i);
    float4 p = *(const float4*)(wpe + (size_t)t   * EE + i);
    a.x += p.x; a.y += p.y; a.z += p.z; a.w += p.w;
    *(float4*)(h + (size_t)bt * EE + i) = a;
}

// ---------------- LayerNorm: fp32 in, half out ----------------
__global__ void layernorm_k(const float* __restrict__ xin, const float* __restrict__ g,
                            const float* __restrict__ bb, __half* __restrict__ y) {
    __shared__ float rs[8], rq[8];
    int row = blockIdx.x, tid = threadIdx.x;
    const float* xr = xin + (size_t)row * EE;
    float4 v = *(const float4*)(xr + tid * 4);
    float s = v.x + v.y + v.z + v.w;
    float q = v.x * v.x + v.y * v.y + v.z * v.z + v.w * v.w;
#pragma unroll
    for (int o = 16; o; o >>= 1) {
        s += __shfl_xor_sync(0xffffffffu, s, o);
        q += __shfl_xor_sync(0xffffffffu, q, o);
    }
    if ((tid & 31) == 0) { rs[tid >> 5] = s; rq[tid >> 5] = q; }
    __syncthreads();
    if (tid == 0) {
        float S = 0.f, Q = 0.f;
#pragma unroll
        for (int i = 0; i < 8; i++) { S += rs[i]; Q += rq[i]; }
        rs[0] = S; rq[0] = Q;
    }
    __syncthreads();
    float mean = rs[0] * (1.f / EE);
    float var  = rq[0] * (1.f / EE) - mean * mean;
    float rstd = rsqrtf(var + 1e-5f);
    float4 gg = *(const float4*)(g  + tid * 4);
    float4 be = *(const float4*)(bb + tid * 4);
    st_half4(y + (size_t)row * EE + tid * 4,
             (v.x - mean) * rstd * gg.x + be.x,
             (v.y - mean) * rstd * gg.y + be.y,
             (v.z - mean) * rstd * gg.z + be.z,
             (v.w - mean) * rstd * gg.w + be.w);
}

// ---------------- cp.async 3-stage fp16 GEMM with ldmatrix (MT=128) ----------------
static constexpr int H_AST = 72;
static constexpr int H_STG = 2 * 128 * H_AST;
static constexpr int HSMEM = 3 * H_STG * 2;

template<int ACT, bool RES, bool GUARD, bool OUT_HALF>
__global__ __launch_bounds__(256, 2)
void hgemm_k(const __half* __restrict__ A, const __half* __restrict__ Bw,
             const float* __restrict__ bias, const float* __restrict__ Res,
             void* __restrict__ Cv, int M, int N, int K) {
    extern __shared__ __half smh[];
    const uint32_t sb = smem_u32(smh);
    const int tid  = threadIdx.x;
    const int lane = tid & 31;
    const int wid  = tid >> 5;
    const int wm   = wid >> 2;
    const int wn   = wid & 3;
    const int g    = lane >> 2;
    const int t    = lane & 3;
    const int la16  = lane & 15;
    const int lac8  = (lane >> 4) << 3;
    const int lbrow = ((lane >> 4) << 3) + (lane & 7);
    const int lbcol = ((lane >> 3) & 1) << 3;

    const int row0 = blockIdx.x * 128;
    const int col0 = blockIdx.y * 128;
    const int iters = K >> 6;

    auto issue_stage = [&](int it) {
        const int k0 = it << 6;
        const int s = it % 3;
        const uint32_t stA = sb + (uint32_t)(s * H_STG) * 2;
        const uint32_t stB = stA + (uint32_t)(128 * H_AST) * 2;
#pragma unroll
        for (int u = 0; u < 4; u++) {
            int ca = u * 256 + tid;
            int r = ca >> 3, c16 = ca & 7;
            const __half* gs = A + (size_t)(row0 + r) * K + k0 + c16 * 8;
            uint32_t sd = stA + (uint32_t)(r * H_AST + c16 * 8) * 2;
            asm volatile("cp.async.cg.shared.global [%0], [%1], 16;" :: "r"(sd), "l"(gs));
        }
#pragma unroll
        for (int u = 0; u < 4; u++) {
            int cb = u * 256 + tid;
            int n = cb >> 3, c16 = cb & 7;
            const __half* gs = Bw + (size_t)(col0 + n) * K + k0 + c16 * 8;
            uint32_t sd = stB + (uint32_t)(n * H_AST + c16 * 8) * 2;
            if (GUARD) {
                int sz = (col0 + n < N) ? 16 : 0;
                asm volatile("cp.async.cg.shared.global [%0], [%1], 16, %2;"
                             :: "r"(sd), "l"(gs), "r"(sz));
            } else {
                asm volatile("cp.async.cg.shared.global [%0], [%1], 16;" :: "r"(sd), "l"(gs));
            }
        }
        asm volatile("cp.async.commit_group;" ::: "memory");
    };

    float acc[4][4][4] = {};

    issue_stage(0);
    issue_stage(1);

    for (int it = 0; it < iters; ++it) {
        if (it == iters - 1) {
            asm volatile("cp.async.wait_group 0;" ::: "memory");
        } else {
            asm volatile("cp.async.wait_group 1;" ::: "memory");
        }
        __syncthreads();
        if (it + 2 < iters) issue_stage(it + 2);

        const uint32_t stA = sb + (uint32_t)((it % 3) * H_STG) * 2;
        const uint32_t stB = stA + (uint32_t)(128 * H_AST) * 2;
        const uint32_t aBase = stA + (uint32_t)((wm * 64 + la16) * H_AST + lac8) * 2;
        const uint32_t bBase = stB + (uint32_t)((wn * 32 + lbrow) * H_AST + lbcol) * 2;
#pragma unroll
        for (int ks = 0; ks < 4; ks++) {
            uint32_t afr[4][4];
            uint32_t bfr[4][2];
#pragma unroll
            for (int mt = 0; mt < 4; mt++)
                ldsm_x4(afr[mt], aBase + (uint32_t)(mt * 16 * H_AST + ks * 16) * 2);
#pragma unroll
            for (int ntp = 0; ntp < 2; ntp++) {
                uint32_t bp[4];
                ldsm_x4(bp, bBase + (uint32_t)(ntp * 16 * H_AST + ks * 16) * 2);
                bfr[2 * ntp][0]     = bp[0]; bfr[2 * ntp][1]     = bp[1];
                bfr[2 * ntp + 1][0] = bp[2]; bfr[2 * ntp + 1][1] = bp[3];
            }
#pragma unroll
            for (int mt = 0; mt < 4; mt++)
#pragma unroll
                for (int nt = 0; nt < 4; nt++)
                    mma_f16(acc[mt][nt], afr[mt], bfr[nt]);
        }
    }

#pragma unroll
    for (int mt = 0; mt < 4; mt++) {
        int r0 = row0 + wm * 64 + mt * 16 + g;
#pragma unroll
        for (int nt = 0; nt < 4; nt++) {
            int c = col0 + wn * 32 + nt * 8 + t * 2;
#pragma unroll
            for (int half_i = 0; half_i < 2; half_i++) {
                int r = r0 + half_i * 8;
                float v0 = acc[mt][nt][half_i * 2 + 0];
                float v1 = acc[mt][nt][half_i * 2 + 1];
                if (GUARD) {
                    float* C = (float*)Cv;
                    if (c < N)     C[(size_t)r * N + c]     = v0 + bias[c];
                    if (c + 1 < N) C[(size_t)r * N + c + 1] = v1 + bias[c + 1];
                } else {
                    v0 += bias[c]; v1 += bias[c + 1];
                    if (ACT == 1) {
                        v0 = 0.5f * v0 * (1.f + erff(v0 * 0.70710678118654752f));
                        v1 = 0.5f * v1 * (1.f + erff(v1 * 0.70710678118654752f));
                    }
                    if (RES) {
                        v0 += Res[(size_t)r * N + c];
                        v1 += Res[(size_t)r * N + c + 1];
                    }
                    if (OUT_HALF) {
                        __half2 hv = __floats2half2_rn(v0, v1);
                        *(__half2*)((__half*)Cv + (size_t)r * N + c) = hv;
                    } else {
                        *(float2*)((float*)Cv + (size_t)r * N + c) = make_float2(v0, v1);
                    }
                }
            }
        }
    }
}

// ---------------- Tensor-core split-KV flash attention ----------------
static constexpr int FH_PAD = 72;

__global__ __launch_bounds__(128)
void flash_attn_k(const __half* __restrict__ qkv, float* __restrict__ pO,
                  float* __restrict__ pm, float* __restrict__ pl) {
    __shared__ __half Qh[64 * FH_PAD];
    __shared__ __half Kh[64 * FH_PAD];
    __shared__ __half Vt[64 * FH_PAD];

    const int tid  = threadIdx.x;
    const int lane = tid & 31;
    const int wid  = tid >> 5;
    const int g    = lane >> 2;
    const int t    = lane & 3;
    const int wr   = wid * 16;

    const int u  = blockIdx.x;
    const int bh = blockIdx.y;
    const int qi = c_qi[u];
    const int sp = c_sp[u];
    const int q0 = qi * 64;
    const int b = bh / HH, h = bh % HH;

    const __half* base = qkv + (size_t)b * TT * 3 * EE + h * DD;

    {
        int r = tid >> 1, cpart = tid & 1;
        const __half* qp = base + (size_t)(q0 + r) * 3 * EE + cpart * 32;
#pragma unroll
        for (int i = 0; i < 4; i++)
            *(uint4*)(Qh + r * FH_PAD + cpart * 32 + i * 8) = *(const uint4*)(qp + i * 8);
    }

    float m_old[2] = {-1e30f, -1e30f};
    float lsum[2]  = {0.f, 0.f};
    float oacc[8][4] = {};
    const int c0 = sp * 4;
    const int c1 = min(c0 + 4, qi + 1);

    for (int ch = c0; ch < c1; ch++) {
        const int kt = ch * 64;
        __syncthreads();
        {
            int r = tid >> 1, cpart = tid & 1;
            const __half* kp = base + (size_t)(kt + r) * 3 * EE + EE + cpart * 32;
            const __half* vp = base + (size_t)(kt + r) * 3 * EE + 2 * EE + cpart * 32;
#pragma unroll
            for (int i = 0; i < 4; i++) {
                *(uint4*)(Kh + r * FH_PAD + cpart * 32 + i * 8) = *(const uint4*)(kp + i * 8);
                uint4 vv = *(const uint4*)(vp + i * 8);
                const __half* hv = (const __half*)&vv;
                int d = cpart * 32 + i * 8;
#pragma unroll
                for (int j = 0; j < 8; j++)
                    Vt[(d + j) * FH_PAD + r] = hv[j];
            }
        }
        __syncthreads();

        // ---- S = Q @ K^T ----
        float sacc[8][4] = {};
#pragma unroll
        for (int j = 0; j < 4; j++) {
            const int kk = j * 16 + t * 2;
            uint32_t a[4];
            a[0] = *(const uint32_t*)&Qh[(wr + g)     * FH_PAD + kk];
            a[1] = *(const uint32_t*)&Qh[(wr + g + 8) * FH_PAD + kk];
            a[2] = *(const uint32_t*)&Qh[(wr + g)     * FH_PAD + kk + 8];
            a[3] = *(const uint32_t*)&Qh[(wr + g + 8) * FH_PAD + kk + 8];
#pragma unroll
            for (int nt = 0; nt < 8; nt++) {
                uint32_t bfr[2];
                bfr[0] = *(const uint32_t*)&Kh[(nt * 8 + g) * FH_PAD + kk];
                bfr[1] = *(const uint32_t*)&Kh[(nt * 8 + g) * FH_PAD + kk + 8];
                mma_f16(sacc[nt], a, bfr);
            }
        }

        // ---- online softmax; P via f16x2 ex2 directly into A-fragments ----
        const bool diag = (ch == qi);
        uint32_t ap[4][4];
        float al[2];
#pragma unroll
        for (int rh = 0; rh < 2; rh++) {
            int row = q0 + wr + g + rh * 8;
            float pv[16];
            float lm = -1e30f;
#pragma unroll
            for (int nt = 0; nt < 8; nt++) {
#pragma unroll
                for (int jj = 0; jj < 2; jj++) {
                    float s = sacc[nt][rh * 2 + jj] * 0.125f;
                    if (diag && (kt + nt * 8 + t * 2 + jj > row)) s = -1e30f;
                    pv[nt * 2 + jj] = s;
                    lm = fmaxf(lm, s);
                }
            }
            lm = fmaxf(lm, __shfl_xor_sync(0xffffffffu, lm, 1));
            lm = fmaxf(lm, __shfl_xor_sync(0xffffffffu, lm, 2));
            float mnew = fmaxf(m_old[rh], lm);
            al[rh] = __expf(m_old[rh] - mnew);
            m_old[rh] = mnew;
            const float mb = mnew * L2E;
            float ls = 0.f;
#pragma unroll
            for (int j = 0; j < 4; j++) {
                uint32_t p01 = ex2_h2(fmaf(pv[4 * j + 0], L2E, -mb),
                                      fmaf(pv[4 * j + 1], L2E, -mb));
                uint32_t p23 = ex2_h2(fmaf(pv[4 * j + 2], L2E, -mb),
                                      fmaf(pv[4 * j + 3], L2E, -mb));
                ap[j][rh]     = p01;
                ap[j][rh + 2] = p23;
                float2 f0 = __half22float2(*(__half2*)&p01);
                float2 f1 = __half22float2(*(__half2*)&p23);
                ls += (f0.x + f0.y) + (f1.x + f1.y);
            }
            ls += __shfl_xor_sync(0xffffffffu, ls, 1);
            ls += __shfl_xor_sync(0xffffffffu, ls, 2);
            lsum[rh] = lsum[rh] * al[rh] + ls;
        }

        // ---- O = O*alpha + P @ V ----
#pragma unroll
        for (int dt = 0; dt < 8; dt++) {
            oacc[dt][0] *= al[0]; oacc[dt][1] *= al[0];
            oacc[dt][2] *= al[1]; oacc[dt][3] *= al[1];
        }
#pragma unroll
        for (int j = 0; j < 4; j++) {
            const int kk = j * 16 + t * 2;
#pragma unroll
            for (int dt = 0; dt < 8; dt++) {
                uint32_t bfr[2];
                bfr[0] = *(const uint32_t*)&Vt[(dt * 8 + g) * FH_PAD + kk];
                bfr[1] = *(const uint32_t*)&Vt[(dt * 8 + g) * FH_PAD + kk + 8];
                mma_f16(oacc[dt], ap[j], bfr);
            }
        }
    }

    float* po = pO + ((size_t)(bh * NU + u) * 64) * 64;
    int r0 = wr + g;
#pragma unroll
    for (int dt = 0; dt < 8; dt++) {
        *(float2*)(po + (size_t)r0 * 64 + dt * 8 + t * 2)       = make_float2(oacc[dt][0], oacc[dt][1]);
        *(float2*)(po + (size_t)(r0 + 8) * 64 + dt * 8 + t * 2) = make_float2(oacc[dt][2], oacc[dt][3]);
    }
    if (t == 0) {
        pm[(size_t)(bh * NU + u) * 64 + r0]     = m_old[0];
        pm[(size_t)(bh * NU + u) * 64 + r0 + 8] = m_old[1];
        pl[(size_t)(bh * NU + u) * 64 + r0]     = lsum[0];
        pl[(size_t)(bh * NU + u) * 64 + r0 + 8] = lsum[1];
    }
}

// Combine split partials; half output
__global__ __launch_bounds__(256)
void fa_combine_k(const float* __restrict__ pO, const float* __restrict__ pm,
                  const float* __restrict__ pl, __half* __restrict__ out) {
    const int qi = blockIdx.x;
    const int bh = blockIdx.y;
    const int b = bh / HH, h = bh % HH;
    const int ns = c_ns[qi];
    const int u0 = c_u0[qi];
    const int tid = threadIdx.x;
    const int r4 = tid >> 6;
    const int d  = tid & 63;
    for (int p = 0; p < 16; p++) {
        int row = p * 4 + r4;
        float M = -1e30f;
        for (int s = 0; s < ns; s++)
            M = fmaxf(M, pm[(size_t)(bh * NU + u0 + s) * 64 + row]);
        float L = 0.f, O = 0.f;
        for (int s = 0; s < ns; s++) {
            size_t ub = (size_t)(bh * NU + u0 + s);
            float w = __expf(pm[ub * 64 + row] - M);
            L += w * pl[ub * 64 + row];
            O += w * pO[(ub * 64 + row) * 64 + d];
        }
        out[((size_t)(b * TT + qi * 64 + row)) * EE + h * DD + d] = __float2half_rn(O / L);
    }
}

// ---------------- Per-row NLL (pairwise f16x2 ex2) ----------------
__global__ void nll_k(const float* __restrict__ logits, const int* __restrict__ tgt,
                      float* __restrict__ nll) {
    int row = blockIdx.x;
    const float* lr = logits + (size_t)row * VV;
    int tid = threadIdx.x;
    __shared__ float sh[256];
    float m = -1e30f;
    for (int i = tid; i < VV; i += 256) m = fmaxf(m, lr[i]);
    sh[tid] = m; __syncthreads();
    for (int o = 128; o; o >>= 1) { if (tid < o) sh[tid] = fmaxf(sh[tid], sh[tid + o]); __syncthreads(); }
    m = sh[0]; __syncthreads();
    const float mb = m * L2E;
    float s = 0.f;
    for (int i = tid * 2; i + 1 < VV; i += 512) {
        float a = lr[i], b = lr[i + 1];
        uint32_t e = ex2_h2(fmaf(a, L2E, -mb), fmaf(b, L2E, -mb));
        float2 f = __half22float2(*(__half2*)&e);
        s += f.x + f.y;
    }
    if (tid == 0) s += __expf(lr[VV - 1] - m);
    sh[tid] = s; __syncthreads();
    for (int o = 128; o; o >>= 1) { if (tid < o) sh[tid] += sh[tid + o]; __syncthreads(); }
    if (tid == 0) nll[row] = logf(sh[0]) + m - lr[tgt[row]];
}

__global__ void loss_reduce_k(const float* __restrict__ nll, float* __restrict__ dst, int count) {
    __shared__ float sh[256];
    float s = 0.f;
    for (int i = threadIdx.x; i < MM; i += 256) s += nll[i];
    sh[threadIdx.x] = s; __syncthreads();
    for (int o = 128; o; o >>= 1) { if (threadIdx.x < o) sh[threadIdx.x] += sh[threadIdx.x + o]; __syncthreads(); }
    if (threadIdx.x == 0) {
        float loss = sh[0] * (1.f / (float)MM);
        for (int i = 0; i < count; i++) dst[i] = loss;
    }
}

// ---------------- Launch ----------------
extern "C" void kernel_launch(void* const* d_in, const int* in_sizes, int n_in,
                              void* d_out, int out_size) {
    const int*   idx     = (const int*)  d_in[0];
    const int*   targets = (const int*)  d_in[1];
    const float* wte     = (const float*)d_in[2];
    const float* wpe     = (const float*)d_in[3];
    const float* ln1_g   = (const float*)d_in[4];
    const float* ln1_b   = (const float*)d_in[5];
    const float* qkv_w   = (const float*)d_in[6];
    const float* qkv_b   = (const float*)d_in[7];
    const float* o_w     = (const float*)d_in[8];
    const float* o_b     = (const float*)d_in[9];
    const float* ln2_g   = (const float*)d_in[10];
    const float* ln2_b   = (const float*)d_in[11];
    const float* up_w    = (const float*)d_in[12];
    const float* up_b    = (const float*)d_in[13];
    const float* down_w  = (const float*)d_in[14];
    const float* down_b  = (const float*)d_in[15];
    const float* lnf_g   = (const float*)d_in[16];
    const float* lnf_b   = (const float*)d_in[17];
    const float* lm_b    = (const float*)d_in[18];

    float *h, *nll, *logits_scratch, *pO, *pm, *pl;
    __half *xh, *qkvh, *attnh, *mlph, *qkvT, *oT, *upT, *downT, *wteH;
    cudaGetSymbolAddress((void**)&h,    g_h);
    cudaGetSymbolAddress((void**)&xh,   g_xh);
    cudaGetSymbolAddress((void**)&qkvh, g_qkvh);
    cudaGetSymbolAddress((void**)&attnh, g_attnh);
    cudaGetSymbolAddress((void**)&mlph, g_mlph);
    cudaGetSymbolAddress((void**)&nll,  g_nll);
    cudaGetSymbolAddress((void**)&logits_scratch, g_logits);
    cudaGetSymbolAddress((void**)&pO,   g_pO);
    cudaGetSymbolAddress((void**)&pm,   g_pm);
    cudaGetSymbolAddress((void**)&pl,   g_pl);
    cudaGetSymbolAddress((void**)&qkvT,  g_qkvT);
    cudaGetSymbolAddress((void**)&oT,    g_oT);
    cudaGetSymbolAddress((void**)&upT,   g_upT);
    cudaGetSymbolAddress((void**)&downT, g_downT);
    cudaGetSymbolAddress((void**)&wteH,  g_wteH);

    static bool attr_set = false;
    if (!attr_set) {
        cudaFuncSetAttribute(hgemm_k<0, false, false, true >, cudaFuncAttributeMaxDynamicSharedMemorySize, HSMEM);
        cudaFuncSetAttribute(hgemm_k<0, true,  false, false>, cudaFuncAttributeMaxDynamicSharedMemorySize, HSMEM);
        cudaFuncSetAttribute(hgemm_k<1, false, false, true >, cudaFuncAttributeMaxDynamicSharedMemorySize, HSMEM);
        cudaFuncSetAttribute(hgemm_k<0, false, true,  false>, cudaFuncAttributeMaxDynamicSharedMemorySize, HSMEM);
        attr_set = true;
    }

    float* logits = ((long long)out_size >= NBTV) ? (float*)d_out : logits_scratch;

    transh_k<<<dim3(3 * EE / 32, EE / 32, LL), dim3(32, 8)>>>(qkv_w, qkvT, EE, 3 * EE);
    transh_k<<<dim3(EE / 32, EE / 32, LL), dim3(32, 8)>>>(o_w, oT, EE, EE);
    transh_k<<<dim3(4 * EE / 32, EE / 32, LL), dim3(32, 8)>>>(up_w, upT, EE, 4 * EE);
    transh_k<<<dim3(EE / 32, 4 * EE / 32, LL), dim3(32, 8)>>>(down_w, downT, 4 * EE, EE);
    {
        int n = VV * EE / 4;
        halfcpy_k<<<(n + 255) / 256, 256>>>(wte, wteH, n);
    }

    embed_k<<<MM, 256>>>(idx, wte, wpe, h);

    for (int l = 0; l < LL; l++) {
        layernorm_k<<<MM, 256>>>(h, ln1_g + (size_t)l * EE, ln1_b + (size_t)l * EE, xh);
        hgemm_k<0, false, false, true><<<dim3(MM / 128, 3 * EE / 128), 256, HSMEM>>>(
            xh, qkvT + (size_t)l * 3 * EE * EE, qkv_b + (size_t)l * 3 * EE, nullptr,
            qkvh, MM, 3 * EE, EE);
        flash_attn_k<<<dim3(NU, BB * HH), 128>>>(qkvh, pO, pm, pl);
        fa_combine_k<<<dim3(TT / 64, BB * HH), 256>>>(pO, pm, pl, attnh);
        hgemm_k<0, true, false, false><<<dim3(MM / 128, EE / 128), 256, HSMEM>>>(
            attnh, oT + (size_t)l * EE * EE, o_b + (size_t)l * EE, h,
            h, MM, EE, EE);
        layernorm_k<<<MM, 256>>>(h, ln2_g + (size_t)l * EE, ln2_b + (size_t)l * EE, xh);
        hgemm_k<1, false, false, true><<<dim3(MM / 128, 4 * EE / 128), 256, HSMEM>>>(
            xh, upT + (size_t)l * 4 * EE * EE, up_b + (size_t)l * 4 * EE, nullptr,
            mlph, MM, 4 * EE, EE);
        hgemm_k<0, true, false, false><<<dim3(MM / 128, EE / 128), 256, HSMEM>>>(
            mlph, downT + (size_t)l * 4 * EE * EE, down_b + (size_t)l * EE, h,
            h, MM, EE, 4 * EE);
    }

    layernorm_k<<<MM, 256>>>(h, lnf_g, lnf_b, xh);
    hgemm_k<0, false, true, false><<<dim3(MM / 128, (VV + 127) / 128), 256, HSMEM>>>(
        xh, wteH, lm_b, nullptr, logits, MM, VV, EE);

    nll_k<<<MM, 256>>>(logits, targets, nll);

    long long extra = (long long)out_size - NBTV;
    if (extra > 0) {
        loss_reduce_k<<<1, 256>>>(nll, (float*)d_out + NBTV, (int)extra);
    } else if ((long long)out_size < NBTV) {
        loss_reduce_k<<<1, 256>>>(nll, (float*)d_out, out_size);
    }
}

// round 14
// speedup vs baseline: 1.0734x; 1.0239x over previous
#include <cuda_runtime.h>
#include <cuda_fp16.h>
#include <math.h>
#include <stdint.h>

// ---------------- Problem constants ----------------
static constexpr int BB = 2;
static constexpr int TT = 1024;
static constexpr int EE = 1024;
static constexpr int HH = 16;
static constexpr int DD = 64;
static constexpr int LL = 12;
static constexpr int VV = 50257;
static constexpr int MM = BB * TT;
static constexpr long long NBTV = (long long)MM * VV;
static constexpr int NU = 40;
static constexpr float L2E = 1.44269504088896340736f;
static constexpr int NTILE = (VV + 127) / 128;   // 393
static constexpr int NTP = 400;                  // padded stride

// ---------------- Scratch ----------------
__device__ float g_h   [(size_t)MM * EE];
__device__ __half g_xh  [(size_t)MM * EE];
__device__ __half g_qkvh[(size_t)MM * 3 * EE];
__device__ __half g_attnh[(size_t)MM * EE];
__device__ __half g_mlph [(size_t)MM * 4 * EE];
__device__ float g_nll [MM];
__device__ float g_logits[(size_t)MM * VV];
__device__ float g_pO[(size_t)BB * HH * NU * 64 * 64];
__device__ float g_pm[(size_t)BB * HH * NU * 64];
__device__ float g_pl[(size_t)BB * HH * NU * 64];
__device__ float g_sm_m[(size_t)MM * NTP];
__device__ float g_sm_l[(size_t)MM * NTP];
__device__ __half g_qkvT [(size_t)LL * 3 * EE * EE];
__device__ __half g_oT   [(size_t)LL * EE * EE];
__device__ __half g_upT  [(size_t)LL * 4 * EE * EE];
__device__ __half g_downT[(size_t)LL * 4 * EE * EE];
__device__ __half g_wteH [(size_t)VV * EE];

__constant__ int c_qi[NU] = {15,15,15,15, 14,14,14,14, 13,13,13,13, 12,12,12,12,
                             11,11,11, 10,10,10, 9,9,9, 8,8,8, 7,7, 6,6, 5,5, 4,4,
                             3, 2, 1, 0};
__constant__ int c_sp[NU] = {0,1,2,3, 0,1,2,3, 0,1,2,3, 0,1,2,3,
                             0,1,2, 0,1,2, 0,1,2, 0,1,2, 0,1, 0,1, 0,1, 0,1,
                             0, 0, 0, 0};
__constant__ int c_u0[16] = {39,38,37,36, 34,32,30,28, 25,22,19,16, 12,8,4,0};
__constant__ int c_ns[16] = {1,1,1,1, 2,2,2,2, 3,3,3,3, 4,4,4,4};

// ---------------- Helpers ----------------
__device__ __forceinline__ uint32_t smem_u32(const void* p) {
    uint32_t r;
    asm("{ .reg .u64 t; cvta.to.shared.u64 t, %1; cvt.u32.u64 %0, t; }" : "=r"(r) : "l"(p));
    return r;
}

__device__ __forceinline__ void mma_f16(float c[4], const uint32_t a[4], const uint32_t b[2]) {
    asm volatile(
        "mma.sync.aligned.m16n8k16.row.col.f32.f16.f16.f32 "
        "{%0,%1,%2,%3}, {%4,%5,%6,%7}, {%8,%9}, {%0,%1,%2,%3};"
        : "+f"(c[0]), "+f"(c[1]), "+f"(c[2]), "+f"(c[3])
        : "r"(a[0]), "r"(a[1]), "r"(a[2]), "r"(a[3]), "r"(b[0]), "r"(b[1]));
}

__device__ __forceinline__ void ldsm_x4(uint32_t r[4], uint32_t addr) {
    asm volatile("ldmatrix.sync.aligned.m8n8.x4.shared.b16 {%0,%1,%2,%3}, [%4];"
        : "=r"(r[0]), "=r"(r[1]), "=r"(r[2]), "=r"(r[3]) : "r"(addr));
}

__device__ __forceinline__ void st_half4(__half* p, float a, float b, float c, float d) {
    __half2 lo = __floats2half2_rn(a, b);
    __half2 hi = __floats2half2_rn(c, d);
    uint2 v = make_uint2(*(uint32_t*)&lo, *(uint32_t*)&hi);
    *(uint2*)p = v;
}

// two exps via one MUFU op: returns packed half2 {exp2(a), exp2(b)} for fp32 args
__device__ __forceinline__ uint32_t ex2_h2(float a, float b) {
    __half2 h = __floats2half2_rn(a, b);
    uint32_t u = *(uint32_t*)&h, o;
    asm("ex2.approx.f16x2 %0, %1;" : "=r"(o) : "r"(u));
    return o;
}

// ---------------- Weight prep ----------------
__global__ void transh_k(const float* __restrict__ W, __half* __restrict__ WT,
                         int K, int N) {
    __shared__ float tl[32][33];
    size_t off = (size_t)blockIdx.z * K * N;
    int n0 = blockIdx.x * 32, k0 = blockIdx.y * 32;
    int lx = threadIdx.x, ly = threadIdx.y;
#pragma unroll
    for (int i = 0; i < 4; i++)
        tl[ly + 8 * i][lx] = W[off + (size_t)(k0 + ly + 8 * i) * N + n0 + lx];
    __syncthreads();
#pragma unroll
    for (int i = 0; i < 4; i++)
        WT[off + (size_t)(n0 + ly + 8 * i) * K + k0 + lx] =
            __float2half_rn(tl[lx][ly + 8 * i]);
}

__global__ void halfcpy_k(const float* __restrict__ src, __half* __restrict__ dst, int n4) {
    int i = blockIdx.x * 256 + threadIdx.x;
    if (i < n4) {
        float4 v = *(const float4*)(src + (size_t)i * 4);
        st_half4(dst + (size_t)i * 4, v.x, v.y, v.z, v.w);
    }
}

// ---------------- Embedding ----------------
__global__ void embed_k(const int* __restrict__ idx, const float* __restrict__ wte,
                        const float* __restrict__ wpe, float* __restrict__ h) {
    int bt = blockIdx.x;
    int t  = bt % TT;
    int tok = idx[bt];
    int i = threadIdx.x * 4;
    float4 a = *(const float4*)(wte + (size_t)tok * EE + i);
    float4 p = *(const float4*)(wpe + (size_t)t   * EE + i);
    a.x += p.x; a.y += p.y; a.z += p.z; a.w += p.w;
    *(float4*)(h + (size_t)bt * EE + i) = a;
}

// ---------------- LayerNorm: fp32 in, half out ----------------
__global__ void layernorm_k(const float* __restrict__ xin, const float* __restrict__ g,
                            const float* __restrict__ bb, __half* __restrict__ y) {
    __shared__ float rs[8], rq[8];
    int row = blockIdx.x, tid = threadIdx.x;
    const float* xr = xin + (size_t)row * EE;
    float4 v = *(const float4*)(xr + tid * 4);
    float s = v.x + v.y + v.z + v.w;
    float q = v.x * v.x + v.y * v.y + v.z * v.z + v.w * v.w;
#pragma unroll
    for (int o = 16; o; o >>= 1) {
        s += __shfl_xor_sync(0xffffffffu, s, o);
        q += __shfl_xor_sync(0xffffffffu, q, o);
    }
    if ((tid & 31) == 0) { rs[tid >> 5] = s; rq[tid >> 5] = q; }
    __syncthreads();
    if (tid == 0) {
        float S = 0.f, Q = 0.f;
#pragma unroll
        for (int i = 0; i < 8; i++) { S += rs[i]; Q += rq[i]; }
        rs[0] = S; rq[0] = Q;
    }
    __syncthreads();
    float mean = rs[0] * (1.f / EE);
    float var  = rq[0] * (1.f / EE) - mean * mean;
    float rstd = rsqrtf(var + 1e-5f);
    float4 gg = *(const float4*)(g  + tid * 4);
    float4 be = *(const float4*)(bb + tid * 4);
    st_half4(y + (size_t)row * EE + tid * 4,
             (v.x - mean) * rstd * gg.x + be.x,
             (v.y - mean) * rstd * gg.y + be.y,
             (v.z - mean) * rstd * gg.z + be.z,
             (v.w - mean) * rstd * gg.w + be.w);
}

// ---------------- cp.async 3-stage fp16 GEMM with ldmatrix (MT=128) ----------------
static constexpr int H_AST = 72;
static constexpr int H_STG = 2 * 128 * H_AST;
static constexpr int HSMEM = 3 * H_STG * 2;

template<int ACT, bool RES, bool GUARD, bool OUT_HALF, bool SMAX>
__global__ __launch_bounds__(256, 2)
void hgemm_k(const __half* __restrict__ A, const __half* __restrict__ Bw,
             const float* __restrict__ bias, const float* __restrict__ Res,
             void* __restrict__ Cv, int M, int N, int K,
             float* __restrict__ smM, float* __restrict__ smL) {
    extern __shared__ __half smh[];
    const uint32_t sb = smem_u32(smh);
    const int tid  = threadIdx.x;
    const int lane = tid & 31;
    const int wid  = tid >> 5;
    const int wm   = wid >> 2;
    const int wn   = wid & 3;
    const int g    = lane >> 2;
    const int t    = lane & 3;
    const int la16  = lane & 15;
    const int lac8  = (lane >> 4) << 3;
    const int lbrow = ((lane >> 4) << 3) + (lane & 7);
    const int lbcol = ((lane >> 3) & 1) << 3;

    const int row0 = blockIdx.x * 128;
    const int col0 = blockIdx.y * 128;
    const int iters = K >> 6;

    auto issue_stage = [&](int it) {
        const int k0 = it << 6;
        const int s = it % 3;
        const uint32_t stA = sb + (uint32_t)(s * H_STG) * 2;
        const uint32_t stB = stA + (uint32_t)(128 * H_AST) * 2;
#pragma unroll
        for (int u = 0; u < 4; u++) {
            int ca = u * 256 + tid;
            int r = ca >> 3, c16 = ca & 7;
            const __half* gs = A + (size_t)(row0 + r) * K + k0 + c16 * 8;
            uint32_t sd = stA + (uint32_t)(r * H_AST + c16 * 8) * 2;
            asm volatile("cp.async.cg.shared.global [%0], [%1], 16;" :: "r"(sd), "l"(gs));
        }
#pragma unroll
        for (int u = 0; u < 4; u++) {
            int cb = u * 256 + tid;
            int n = cb >> 3, c16 = cb & 7;
            const __half* gs = Bw + (size_t)(col0 + n) * K + k0 + c16 * 8;
            uint32_t sd = stB + (uint32_t)(n * H_AST + c16 * 8) * 2;
            if (GUARD) {
                int sz = (col0 + n < N) ? 16 : 0;
                asm volatile("cp.async.cg.shared.global [%0], [%1], 16, %2;"
                             :: "r"(sd), "l"(gs), "r"(sz));
            } else {
                asm volatile("cp.async.cg.shared.global [%0], [%1], 16;" :: "r"(sd), "l"(gs));
            }
        }
        asm volatile("cp.async.commit_group;" ::: "memory");
    };

    float acc[4][4][4] = {};

    issue_stage(0);
    issue_stage(1);

    for (int it = 0; it < iters; ++it) {
        if (it == iters - 1) {
            asm volatile("cp.async.wait_group 0;" ::: "memory");
        } else {
            asm volatile("cp.async.wait_group 1;" ::: "memory");
        }
        __syncthreads();
        if (it + 2 < iters) issue_stage(it + 2);

        const uint32_t stA = sb + (uint32_t)((it % 3) * H_STG) * 2;
        const uint32_t stB = stA + (uint32_t)(128 * H_AST) * 2;
        const uint32_t aBase = stA + (uint32_t)((wm * 64 + la16) * H_AST + lac8) * 2;
        const uint32_t bBase = stB + (uint32_t)((wn * 32 + lbrow) * H_AST + lbcol) * 2;
#pragma unroll
        for (int ks = 0; ks < 4; ks++) {
            uint32_t afr[4][4];
            uint32_t bfr[4][2];
#pragma unroll
            for (int mt = 0; mt < 4; mt++)
                ldsm_x4(afr[mt], aBase + (uint32_t)(mt * 16 * H_AST + ks * 16) * 2);
#pragma unroll
            for (int ntp = 0; ntp < 2; ntp++) {
                uint32_t bp[4];
                ldsm_x4(bp, bBase + (uint32_t)(ntp * 16 * H_AST + ks * 16) * 2);
                bfr[2 * ntp][0]     = bp[0]; bfr[2 * ntp][1]     = bp[1];
                bfr[2 * ntp + 1][0] = bp[2]; bfr[2 * ntp + 1][1] = bp[3];
            }
#pragma unroll
            for (int mt = 0; mt < 4; mt++)
#pragma unroll
                for (int nt = 0; nt < 4; nt++)
                    mma_f16(acc[mt][nt], afr[mt], bfr[nt]);
        }
    }

    // ---- epilogue ----
#pragma unroll
    for (int mt = 0; mt < 4; mt++) {
        int r0 = row0 + wm * 64 + mt * 16 + g;
#pragma unroll
        for (int nt = 0; nt < 4; nt++) {
            int c = col0 + wn * 32 + nt * 8 + t * 2;
#pragma unroll
            for (int half_i = 0; half_i < 2; half_i++) {
                int r = r0 + half_i * 8;
                float v0 = acc[mt][nt][half_i * 2 + 0];
                float v1 = acc[mt][nt][half_i * 2 + 1];
                if (GUARD) {
                    float* C = (float*)Cv;
                    if (c < N)     C[(size_t)r * N + c]     = v0 + bias[c];
                    if (c + 1 < N) C[(size_t)r * N + c + 1] = v1 + bias[c + 1];
                } else {
                    v0 += bias[c]; v1 += bias[c + 1];
                    if (ACT == 1) {
                        v0 = 0.5f * v0 * (1.f + erff(v0 * 0.70710678118654752f));
                        v1 = 0.5f * v1 * (1.f + erff(v1 * 0.70710678118654752f));
                    }
                    if (RES) {
                        v0 += Res[(size_t)r * N + c];
                        v1 += Res[(size_t)r * N + c + 1];
                    }
                    if (OUT_HALF) {
                        __half2 hv = __floats2half2_rn(v0, v1);
                        *(__half2*)((__half*)Cv + (size_t)r * N + c) = hv;
                    } else {
                        *(float2*)((float*)Cv + (size_t)r * N + c) = make_float2(v0, v1);
                    }
                }
            }
        }
    }

    // ---- fused per-row softmax partials (LM head) ----
    if (SMAX) {
        float* red = (float*)smh;   // 128 rows x 4 warps
        __syncthreads();            // smem reuse safe
        float rmax[8];
#pragma unroll
        for (int idx = 0; idx < 8; idx++) {
            int mt = idx >> 1, hi = idx & 1;
            float m = -1e30f;
#pragma unroll
            for (int nt = 0; nt < 4; nt++) {
                int c = col0 + wn * 32 + nt * 8 + t * 2;
                float v0 = (c < N)     ? acc[mt][nt][hi * 2 + 0] + bias[c]     : -1e30f;
                float v1 = (c + 1 < N) ? acc[mt][nt][hi * 2 + 1] + bias[c + 1] : -1e30f;
                m = fmaxf(m, fmaxf(v0, v1));
            }
            m = fmaxf(m, __shfl_xor_sync(0xffffffffu, m, 1));
            m = fmaxf(m, __shfl_xor_sync(0xffffffffu, m, 2));
            rmax[idx] = m;
        }
        if (t == 0) {
#pragma unroll
            for (int idx = 0; idx < 8; idx++) {
                int rc = wm * 64 + (idx >> 1) * 16 + (idx & 1) * 8 + g;
                red[rc * 4 + wn] = rmax[idx];
            }
        }
        __syncthreads();
#pragma unroll
        for (int idx = 0; idx < 8; idx++) {
            int rc = wm * 64 + (idx >> 1) * 16 + (idx & 1) * 8 + g;
            float m = fmaxf(fmaxf(red[rc * 4 + 0], red[rc * 4 + 1]),
                            fmaxf(red[rc * 4 + 2], red[rc * 4 + 3]));
            rmax[idx] = m;
        }
        __syncthreads();
        float rsum[8];
#pragma unroll
        for (int idx = 0; idx < 8; idx++) {
            int mt = idx >> 1, hi = idx & 1;
            const float mb = rmax[idx] * L2E;
            float s = 0.f;
#pragma unroll
            for (int nt = 0; nt < 4; nt++) {
                int c = col0 + wn * 32 + nt * 8 + t * 2;
                float v0 = (c < N)     ? acc[mt][nt][hi * 2 + 0] + bias[c]     : -1e30f;
                float v1 = (c + 1 < N) ? acc[mt][nt][hi * 2 + 1] + bias[c + 1] : -1e30f;
                uint32_t e = ex2_h2(fmaf(v0, L2E, -mb), fmaf(v1, L2E, -mb));
                float2 f = __half22float2(*(__half2*)&e);
                s += f.x + f.y;
            }
            s += __shfl_xor_sync(0xffffffffu, s, 1);
            s += __shfl_xor_sync(0xffffffffu, s, 2);
            rsum[idx] = s;
        }
        if (t == 0) {
#pragma unroll
            for (int idx = 0; idx < 8; idx++) {
                int rc = wm * 64 + (idx >> 1) * 16 + (idx & 1) * 8 + g;
                red[rc * 4 + wn] = rsum[idx];
            }
        }
        __syncthreads();
        if (t == 0 && wn == 0) {
#pragma unroll
            for (int idx = 0; idx < 8; idx++) {
                int rc = wm * 64 + (idx >> 1) * 16 + (idx & 1) * 8 + g;
                float L = red[rc * 4 + 0] + red[rc * 4 + 1] + red[rc * 4 + 2] + red[rc * 4 + 3];
                smM[(size_t)(row0 + rc) * NTP + blockIdx.y] = rmax[idx];
                smL[(size_t)(row0 + rc) * NTP + blockIdx.y] = L;
            }
        }
    }
}

// ---------------- Tensor-core split-KV flash attention ----------------
static constexpr int FH_PAD = 72;

__global__ __launch_bounds__(128)
void flash_attn_k(const __half* __restrict__ qkv, float* __restrict__ pO,
                  float* __restrict__ pm, float* __restrict__ pl,
                  __half* __restrict__ attnOut) {
    __shared__ __half Qh[64 * FH_PAD];
    __shared__ __half Kh[64 * FH_PAD];
    __shared__ __half Vt[64 * FH_PAD];

    const int tid  = threadIdx.x;
    const int lane = tid & 31;
    const int wid  = tid >> 5;
    const int g    = lane >> 2;
    const int t    = lane & 3;
    const int wr   = wid * 16;

    const int u  = blockIdx.x;
    const int bh = blockIdx.y;
    const int qi = c_qi[u];
    const int sp = c_sp[u];
    const int q0 = qi * 64;
    const int b = bh / HH, h = bh % HH;

    const __half* base = qkv + (size_t)b * TT * 3 * EE + h * DD;

    {
        int r = tid >> 1, cpart = tid & 1;
        const __half* qp = base + (size_t)(q0 + r) * 3 * EE + cpart * 32;
#pragma unroll
        for (int i = 0; i < 4; i++)
            *(uint4*)(Qh + r * FH_PAD + cpart * 32 + i * 8) = *(const uint4*)(qp + i * 8);
    }

    float m_old[2] = {-1e30f, -1e30f};
    float lsum[2]  = {0.f, 0.f};
    float oacc[8][4] = {};
    const int c0 = sp * 4;
    const int c1 = min(c0 + 4, qi + 1);

    for (int ch = c0; ch < c1; ch++) {
        const int kt = ch * 64;
        __syncthreads();
        {
            int r = tid >> 1, cpart = tid & 1;
            const __half* kp = base + (size_t)(kt + r) * 3 * EE + EE + cpart * 32;
            const __half* vp = base + (size_t)(kt + r) * 3 * EE + 2 * EE + cpart * 32;
#pragma unroll
            for (int i = 0; i < 4; i++) {
                *(uint4*)(Kh + r * FH_PAD + cpart * 32 + i * 8) = *(const uint4*)(kp + i * 8);
                uint4 vv = *(const uint4*)(vp + i * 8);
                const __half* hv = (const __half*)&vv;
                int d = cpart * 32 + i * 8;
#pragma unroll
                for (int j = 0; j < 8; j++)
                    Vt[(d + j) * FH_PAD + r] = hv[j];
            }
        }
        __syncthreads();

        float sacc[8][4] = {};
#pragma unroll
        for (int j = 0; j < 4; j++) {
            const int kk = j * 16 + t * 2;
            uint32_t a[4];
            a[0] = *(const uint32_t*)&Qh[(wr + g)     * FH_PAD + kk];
            a[1] = *(const uint32_t*)&Qh[(wr + g + 8) * FH_PAD + kk];
            a[2] = *(const uint32_t*)&Qh[(wr + g)     * FH_PAD + kk + 8];
            a[3] = *(const uint32_t*)&Qh[(wr + g + 8) * FH_PAD + kk + 8];
#pragma unroll
            for (int nt = 0; nt < 8; nt++) {
                uint32_t bfr[2];
                bfr[0] = *(const uint32_t*)&Kh[(nt * 8 + g) * FH_PAD + kk];
                bfr[1] = *(const uint32_t*)&Kh[(nt * 8 + g) * FH_PAD + kk + 8];
                mma_f16(sacc[nt], a, bfr);
            }
        }

        const bool diag = (ch == qi);
        uint32_t ap[4][4];
        float al[2];
#pragma unroll
        for (int rh = 0; rh < 2; rh++) {
            int row = q0 + wr + g + rh * 8;
            float pv[16];
            float lm = -1e30f;
#pragma unroll
            for (int nt = 0; nt < 8; nt++) {
#pragma unroll
                for (int jj = 0; jj < 2; jj++) {
                    float s = sacc[nt][rh * 2 + jj] * 0.125f;
                    if (diag && (kt + nt * 8 + t * 2 + jj > row)) s = -1e30f;
                    pv[nt * 2 + jj] = s;
                    lm = fmaxf(lm, s);
                }
            }
            lm = fmaxf(lm, __shfl_xor_sync(0xffffffffu, lm, 1));
            lm = fmaxf(lm, __shfl_xor_sync(0xffffffffu, lm, 2));
            float mnew = fmaxf(m_old[rh], lm);
            al[rh] = __expf(m_old[rh] - mnew);
            m_old[rh] = mnew;
            const float mb = mnew * L2E;
            float ls = 0.f;
#pragma unroll
            for (int j = 0; j < 4; j++) {
                uint32_t p01 = ex2_h2(fmaf(pv[4 * j + 0], L2E, -mb),
                                      fmaf(pv[4 * j + 1], L2E, -mb));
                uint32_t p23 = ex2_h2(fmaf(pv[4 * j + 2], L2E, -mb),
                                      fmaf(pv[4 * j + 3], L2E, -mb));
                ap[j][rh]     = p01;
                ap[j][rh + 2] = p23;
                float2 f0 = __half22float2(*(__half2*)&p01);
                float2 f1 = __half22float2(*(__half2*)&p23);
                ls += (f0.x + f0.y) + (f1.x + f1.y);
            }
            ls += __shfl_xor_sync(0xffffffffu, ls, 1);
            ls += __shfl_xor_sync(0xffffffffu, ls, 2);
            lsum[rh] = lsum[rh] * al[rh] + ls;
        }

#pragma unroll
        for (int dt = 0; dt < 8; dt++) {
            oacc[dt][0] *= al[0]; oacc[dt][1] *= al[0];
            oacc[dt][2] *= al[1]; oacc[dt][3] *= al[1];
        }
#pragma unroll
        for (int j = 0; j < 4; j++) {
            const int kk = j * 16 + t * 2;
#pragma unroll
            for (int dt = 0; dt < 8; dt++) {
                uint32_t bfr[2];
                bfr[0] = *(const uint32_t*)&Vt[(dt * 8 + g) * FH_PAD + kk];
                bfr[1] = *(const uint32_t*)&Vt[(dt * 8 + g) * FH_PAD + kk + 8];
                mma_f16(oacc[dt], ap[j], bfr);
            }
        }
    }

    int r0 = wr + g;
    if (c_ns[qi] == 1) {
        // single split: normalize and write attnh directly
        float inv0 = 1.f / lsum[0], inv1 = 1.f / lsum[1];
        size_t tok0 = (size_t)(b * TT + q0 + r0);
#pragma unroll
        for (int dt = 0; dt < 8; dt++) {
            __half2 h0 = __floats2half2_rn(oacc[dt][0] * inv0, oacc[dt][1] * inv0);
            __half2 h1 = __floats2half2_rn(oacc[dt][2] * inv1, oacc[dt][3] * inv1);
            *(__half2*)(attnOut + tok0 * EE + h * DD + dt * 8 + t * 2) = h0;
            *(__half2*)(attnOut + (tok0 + 8) * EE + h * DD + dt * 8 + t * 2) = h1;
        }
    } else {
        float* po = pO + ((size_t)(bh * NU + u) * 64) * 64;
#pragma unroll
        for (int dt = 0; dt < 8; dt++) {
            *(float2*)(po + (size_t)r0 * 64 + dt * 8 + t * 2)       = make_float2(oacc[dt][0], oacc[dt][1]);
            *(float2*)(po + (size_t)(r0 + 8) * 64 + dt * 8 + t * 2) = make_float2(oacc[dt][2], oacc[dt][3]);
        }
        if (t == 0) {
            pm[(size_t)(bh * NU + u) * 64 + r0]     = m_old[0];
            pm[(size_t)(bh * NU + u) * 64 + r0 + 8] = m_old[1];
            pl[(size_t)(bh * NU + u) * 64 + r0]     = lsum[0];
            pl[(size_t)(bh * NU + u) * 64 + r0 + 8] = lsum[1];
        }
    }
}

// Combine split partials (qi 4..15 only); half output
__global__ __launch_bounds__(256)
void fa_combine_k(const float* __restrict__ pO, const float* __restrict__ pm,
                  const float* __restrict__ pl, __half* __restrict__ out) {
    const int qi = blockIdx.x + 4;
    const int bh = blockIdx.y;
    const int b = bh / HH, h = bh % HH;
    const int ns = c_ns[qi];
    const int u0 = c_u0[qi];
    const int tid = threadIdx.x;
    const int r4 = tid >> 6;
    const int d  = tid & 63;
    for (int p = 0; p < 16; p++) {
        int row = p * 4 + r4;
        float M = -1e30f;
        for (int s = 0; s < ns; s++)
            M = fmaxf(M, pm[(size_t)(bh * NU + u0 + s) * 64 + row]);
        float L = 0.f, O = 0.f;
        for (int s = 0; s < ns; s++) {
            size_t ub = (size_t)(bh * NU + u0 + s);
            float w = __expf(pm[ub * 64 + row] - M);
            L += w * pl[ub * 64 + row];
            O += w * pO[(ub * 64 + row) * 64 + d];
        }
        out[((size_t)(b * TT + qi * 64 + row)) * EE + h * DD + d] = __float2half_rn(O / L);
    }
}

// ---------------- NLL from fused partials ----------------
__global__ __launch_bounds__(128)
void nll2_k(const float* __restrict__ logits, const float* __restrict__ smM,
            const float* __restrict__ smL, const int* __restrict__ tgt,
            float* __restrict__ nll) {
    const int row = blockIdx.x;
    const int tid = threadIdx.x;
    __shared__ float sh[128];
    float M = -1e30f;
    for (int i = tid; i < NTILE; i += 128)
        M = fmaxf(M, smM[(size_t)row * NTP + i]);
    sh[tid] = M; __syncthreads();
    for (int o = 64; o; o >>= 1) { if (tid < o) sh[tid] = fmaxf(sh[tid], sh[tid + o]); __syncthreads(); }
    M = sh[0]; __syncthreads();
    float L = 0.f;
    for (int i = tid; i < NTILE; i += 128)
        L += smL[(size_t)row * NTP + i] * __expf(smM[(size_t)row * NTP + i] - M);
    sh[tid] = L; __syncthreads();
    for (int o = 64; o; o >>= 1) { if (tid < o) sh[tid] += sh[tid + o]; __syncthreads(); }
    if (tid == 0)
        nll[row] = logf(sh[0]) + M - logits[(size_t)row * VV + tgt[row]];
}

__global__ void loss_reduce_k(const float* __restrict__ nll, float* __restrict__ dst, int count) {
    __shared__ float sh[256];
    float s = 0.f;
    for (int i = threadIdx.x; i < MM; i += 256) s += nll[i];
    sh[threadIdx.x] = s; __syncthreads();
    for (int o = 128; o; o >>= 1) { if (threadIdx.x < o) sh[threadIdx.x] += sh[threadIdx.x + o]; __syncthreads(); }
    if (threadIdx.x == 0) {
        float loss = sh[0] * (1.f / (float)MM);
        for (int i = 0; i < count; i++) dst[i] = loss;
    }
}

// ---------------- Launch ----------------
extern "C" void kernel_launch(void* const* d_in, const int* in_sizes, int n_in,
                              void* d_out, int out_size) {
    const int*   idx     = (const int*)  d_in[0];
    const int*   targets = (const int*)  d_in[1];
    const float* wte     = (const float*)d_in[2];
    const float* wpe     = (const float*)d_in[3];
    const float* ln1_g   = (const float*)d_in[4];
    const float* ln1_b   = (const float*)d_in[5];
    const float* qkv_w   = (const float*)d_in[6];
    const float* qkv_b   = (const float*)d_in[7];
    const float* o_w     = (const float*)d_in[8];
    const float* o_b     = (const float*)d_in[9];
    const float* ln2_g   = (const float*)d_in[10];
    const float* ln2_b   = (const float*)d_in[11];
    const float* up_w    = (const float*)d_in[12];
    const float* up_b    = (const float*)d_in[13];
    const float* down_w  = (const float*)d_in[14];
    const float* down_b  = (const float*)d_in[15];
    const float* lnf_g   = (const float*)d_in[16];
    const float* lnf_b   = (const float*)d_in[17];
    const float* lm_b    = (const float*)d_in[18];

    float *h, *nll, *logits_scratch, *pO, *pm, *pl, *smM, *smL;
    __half *xh, *qkvh, *attnh, *mlph, *qkvT, *oT, *upT, *downT, *wteH;
    cudaGetSymbolAddress((void**)&h,    g_h);
    cudaGetSymbolAddress((void**)&xh,   g_xh);
    cudaGetSymbolAddress((void**)&qkvh, g_qkvh);
    cudaGetSymbolAddress((void**)&attnh, g_attnh);
    cudaGetSymbolAddress((void**)&mlph, g_mlph);
    cudaGetSymbolAddress((void**)&nll,  g_nll);
    cudaGetSymbolAddress((void**)&logits_scratch, g_logits);
    cudaGetSymbolAddress((void**)&pO,   g_pO);
    cudaGetSymbolAddress((void**)&pm,   g_pm);
    cudaGetSymbolAddress((void**)&pl,   g_pl);
    cudaGetSymbolAddress((void**)&smM,  g_sm_m);
    cudaGetSymbolAddress((void**)&smL,  g_sm_l);
    cudaGetSymbolAddress((void**)&qkvT,  g_qkvT);
    cudaGetSymbolAddress((void**)&oT,    g_oT);
    cudaGetSymbolAddress((void**)&upT,   g_upT);
    cudaGetSymbolAddress((void**)&downT, g_downT);
    cudaGetSymbolAddress((void**)&wteH,  g_wteH);

    static bool attr_set = false;
    if (!attr_set) {
        cudaFuncSetAttribute(hgemm_k<0, false, false, true,  false>, cudaFuncAttributeMaxDynamicSharedMemorySize, HSMEM);
        cudaFuncSetAttribute(hgemm_k<0, true,  false, false, false>, cudaFuncAttributeMaxDynamicSharedMemorySize, HSMEM);
        cudaFuncSetAttribute(hgemm_k<1, false, false, true,  false>, cudaFuncAttributeMaxDynamicSharedMemorySize, HSMEM);
        cudaFuncSetAttribute(hgemm_k<0, false, true,  false, true >, cudaFuncAttributeMaxDynamicSharedMemorySize, HSMEM);
        attr_set = true;
    }

    float* logits = ((long long)out_size >= NBTV) ? (float*)d_out : logits_scratch;

    transh_k<<<dim3(3 * EE / 32, EE / 32, LL), dim3(32, 8)>>>(qkv_w, qkvT, EE, 3 * EE);
    transh_k<<<dim3(EE / 32, EE / 32, LL), dim3(32, 8)>>>(o_w, oT, EE, EE);
    transh_k<<<dim3(4 * EE / 32, EE / 32, LL), dim3(32, 8)>>>(up_w, upT, EE, 4 * EE);
    transh_k<<<dim3(EE / 32, 4 * EE / 32, LL), dim3(32, 8)>>>(down_w, downT, 4 * EE, EE);
    {
        int n = VV * EE / 4;
        halfcpy_k<<<(n + 255) / 256, 256>>>(wte, wteH, n);
    }

    embed_k<<<MM, 256>>>(idx, wte, wpe, h);

    for (int l = 0; l < LL; l++) {
        layernorm_k<<<MM, 256>>>(h, ln1_g + (size_t)l * EE, ln1_b + (size_t)l * EE, xh);
        hgemm_k<0, false, false, true, false><<<dim3(MM / 128, 3 * EE / 128), 256, HSMEM>>>(
            xh, qkvT + (size_t)l * 3 * EE * EE, qkv_b + (size_t)l * 3 * EE, nullptr,
            qkvh, MM, 3 * EE, EE, nullptr, nullptr);
        flash_attn_k<<<dim3(NU, BB * HH), 128>>>(qkvh, pO, pm, pl, attnh);
        fa_combine_k<<<dim3(12, BB * HH), 256>>>(pO, pm, pl, attnh);
        hgemm_k<0, true, false, false, false><<<dim3(MM / 128, EE / 128), 256, HSMEM>>>(
            attnh, oT + (size_t)l * EE * EE, o_b + (size_t)l * EE, h,
            h, MM, EE, EE, nullptr, nullptr);
        layernorm_k<<<MM, 256>>>(h, ln2_g + (size_t)l * EE, ln2_b + (size_t)l * EE, xh);
        hgemm_k<1, false, false, true, false><<<dim3(MM / 128, 4 * EE / 128), 256, HSMEM>>>(
            xh, upT + (size_t)l * 4 * EE * EE, up_b + (size_t)l * 4 * EE, nullptr,
            mlph, MM, 4 * EE, EE, nullptr, nullptr);
        hgemm_k<0, true, false, false, false><<<dim3(MM / 128, EE / 128), 256, HSMEM>>>(
            mlph, downT + (size_t)l * 4 * EE * EE, down_b + (size_t)l * EE, h,
            h, MM, EE, 4 * EE, nullptr, nullptr);
    }

    layernorm_k<<<MM, 256>>>(h, lnf_g, lnf_b, xh);
    hgemm_k<0, false, true, false, true><<<dim3(MM / 128, (VV + 127) / 128), 256, HSMEM>>>(
        xh, wteH, lm_b, nullptr, logits, MM, VV, EE, smM, smL);

    nll2_k<<<MM, 128>>>(logits, smM, smL, targets, nll);

    long long extra = (long long)out_size - NBTV;
    if (extra > 0) {
        loss_reduce_k<<<1, 256>>>(nll, (float*)d_out + NBTV, (int)extra);
    } else if ((long long)out_size < NBTV) {
        loss_reduce_k<<<1, 256>>>(nll, (float*)d_out, out_size);
    }
}

// round 15
// speedup vs baseline: 1.0818x; 1.0078x over previous
#include <cuda_runtime.h>
#include <cuda_fp16.h>
#include <math.h>
#include <stdint.h>

// ---------------- Problem constants ----------------
static constexpr int BB = 2;
static constexpr int TT = 1024;
static constexpr int EE = 1024;
static constexpr int HH = 16;
static constexpr int DD = 64;
static constexpr int LL = 12;
static constexpr int VV = 50257;
static constexpr int MM = BB * TT;
static constexpr long long NBTV = (long long)MM * VV;
static constexpr int NU = 40;
static constexpr float L2E = 1.44269504088896340736f;
static constexpr int NTILE = (VV + 127) / 128;   // 393
static constexpr int NTP = 400;                  // padded stride

// ---------------- Scratch ----------------
__device__ float g_h   [(size_t)MM * EE];
__device__ __half g_xh  [(size_t)MM * EE];
__device__ __half g_qkvh[(size_t)MM * 3 * EE];
__device__ __half g_attnh[(size_t)MM * EE];
__device__ __half g_mlph [(size_t)MM * 4 * EE];
__device__ float g_nll [MM];
__device__ float g_logits[(size_t)MM * VV];
__device__ float g_pO[(size_t)BB * HH * NU * 64 * 64];
__device__ float g_pm[(size_t)BB * HH * NU * 64];
__device__ float g_pl[(size_t)BB * HH * NU * 64];
__device__ float g_sm_m[(size_t)MM * NTP];
__device__ float g_sm_l[(size_t)MM * NTP];
__device__ __half g_qkvT [(size_t)LL * 3 * EE * EE];
__device__ __half g_oT   [(size_t)LL * EE * EE];
__device__ __half g_upT  [(size_t)LL * 4 * EE * EE];
__device__ __half g_downT[(size_t)LL * 4 * EE * EE];
__device__ __half g_wteH [(size_t)VV * EE];

__constant__ int c_qi[NU] = {15,15,15,15, 14,14,14,14, 13,13,13,13, 12,12,12,12,
                             11,11,11, 10,10,10, 9,9,9, 8,8,8, 7,7, 6,6, 5,5, 4,4,
                             3, 2, 1, 0};
__constant__ int c_sp[NU] = {0,1,2,3, 0,1,2,3, 0,1,2,3, 0,1,2,3,
                             0,1,2, 0,1,2, 0,1,2, 0,1,2, 0,1, 0,1, 0,1, 0,1,
                             0, 0, 0, 0};
__constant__ int c_u0[16] = {39,38,37,36, 34,32,30,28, 25,22,19,16, 12,8,4,0};
__constant__ int c_ns[16] = {1,1,1,1, 2,2,2,2, 3,3,3,3, 4,4,4,4};

// ---------------- Helpers ----------------
__device__ __forceinline__ uint32_t smem_u32(const void* p) {
    uint32_t r;
    asm("{ .reg .u64 t; cvta.to.shared.u64 t, %1; cvt.u32.u64 %0, t; }" : "=r"(r) : "l"(p));
    return r;
}

__device__ __forceinline__ void mma_f16(float c[4], const uint32_t a[4], const uint32_t b[2]) {
    asm volatile(
        "mma.sync.aligned.m16n8k16.row.col.f32.f16.f16.f32 "
        "{%0,%1,%2,%3}, {%4,%5,%6,%7}, {%8,%9}, {%0,%1,%2,%3};"
        : "+f"(c[0]), "+f"(c[1]), "+f"(c[2]), "+f"(c[3])
        : "r"(a[0]), "r"(a[1]), "r"(a[2]), "r"(a[3]), "r"(b[0]), "r"(b[1]));
}

__device__ __forceinline__ void ldsm_x4(uint32_t r[4], uint32_t addr) {
    asm volatile("ldmatrix.sync.aligned.m8n8.x4.shared.b16 {%0,%1,%2,%3}, [%4];"
        : "=r"(r[0]), "=r"(r[1]), "=r"(r[2]), "=r"(r[3]) : "r"(addr));
}

__device__ __forceinline__ void st_half4(__half* p, float a, float b, float c, float d) {
    __half2 lo = __floats2half2_rn(a, b);
    __half2 hi = __floats2half2_rn(c, d);
    uint2 v = make_uint2(*(uint32_t*)&lo, *(uint32_t*)&hi);
    *(uint2*)p = v;
}

// two exps via one MUFU op: returns packed half2 {exp2(a), exp2(b)} for fp32 args
__device__ __forceinline__ uint32_t ex2_h2(float a, float b) {
    __half2 h = __floats2half2_rn(a, b);
    uint32_t u = *(uint32_t*)&h, o;
    asm("ex2.approx.f16x2 %0, %1;" : "=r"(o) : "r"(u));
    return o;
}

// ---------------- Weight prep: W[K,N] fp32 -> WT[N,K] half (vectorized 64x64) ----------------
__global__ void transh_k(const float* __restrict__ W, __half* __restrict__ WT,
                         int K, int N) {
    __shared__ float tl[64][65];
    size_t off = (size_t)blockIdx.z * K * N;
    int n0 = blockIdx.x * 64, k0 = blockIdx.y * 64;
    int tid = threadIdx.x;
    // read: 64k x 64n, float4 per thread x 4 rows
    int rr = tid >> 4;               // 0..15
    int rc = (tid & 15) << 2;        // 0..60
#pragma unroll
    for (int i = 0; i < 4; i++) {
        float4 v = *(const float4*)(W + off + (size_t)(k0 + rr + 16 * i) * N + n0 + rc);
        tl[rr + 16 * i][rc + 0] = v.x;
        tl[rr + 16 * i][rc + 1] = v.y;
        tl[rr + 16 * i][rc + 2] = v.z;
        tl[rr + 16 * i][rc + 3] = v.w;
    }
    __syncthreads();
    // write: 64n rows x 64k, 8 halfs (uint4) per thread x 2 rows
    int wn = tid >> 3;               // 0..31
    int wk = (tid & 7) << 3;         // 0..56
#pragma unroll
    for (int i = 0; i < 2; i++) {
        int n = wn + 32 * i;
        __half hv[8];
#pragma unroll
        for (int j = 0; j < 8; j++) hv[j] = __float2half_rn(tl[wk + j][n]);
        *(uint4*)(WT + off + (size_t)(n0 + n) * K + k0 + wk) = *(uint4*)hv;
    }
}

__global__ void halfcpy_k(const float* __restrict__ src, __half* __restrict__ dst, int n4) {
    int i = blockIdx.x * 256 + threadIdx.x;
    if (i < n4) {
        float4 v = *(const float4*)(src + (size_t)i * 4);
        st_half4(dst + (size_t)i * 4, v.x, v.y, v.z, v.w);
    }
}

// ---------------- Embedding ----------------
__global__ void embed_k(const int* __restrict__ idx, const float* __restrict__ wte,
                        const float* __restrict__ wpe, float* __restrict__ h) {
    int bt = blockIdx.x;
    int t  = bt % TT;
    int tok = idx[bt];
    int i = threadIdx.x * 4;
    float4 a = *(const float4*)(wte + (size_t)tok * EE + i);
    float4 p = *(const float4*)(wpe + (size_t)t   * EE + i);
    a.x += p.x; a.y += p.y; a.z += p.z; a.w += p.w;
    *(float4*)(h + (size_t)bt * EE + i) = a;
}

// ---------------- LayerNorm: fp32 in, half out ----------------
__global__ void layernorm_k(const float* __restrict__ xin, const float* __restrict__ g,
                            const float* __restrict__ bb, __half* __restrict__ y) {
    __shared__ float rs[8], rq[8];
    int row = blockIdx.x, tid = threadIdx.x;
    const float* xr = xin + (size_t)row * EE;
    float4 v = *(const float4*)(xr + tid * 4);
    float s = v.x + v.y + v.z + v.w;
    float q = v.x * v.x + v.y * v.y + v.z * v.z + v.w * v.w;
#pragma unroll
    for (int o = 16; o; o >>= 1) {
        s += __shfl_xor_sync(0xffffffffu, s, o);
        q += __shfl_xor_sync(0xffffffffu, q, o);
    }
    if ((tid & 31) == 0) { rs[tid >> 5] = s; rq[tid >> 5] = q; }
    __syncthreads();
    if (tid == 0) {
        float S = 0.f, Q = 0.f;
#pragma unroll
        for (int i = 0; i < 8; i++) { S += rs[i]; Q += rq[i]; }
        rs[0] = S; rq[0] = Q;
    }
    __syncthreads();
    float mean = rs[0] * (1.f / EE);
    float var  = rq[0] * (1.f / EE) - mean * mean;
    float rstd = rsqrtf(var + 1e-5f);
    float4 gg = *(const float4*)(g  + tid * 4);
    float4 be = *(const float4*)(bb + tid * 4);
    st_half4(y + (size_t)row * EE + tid * 4,
             (v.x - mean) * rstd * gg.x + be.x,
             (v.y - mean) * rstd * gg.y + be.y,
             (v.z - mean) * rstd * gg.z + be.z,
             (v.w - mean) * rstd * gg.w + be.w);
}

// ---------------- cp.async 3-stage fp16 GEMM with ldmatrix (MT=128) ----------------
static constexpr int H_AST = 72;
static constexpr int H_STG = 2 * 128 * H_AST;
static constexpr int HSMEM = 3 * H_STG * 2;

template<int ACT, bool RES, bool GUARD, bool OUT_HALF, bool SMAX>
__global__ __launch_bounds__(256, 2)
void hgemm_k(const __half* __restrict__ A, const __half* __restrict__ Bw,
             const float* __restrict__ bias, const float* __restrict__ Res,
             void* __restrict__ Cv, int M, int N, int K,
             float* __restrict__ smM, float* __restrict__ smL) {
    extern __shared__ __half smh[];
    const uint32_t sb = smem_u32(smh);
    const int tid  = threadIdx.x;
    const int lane = tid & 31;
    const int wid  = tid >> 5;
    const int wm   = wid >> 2;
    const int wn   = wid & 3;
    const int g    = lane >> 2;
    const int t    = lane & 3;
    const int la16  = lane & 15;
    const int lac8  = (lane >> 4) << 3;
    const int lbrow = ((lane >> 4) << 3) + (lane & 7);
    const int lbcol = ((lane >> 3) & 1) << 3;

    const int row0 = blockIdx.x * 128;
    const int col0 = blockIdx.y * 128;
    const int iters = K >> 6;

    auto issue_stage = [&](int it) {
        const int k0 = it << 6;
        const int s = it % 3;
        const uint32_t stA = sb + (uint32_t)(s * H_STG) * 2;
        const uint32_t stB = stA + (uint32_t)(128 * H_AST) * 2;
#pragma unroll
        for (int u = 0; u < 4; u++) {
            int ca = u * 256 + tid;
            int r = ca >> 3, c16 = ca & 7;
            const __half* gs = A + (size_t)(row0 + r) * K + k0 + c16 * 8;
            uint32_t sd = stA + (uint32_t)(r * H_AST + c16 * 8) * 2;
            asm volatile("cp.async.cg.shared.global [%0], [%1], 16;" :: "r"(sd), "l"(gs));
        }
#pragma unroll
        for (int u = 0; u < 4; u++) {
            int cb = u * 256 + tid;
            int n = cb >> 3, c16 = cb & 7;
            const __half* gs = Bw + (size_t)(col0 + n) * K + k0 + c16 * 8;
            uint32_t sd = stB + (uint32_t)(n * H_AST + c16 * 8) * 2;
            if (GUARD) {
                int sz = (col0 + n < N) ? 16 : 0;
                asm volatile("cp.async.cg.shared.global [%0], [%1], 16, %2;"
                             :: "r"(sd), "l"(gs), "r"(sz));
            } else {
                asm volatile("cp.async.cg.shared.global [%0], [%1], 16;" :: "r"(sd), "l"(gs));
            }
        }
        asm volatile("cp.async.commit_group;" ::: "memory");
    };

    float acc[4][4][4] = {};

    issue_stage(0);
    issue_stage(1);

    for (int it = 0; it < iters; ++it) {
        if (it == iters - 1) {
            asm volatile("cp.async.wait_group 0;" ::: "memory");
        } else {
            asm volatile("cp.async.wait_group 1;" ::: "memory");
        }
        __syncthreads();
        if (it + 2 < iters) issue_stage(it + 2);

        const uint32_t stA = sb + (uint32_t)((it % 3) * H_STG) * 2;
        const uint32_t stB = stA + (uint32_t)(128 * H_AST) * 2;
        const uint32_t aBase = stA + (uint32_t)((wm * 64 + la16) * H_AST + lac8) * 2;
        const uint32_t bBase = stB + (uint32_t)((wn * 32 + lbrow) * H_AST + lbcol) * 2;
#pragma unroll
        for (int ks = 0; ks < 4; ks++) {
            uint32_t afr[4][4];
            uint32_t bfr[4][2];
#pragma unroll
            for (int mt = 0; mt < 4; mt++)
                ldsm_x4(afr[mt], aBase + (uint32_t)(mt * 16 * H_AST + ks * 16) * 2);
#pragma unroll
            for (int ntp = 0; ntp < 2; ntp++) {
                uint32_t bp[4];
                ldsm_x4(bp, bBase + (uint32_t)(ntp * 16 * H_AST + ks * 16) * 2);
                bfr[2 * ntp][0]     = bp[0]; bfr[2 * ntp][1]     = bp[1];
                bfr[2 * ntp + 1][0] = bp[2]; bfr[2 * ntp + 1][1] = bp[3];
            }
#pragma unroll
            for (int mt = 0; mt < 4; mt++)
#pragma unroll
                for (int nt = 0; nt < 4; nt++)
                    mma_f16(acc[mt][nt], afr[mt], bfr[nt]);
        }
    }

    // ---- epilogue ----
#pragma unroll
    for (int mt = 0; mt < 4; mt++) {
        int r0 = row0 + wm * 64 + mt * 16 + g;
#pragma unroll
        for (int nt = 0; nt < 4; nt++) {
            int c = col0 + wn * 32 + nt * 8 + t * 2;
#pragma unroll
            for (int half_i = 0; half_i < 2; half_i++) {
                int r = r0 + half_i * 8;
                float v0 = acc[mt][nt][half_i * 2 + 0];
                float v1 = acc[mt][nt][half_i * 2 + 1];
                if (GUARD) {
                    float* C = (float*)Cv;
                    if (c < N)     C[(size_t)r * N + c]     = v0 + bias[c];
                    if (c + 1 < N) C[(size_t)r * N + c + 1] = v1 + bias[c + 1];
                } else {
                    v0 += bias[c]; v1 += bias[c + 1];
                    if (ACT == 1) {
                        v0 = 0.5f * v0 * (1.f + erff(v0 * 0.70710678118654752f));
                        v1 = 0.5f * v1 * (1.f + erff(v1 * 0.70710678118654752f));
                    }
                    if (RES) {
                        v0 += Res[(size_t)r * N + c];
                        v1 += Res[(size_t)r * N + c + 1];
                    }
                    if (OUT_HALF) {
                        __half2 hv = __floats2half2_rn(v0, v1);
                        *(__half2*)((__half*)Cv + (size_t)r * N + c) = hv;
                    } else {
                        *(float2*)((float*)Cv + (size_t)r * N + c) = make_float2(v0, v1);
                    }
                }
            }
        }
    }

    // ---- fused per-row softmax partials (LM head) ----
    if (SMAX) {
        float* red = (float*)smh;
        __syncthreads();
        float rmax[8];
#pragma unroll
        for (int idx = 0; idx < 8; idx++) {
            int mt = idx >> 1, hi = idx & 1;
            float m = -1e30f;
#pragma unroll
            for (int nt = 0; nt < 4; nt++) {
                int c = col0 + wn * 32 + nt * 8 + t * 2;
                float v0 = (c < N)     ? acc[mt][nt][hi * 2 + 0] + bias[c]     : -1e30f;
                float v1 = (c + 1 < N) ? acc[mt][nt][hi * 2 + 1] + bias[c + 1] : -1e30f;
                m = fmaxf(m, fmaxf(v0, v1));
            }
            m = fmaxf(m, __shfl_xor_sync(0xffffffffu, m, 1));
            m = fmaxf(m, __shfl_xor_sync(0xffffffffu, m, 2));
            rmax[idx] = m;
        }
        if (t == 0) {
#pragma unroll
            for (int idx = 0; idx < 8; idx++) {
                int rc = wm * 64 + (idx >> 1) * 16 + (idx & 1) * 8 + g;
                red[rc * 4 + wn] = rmax[idx];
            }
        }
        __syncthreads();
#pragma unroll
        for (int idx = 0; idx < 8; idx++) {
            int rc = wm * 64 + (idx >> 1) * 16 + (idx & 1) * 8 + g;
            float m = fmaxf(fmaxf(red[rc * 4 + 0], red[rc * 4 + 1]),
                            fmaxf(red[rc * 4 + 2], red[rc * 4 + 3]));
            rmax[idx] = m;
        }
        __syncthreads();
        float rsum[8];
#pragma unroll
        for (int idx = 0; idx < 8; idx++) {
            int mt = idx >> 1, hi = idx & 1;
            const float mb = rmax[idx] * L2E;
            float s = 0.f;
#pragma unroll
            for (int nt = 0; nt < 4; nt++) {
                int c = col0 + wn * 32 + nt * 8 + t * 2;
                float v0 = (c < N)     ? acc[mt][nt][hi * 2 + 0] + bias[c]     : -1e30f;
                float v1 = (c + 1 < N) ? acc[mt][nt][hi * 2 + 1] + bias[c + 1] : -1e30f;
                uint32_t e = ex2_h2(fmaf(v0, L2E, -mb), fmaf(v1, L2E, -mb));
                float2 f = __half22float2(*(__half2*)&e);
                s += f.x + f.y;
            }
            s += __shfl_xor_sync(0xffffffffu, s, 1);
            s += __shfl_xor_sync(0xffffffffu, s, 2);
            rsum[idx] = s;
        }
        if (t == 0) {
#pragma unroll
            for (int idx = 0; idx < 8; idx++) {
                int rc = wm * 64 + (idx >> 1) * 16 + (idx & 1) * 8 + g;
                red[rc * 4 + wn] = rsum[idx];
            }
        }
        __syncthreads();
        if (t == 0 && wn == 0) {
#pragma unroll
            for (int idx = 0; idx < 8; idx++) {
                int rc = wm * 64 + (idx >> 1) * 16 + (idx & 1) * 8 + g;
                float L = red[rc * 4 + 0] + red[rc * 4 + 1] + red[rc * 4 + 2] + red[rc * 4 + 3];
                smM[(size_t)(row0 + rc) * NTP + blockIdx.y] = rmax[idx];
                smL[(size_t)(row0 + rc) * NTP + blockIdx.y] = L;
            }
        }
    }
}

// ---------------- Tensor-core split-KV flash attention ----------------
static constexpr int FH_PAD = 72;

__global__ __launch_bounds__(128)
void flash_attn_k(const __half* __restrict__ qkv, float* __restrict__ pO,
                  float* __restrict__ pm, float* __restrict__ pl,
                  __half* __restrict__ attnOut) {
    __shared__ __half Qh[64 * FH_PAD];
    __shared__ __half Kh[64 * FH_PAD];
    __shared__ __half Vt[64 * FH_PAD];

    const int tid  = threadIdx.x;
    const int lane = tid & 31;
    const int wid  = tid >> 5;
    const int g    = lane >> 2;
    const int t    = lane & 3;
    const int wr   = wid * 16;

    const int u  = blockIdx.x;
    const int bh = blockIdx.y;
    const int qi = c_qi[u];
    const int sp = c_sp[u];
    const int q0 = qi * 64;
    const int b = bh / HH, h = bh % HH;

    const __half* base = qkv + (size_t)b * TT * 3 * EE + h * DD;

    {
        int r = tid >> 1, cpart = tid & 1;
        const __half* qp = base + (size_t)(q0 + r) * 3 * EE + cpart * 32;
#pragma unroll
        for (int i = 0; i < 4; i++)
            *(uint4*)(Qh + r * FH_PAD + cpart * 32 + i * 8) = *(const uint4*)(qp + i * 8);
    }

    float m_old[2] = {-1e30f, -1e30f};
    float lsum[2]  = {0.f, 0.f};
    float oacc[8][4] = {};
    const int c0 = sp * 4;
    const int c1 = min(c0 + 4, qi + 1);

    for (int ch = c0; ch < c1; ch++) {
        const int kt = ch * 64;
        __syncthreads();
        {
            int r = tid >> 1, cpart = tid & 1;
            const __half* kp = base + (size_t)(kt + r) * 3 * EE + EE + cpart * 32;
            const __half* vp = base + (size_t)(kt + r) * 3 * EE + 2 * EE + cpart * 32;
#pragma unroll
            for (int i = 0; i < 4; i++) {
                *(uint4*)(Kh + r * FH_PAD + cpart * 32 + i * 8) = *(const uint4*)(kp + i * 8);
                uint4 vv = *(const uint4*)(vp + i * 8);
                const __half* hv = (const __half*)&vv;
                int d = cpart * 32 + i * 8;
#pragma unroll
                for (int j = 0; j < 8; j++)
                    Vt[(d + j) * FH_PAD + r] = hv[j];
            }
        }
        __syncthreads();

        float sacc[8][4] = {};
#pragma unroll
        for (int j = 0; j < 4; j++) {
            const int kk = j * 16 + t * 2;
            uint32_t a[4];
            a[0] = *(const uint32_t*)&Qh[(wr + g)     * FH_PAD + kk];
            a[1] = *(const uint32_t*)&Qh[(wr + g + 8) * FH_PAD + kk];
            a[2] = *(const uint32_t*)&Qh[(wr + g)     * FH_PAD + kk + 8];
            a[3] = *(const uint32_t*)&Qh[(wr + g + 8) * FH_PAD + kk + 8];
#pragma unroll
            for (int nt = 0; nt < 8; nt++) {
                uint32_t bfr[2];
                bfr[0] = *(const uint32_t*)&Kh[(nt * 8 + g) * FH_PAD + kk];
                bfr[1] = *(const uint32_t*)&Kh[(nt * 8 + g) * FH_PAD + kk + 8];
                mma_f16(sacc[nt], a, bfr);
            }
        }

        const bool diag = (ch == qi);
        uint32_t ap[4][4];
        float al[2];
#pragma unroll
        for (int rh = 0; rh < 2; rh++) {
            int row = q0 + wr + g + rh * 8;
            float pv[16];
            float lm = -1e30f;
#pragma unroll
            for (int nt = 0; nt < 8; nt++) {
#pragma unroll
                for (int jj = 0; jj < 2; jj++) {
                    float s = sacc[nt][rh * 2 + jj] * 0.125f;
                    if (diag && (kt + nt * 8 + t * 2 + jj > row)) s = -1e30f;
                    pv[nt * 2 + jj] = s;
                    lm = fmaxf(lm, s);
                }
            }
            lm = fmaxf(lm, __shfl_xor_sync(0xffffffffu, lm, 1));
            lm = fmaxf(lm, __shfl_xor_sync(0xffffffffu, lm, 2));
            float mnew = fmaxf(m_old[rh], lm);
            al[rh] = __expf(m_old[rh] - mnew);
            m_old[rh] = mnew;
            const float mb = mnew * L2E;
            float ls = 0.f;
#pragma unroll
            for (int j = 0; j < 4; j++) {
                uint32_t p01 = ex2_h2(fmaf(pv[4 * j + 0], L2E, -mb),
                                      fmaf(pv[4 * j + 1], L2E, -mb));
                uint32_t p23 = ex2_h2(fmaf(pv[4 * j + 2], L2E, -mb),
                                      fmaf(pv[4 * j + 3], L2E, -mb));
                ap[j][rh]     = p01;
                ap[j][rh + 2] = p23;
                float2 f0 = __half22float2(*(__half2*)&p01);
                float2 f1 = __half22float2(*(__half2*)&p23);
                ls += (f0.x + f0.y) + (f1.x + f1.y);
            }
            ls += __shfl_xor_sync(0xffffffffu, ls, 1);
            ls += __shfl_xor_sync(0xffffffffu, ls, 2);
            lsum[rh] = lsum[rh] * al[rh] + ls;
        }

#pragma unroll
        for (int dt = 0; dt < 8; dt++) {
            oacc[dt][0] *= al[0]; oacc[dt][1] *= al[0];
            oacc[dt][2] *= al[1]; oacc[dt][3] *= al[1];
        }
#pragma unroll
        for (int j = 0; j < 4; j++) {
            const int kk = j * 16 + t * 2;
#pragma unroll
            for (int dt = 0; dt < 8; dt++) {
                uint32_t bfr[2];
                bfr[0] = *(const uint32_t*)&Vt[(dt * 8 + g) * FH_PAD + kk];
                bfr[1] = *(const uint32_t*)&Vt[(dt * 8 + g) * FH_PAD + kk + 8];
                mma_f16(oacc[dt], ap[j], bfr);
            }
        }
    }

    int r0 = wr + g;
    if (c_ns[qi] == 1) {
        float inv0 = 1.f / lsum[0], inv1 = 1.f / lsum[1];
        size_t tok0 = (size_t)(b * TT + q0 + r0);
#pragma unroll
        for (int dt = 0; dt < 8; dt++) {
            __half2 h0 = __floats2half2_rn(oacc[dt][0] * inv0, oacc[dt][1] * inv0);
            __half2 h1 = __floats2half2_rn(oacc[dt][2] * inv1, oacc[dt][3] * inv1);
            *(__half2*)(attnOut + tok0 * EE + h * DD + dt * 8 + t * 2) = h0;
            *(__half2*)(attnOut + (tok0 + 8) * EE + h * DD + dt * 8 + t * 2) = h1;
        }
    } else {
        float* po = pO + ((size_t)(bh * NU + u) * 64) * 64;
#pragma unroll
        for (int dt = 0; dt < 8; dt++) {
            *(float2*)(po + (size_t)r0 * 64 + dt * 8 + t * 2)       = make_float2(oacc[dt][0], oacc[dt][1]);
            *(float2*)(po + (size_t)(r0 + 8) * 64 + dt * 8 + t * 2) = make_float2(oacc[dt][2], oacc[dt][3]);
        }
        if (t == 0) {
            pm[(size_t)(bh * NU + u) * 64 + r0]     = m_old[0];
            pm[(size_t)(bh * NU + u) * 64 + r0 + 8] = m_old[1];
            pl[(size_t)(bh * NU + u) * 64 + r0]     = lsum[0];
            pl[(size_t)(bh * NU + u) * 64 + r0 + 8] = lsum[1];
        }
    }
}

// Combine split partials (qi 4..15 only); half output
__global__ __launch_bounds__(256)
void fa_combine_k(const float* __restrict__ pO, const float* __restrict__ pm,
                  const float* __restrict__ pl, __half* __restrict__ out) {
    const int qi = blockIdx.x + 4;
    const int bh = blockIdx.y;
    const int b = bh / HH, h = bh % HH;
    const int ns = c_ns[qi];
    const int u0 = c_u0[qi];
    const int tid = threadIdx.x;
    const int r4 = tid >> 6;
    const int d  = tid & 63;
    for (int p = 0; p < 16; p++) {
        int row = p * 4 + r4;
        float M = -1e30f;
        for (int s = 0; s < ns; s++)
            M = fmaxf(M, pm[(size_t)(bh * NU + u0 + s) * 64 + row]);
        float L = 0.f, O = 0.f;
        for (int s = 0; s < ns; s++) {
            size_t ub = (size_t)(bh * NU + u0 + s);
            float w = __expf(pm[ub * 64 + row] - M);
            L += w * pl[ub * 64 + row];
            O += w * pO[(ub * 64 + row) * 64 + d];
        }
        out[((size_t)(b * TT + qi * 64 + row)) * EE + h * DD + d] = __float2half_rn(O / L);
    }
}

// ---------------- NLL from fused partials ----------------
__global__ __launch_bounds__(128)
void nll2_k(const float* __restrict__ logits, const float* __restrict__ smM,
            const float* __restrict__ smL, const int* __restrict__ tgt,
            float* __restrict__ nll) {
    const int row = blockIdx.x;
    const int tid = threadIdx.x;
    __shared__ float sh[128];
    float M = -1e30f;
    for (int i = tid; i < NTILE; i += 128)
        M = fmaxf(M, smM[(size_t)row * NTP + i]);
    sh[tid] = M; __syncthreads();
    for (int o = 64; o; o >>= 1) { if (tid < o) sh[tid] = fmaxf(sh[tid], sh[tid + o]); __syncthreads(); }
    M = sh[0]; __syncthreads();
    float L = 0.f;
    for (int i = tid; i < NTILE; i += 128)
        L += smL[(size_t)row * NTP + i] * __expf(smM[(size_t)row * NTP + i] - M);
    sh[tid] = L; __syncthreads();
    for (int o = 64; o; o >>= 1) { if (tid < o) sh[tid] += sh[tid + o]; __syncthreads(); }
    if (tid == 0)
        nll[row] = logf(sh[0]) + M - logits[(size_t)row * VV + tgt[row]];
}

__global__ void loss_reduce_k(const float* __restrict__ nll, float* __restrict__ dst, int count) {
    __shared__ float sh[256];
    float s = 0.f;
    for (int i = threadIdx.x; i < MM; i += 256) s += nll[i];
    sh[threadIdx.x] = s; __syncthreads();
    for (int o = 128; o; o >>= 1) { if (threadIdx.x < o) sh[threadIdx.x] += sh[threadIdx.x + o]; __syncthreads(); }
    if (threadIdx.x == 0) {
        float loss = sh[0] * (1.f / (float)MM);
        for (int i = 0; i < count; i++) dst[i] = loss;
    }
}

// ---------------- Launch ----------------
extern "C" void kernel_launch(void* const* d_in, const int* in_sizes, int n_in,
                              void* d_out, int out_size) {
    const int*   idx     = (const int*)  d_in[0];
    const int*   targets = (const int*)  d_in[1];
    const float* wte     = (const float*)d_in[2];
    const float* wpe     = (const float*)d_in[3];
    const float* ln1_g   = (const float*)d_in[4];
    const float* ln1_b   = (const float*)d_in[5];
    const float* qkv_w   = (const float*)d_in[6];
    const float* qkv_b   = (const float*)d_in[7];
    const float* o_w     = (const float*)d_in[8];
    const float* o_b     = (const float*)d_in[9];
    const float* ln2_g   = (const float*)d_in[10];
    const float* ln2_b   = (const float*)d_in[11];
    const float* up_w    = (const float*)d_in[12];
    const float* up_b    = (const float*)d_in[13];
    const float* down_w  = (const float*)d_in[14];
    const float* down_b  = (const float*)d_in[15];
    const float* lnf_g   = (const float*)d_in[16];
    const float* lnf_b   = (const float*)d_in[17];
    const float* lm_b    = (const float*)d_in[18];

    float *h, *nll, *logits_scratch, *pO, *pm, *pl, *smM, *smL;
    __half *xh, *qkvh, *attnh, *mlph, *qkvT, *oT, *upT, *downT, *wteH;
    cudaGetSymbolAddress((void**)&h,    g_h);
    cudaGetSymbolAddress((void**)&xh,   g_xh);
    cudaGetSymbolAddress((void**)&qkvh, g_qkvh);
    cudaGetSymbolAddress((void**)&attnh, g_attnh);
    cudaGetSymbolAddress((void**)&mlph, g_mlph);
    cudaGetSymbolAddress((void**)&nll,  g_nll);
    cudaGetSymbolAddress((void**)&logits_scratch, g_logits);
    cudaGetSymbolAddress((void**)&pO,   g_pO);
    cudaGetSymbolAddress((void**)&pm,   g_pm);
    cudaGetSymbolAddress((void**)&pl,   g_pl);
    cudaGetSymbolAddress((void**)&smM,  g_sm_m);
    cudaGetSymbolAddress((void**)&smL,  g_sm_l);
    cudaGetSymbolAddress((void**)&qkvT,  g_qkvT);
    cudaGetSymbolAddress((void**)&oT,    g_oT);
    cudaGetSymbolAddress((void**)&upT,   g_upT);
    cudaGetSymbolAddress((void**)&downT, g_downT);
    cudaGetSymbolAddress((void**)&wteH,  g_wteH);

    static bool attr_set = false;
    if (!attr_set) {
        cudaFuncSetAttribute(hgemm_k<0, false, false, true,  false>, cudaFuncAttributeMaxDynamicSharedMemorySize, HSMEM);
        cudaFuncSetAttribute(hgemm_k<0, true,  false, false, false>, cudaFuncAttributeMaxDynamicSharedMemorySize, HSMEM);
        cudaFuncSetAttribute(hgemm_k<1, false, false, true,  false>, cudaFuncAttributeMaxDynamicSharedMemorySize, HSMEM);
        cudaFuncSetAttribute(hgemm_k<0, false, true,  false, true >, cudaFuncAttributeMaxDynamicSharedMemorySize, HSMEM);
        attr_set = true;
    }

    float* logits = ((long long)out_size >= NBTV) ? (float*)d_out : logits_scratch;

    transh_k<<<dim3(3 * EE / 64, EE / 64, LL), 256>>>(qkv_w, qkvT, EE, 3 * EE);
    transh_k<<<dim3(EE / 64, EE / 64, LL), 256>>>(o_w, oT, EE, EE);
    transh_k<<<dim3(4 * EE / 64, EE / 64, LL), 256>>>(up_w, upT, EE, 4 * EE);
    transh_k<<<dim3(EE / 64, 4 * EE / 64, LL), 256>>>(down_w, downT, 4 * EE, EE);
    {
        int n = VV * EE / 4;
        halfcpy_k<<<(n + 255) / 256, 256>>>(wte, wteH, n);
    }

    embed_k<<<MM, 256>>>(idx, wte, wpe, h);

    for (int l = 0; l < LL; l++) {
        layernorm_k<<<MM, 256>>>(h, ln1_g + (size_t)l * EE, ln1_b + (size_t)l * EE, xh);
        hgemm_k<0, false, false, true, false><<<dim3(MM / 128, 3 * EE / 128), 256, HSMEM>>>(
            xh, qkvT + (size_t)l * 3 * EE * EE, qkv_b + (size_t)l * 3 * EE, nullptr,
            qkvh, MM, 3 * EE, EE, nullptr, nullptr);
        flash_attn_k<<<dim3(NU, BB * HH), 128>>>(qkvh, pO, pm, pl, attnh);
        fa_combine_k<<<dim3(12, BB * HH), 256>>>(pO, pm, pl, attnh);
        hgemm_k<0, true, false, false, false><<<dim3(MM / 128, EE / 128), 256, HSMEM>>>(
            attnh, oT + (size_t)l * EE * EE, o_b + (size_t)l * EE, h,
            h, MM, EE, EE, nullptr, nullptr);
        layernorm_k<<<MM, 256>>>(h, ln2_g + (size_t)l * EE, ln2_b + (size_t)l * EE, xh);
        hgemm_k<1, false, false, true, false><<<dim3(MM / 128, 4 * EE / 128), 256, HSMEM>>>(
            xh, upT + (size_t)l * 4 * EE * EE, up_b + (size_t)l * 4 * EE, nullptr,
            mlph, MM, 4 * EE, EE, nullptr, nullptr);
        hgemm_k<0, true, false, false, false><<<dim3(MM / 128, EE / 128), 256, HSMEM>>>(
            mlph, downT + (size_t)l * 4 * EE * EE, down_b + (size_t)l * EE, h,
            h, MM, EE, 4 * EE, nullptr, nullptr);
    }

    layernorm_k<<<MM, 256>>>(h, lnf_g, lnf_b, xh);
    hgemm_k<0, false, true, false, true><<<dim3(MM / 128, (VV + 127) / 128), 256, HSMEM>>>(
        xh, wteH, lm_b, nullptr, logits, MM, VV, EE, smM, smL);

    nll2_k<<<MM, 128>>>(logits, smM, smL, targets, nll);

    long long extra = (long long)out_size - NBTV;
    if (extra > 0) {
        loss_reduce_k<<<1, 256>>>(nll, (float*)d_out + NBTV, (int)extra);
    } else if ((long long)out_size < NBTV) {
        loss_reduce_k<<<1, 256>>>(nll, (float*)d_out, out_size);
    }
}

// round 16
// speedup vs baseline: 1.0989x; 1.0158x over previous
#include <cuda_runtime.h>
#include <cuda_fp16.h>
#include <math.h>
#include <stdint.h>

// ---------------- Problem constants ----------------
static constexpr int BB = 2;
static constexpr int TT = 1024;
static constexpr int EE = 1024;
static constexpr int HH = 16;
static constexpr int DD = 64;
static constexpr int LL = 12;
static constexpr int VV = 50257;
static constexpr int MM = BB * TT;
static constexpr long long NBTV = (long long)MM * VV;
static constexpr int NU = 40;
static constexpr float L2E = 1.44269504088896340736f;
static constexpr int NTILE = (VV + 127) / 128;
static constexpr int NTP = 400;

// ---------------- Scratch ----------------
__device__ float g_h   [(size_t)MM * EE];
__device__ __half g_xh  [(size_t)MM * EE];
__device__ __half g_qkvh[(size_t)MM * 3 * EE];
__device__ __half g_attnh[(size_t)MM * EE];
__device__ __half g_mlph [(size_t)MM * 4 * EE];
__device__ float g_nll [MM];
__device__ float g_logits[(size_t)MM * VV];
__device__ float g_part[(size_t)2 * MM * EE];   // split-K partials
__device__ float g_pO[(size_t)BB * HH * NU * 64 * 64];
__device__ float g_pm[(size_t)BB * HH * NU * 64];
__device__ float g_pl[(size_t)BB * HH * NU * 64];
__device__ float g_sm_m[(size_t)MM * NTP];
__device__ float g_sm_l[(size_t)MM * NTP];
__device__ __half g_qkvT [(size_t)LL * 3 * EE * EE];
__device__ __half g_oT   [(size_t)LL * EE * EE];
__device__ __half g_upT  [(size_t)LL * 4 * EE * EE];
__device__ __half g_downT[(size_t)LL * 4 * EE * EE];
__device__ __half g_wteH [(size_t)VV * EE];

__constant__ int c_qi[NU] = {15,15,15,15, 14,14,14,14, 13,13,13,13, 12,12,12,12,
                             11,11,11, 10,10,10, 9,9,9, 8,8,8, 7,7, 6,6, 5,5, 4,4,
                             3, 2, 1, 0};
__constant__ int c_sp[NU] = {0,1,2,3, 0,1,2,3, 0,1,2,3, 0,1,2,3,
                             0,1,2, 0,1,2, 0,1,2, 0,1,2, 0,1, 0,1, 0,1, 0,1,
                             0, 0, 0, 0};
__constant__ int c_u0[16] = {39,38,37,36, 34,32,30,28, 25,22,19,16, 12,8,4,0};
__constant__ int c_ns[16] = {1,1,1,1, 2,2,2,2, 3,3,3,3, 4,4,4,4};

// ---------------- Helpers ----------------
__device__ __forceinline__ uint32_t smem_u32(const void* p) {
    uint32_t r;
    asm("{ .reg .u64 t; cvta.to.shared.u64 t, %1; cvt.u32.u64 %0, t; }" : "=r"(r) : "l"(p));
    return r;
}

__device__ __forceinline__ void mma_f16(float c[4], const uint32_t a[4], const uint32_t b[2]) {
    asm volatile(
        "mma.sync.aligned.m16n8k16.row.col.f32.f16.f16.f32 "
        "{%0,%1,%2,%3}, {%4,%5,%6,%7}, {%8,%9}, {%0,%1,%2,%3};"
        : "+f"(c[0]), "+f"(c[1]), "+f"(c[2]), "+f"(c[3])
        : "r"(a[0]), "r"(a[1]), "r"(a[2]), "r"(a[3]), "r"(b[0]), "r"(b[1]));
}

__device__ __forceinline__ void ldsm_x4(uint32_t r[4], uint32_t addr) {
    asm volatile("ldmatrix.sync.aligned.m8n8.x4.shared.b16 {%0,%1,%2,%3}, [%4];"
        : "=r"(r[0]), "=r"(r[1]), "=r"(r[2]), "=r"(r[3]) : "r"(addr));
}

__device__ __forceinline__ void st_half4(__half* p, float a, float b, float c, float d) {
    __half2 lo = __floats2half2_rn(a, b);
    __half2 hi = __floats2half2_rn(c, d);
    uint2 v = make_uint2(*(uint32_t*)&lo, *(uint32_t*)&hi);
    *(uint2*)p = v;
}

__device__ __forceinline__ uint32_t ex2_h2(float a, float b) {
    __half2 h = __floats2half2_rn(a, b);
    uint32_t u = *(uint32_t*)&h, o;
    asm("ex2.approx.f16x2 %0, %1;" : "=r"(o) : "r"(u));
    return o;
}

// ---------------- Weight prep: W[K,N] fp32 -> WT[N,K] half (vectorized 64x64) ----------------
__global__ void transh_k(const float* __restrict__ W, __half* __restrict__ WT,
                         int K, int N) {
    __shared__ float tl[64][65];
    size_t off = (size_t)blockIdx.z * K * N;
    int n0 = blockIdx.x * 64, k0 = blockIdx.y * 64;
    int tid = threadIdx.x;
    int rr = tid >> 4;
    int rc = (tid & 15) << 2;
#pragma unroll
    for (int i = 0; i < 4; i++) {
        float4 v = *(const float4*)(W + off + (size_t)(k0 + rr + 16 * i) * N + n0 + rc);
        tl[rr + 16 * i][rc + 0] = v.x;
        tl[rr + 16 * i][rc + 1] = v.y;
        tl[rr + 16 * i][rc + 2] = v.z;
        tl[rr + 16 * i][rc + 3] = v.w;
    }
    __syncthreads();
    int wn = tid >> 3;
    int wk = (tid & 7) << 3;
#pragma unroll
    for (int i = 0; i < 2; i++) {
        int n = wn + 32 * i;
        __half hv[8];
#pragma unroll
        for (int j = 0; j < 8; j++) hv[j] = __float2half_rn(tl[wk + j][n]);
        *(uint4*)(WT + off + (size_t)(n0 + n) * K + k0 + wk) = *(uint4*)hv;
    }
}

__global__ void halfcpy_k(const float* __restrict__ src, __half* __restrict__ dst, int n4) {
    int i = blockIdx.x * 256 + threadIdx.x;
    if (i < n4) {
        float4 v = *(const float4*)(src + (size_t)i * 4);
        st_half4(dst + (size_t)i * 4, v.x, v.y, v.z, v.w);
    }
}

// ---------------- Embedding ----------------
__global__ void embed_k(const int* __restrict__ idx, const float* __restrict__ wte,
                        const float* __restrict__ wpe, float* __restrict__ h) {
    int bt = blockIdx.x;
    int t  = bt % TT;
    int tok = idx[bt];
    int i = threadIdx.x * 4;
    float4 a = *(const float4*)(wte + (size_t)tok * EE + i);
    float4 p = *(const float4*)(wpe + (size_t)t   * EE + i);
    a.x += p.x; a.y += p.y; a.z += p.z; a.w += p.w;
    *(float4*)(h + (size_t)bt * EE + i) = a;
}

// ---------------- Split-K combine: h += p0 + p1 + bias ----------------
__global__ void resadd_k(float* __restrict__ h, const float* __restrict__ p,
                         const float* __restrict__ bias) {
    size_t i = (size_t)blockIdx.x * 256 + threadIdx.x;
    int c4 = (int)(i & (EE / 4 - 1)) * 4;
    float4 hv = *(float4*)(h + i * 4);
    float4 a  = *(const float4*)(p + i * 4);
    float4 b2 = *(const float4*)(p + (size_t)MM * EE + i * 4);
    float4 bv = *(const float4*)(bias + c4);
    hv.x += a.x + b2.x + bv.x;
    hv.y += a.y + b2.y + bv.y;
    hv.z += a.z + b2.z + bv.z;
    hv.w += a.w + b2.w + bv.w;
    *(float4*)(h + i * 4) = hv;
}

// ---------------- LayerNorm: fp32 in, half out ----------------
__global__ void layernorm_k(const float* __restrict__ xin, const float* __restrict__ g,
                            const float* __restrict__ bb, __half* __restrict__ y) {
    __shared__ float rs[8], rq[8];
    int row = blockIdx.x, tid = threadIdx.x;
    const float* xr = xin + (size_t)row * EE;
    float4 v = *(const float4*)(xr + tid * 4);
    float s = v.x + v.y + v.z + v.w;
    float q = v.x * v.x + v.y * v.y + v.z * v.z + v.w * v.w;
#pragma unroll
    for (int o = 16; o; o >>= 1) {
        s += __shfl_xor_sync(0xffffffffu, s, o);
        q += __shfl_xor_sync(0xffffffffu, q, o);
    }
    if ((tid & 31) == 0) { rs[tid >> 5] = s; rq[tid >> 5] = q; }
    __syncthreads();
    if (tid == 0) {
        float S = 0.f, Q = 0.f;
#pragma unroll
        for (int i = 0; i < 8; i++) { S += rs[i]; Q += rq[i]; }
        rs[0] = S; rq[0] = Q;
    }
    __syncthreads();
    float mean = rs[0] * (1.f / EE);
    float var  = rq[0] * (1.f / EE) - mean * mean;
    float rstd = rsqrtf(var + 1e-5f);
    float4 gg = *(const float4*)(g  + tid * 4);
    float4 be = *(const float4*)(bb + tid * 4);
    st_half4(y + (size_t)row * EE + tid * 4,
             (v.x - mean) * rstd * gg.x + be.x,
             (v.y - mean) * rstd * gg.y + be.y,
             (v.z - mean) * rstd * gg.z + be.z,
             (v.w - mean) * rstd * gg.w + be.w);
}

// ---------------- cp.async 3-stage fp16 GEMM with ldmatrix (MT=128) ----------------
static constexpr int H_AST = 72;
static constexpr int H_STG = 2 * 128 * H_AST;
static constexpr int HSMEM = 3 * H_STG * 2;

template<int ACT, bool RES, bool GUARD, bool OUT_HALF, bool SMAX, bool SPLITK>
__global__ __launch_bounds__(256, 2)
void hgemm_k(const __half* __restrict__ A, const __half* __restrict__ Bw,
             const float* __restrict__ bias, const float* __restrict__ Res,
             void* __restrict__ Cv, int M, int N, int K,
             float* __restrict__ smM, float* __restrict__ smL) {
    extern __shared__ __half smh[];
    const uint32_t sb = smem_u32(smh);
    const int tid  = threadIdx.x;
    const int lane = tid & 31;
    const int wid  = tid >> 5;
    const int wm   = wid >> 2;
    const int wn   = wid & 3;
    const int g    = lane >> 2;
    const int t    = lane & 3;
    const int la16  = lane & 15;
    const int lac8  = (lane >> 4) << 3;
    const int lbrow = ((lane >> 4) << 3) + (lane & 7);
    const int lbcol = ((lane >> 3) & 1) << 3;

    const int row0 = blockIdx.x * 128;
    const int col0 = blockIdx.y * 128;
    const int kbase = SPLITK ? blockIdx.z * (K >> 1) : 0;
    const int iters = (SPLITK ? (K >> 1) : K) >> 6;

    auto issue_stage = [&](int it) {
        const int k0 = kbase + (it << 6);
        const int s = it % 3;
        const uint32_t stA = sb + (uint32_t)(s * H_STG) * 2;
        const uint32_t stB = stA + (uint32_t)(128 * H_AST) * 2;
#pragma unroll
        for (int u = 0; u < 4; u++) {
            int ca = u * 256 + tid;
            int r = ca >> 3, c16 = ca & 7;
            const __half* gs = A + (size_t)(row0 + r) * K + k0 + c16 * 8;
            uint32_t sd = stA + (uint32_t)(r * H_AST + c16 * 8) * 2;
            asm volatile("cp.async.cg.shared.global [%0], [%1], 16;" :: "r"(sd), "l"(gs));
        }
#pragma unroll
        for (int u = 0; u < 4; u++) {
            int cb = u * 256 + tid;
            int n = cb >> 3, c16 = cb & 7;
            const __half* gs = Bw + (size_t)(col0 + n) * K + k0 + c16 * 8;
            uint32_t sd = stB + (uint32_t)(n * H_AST + c16 * 8) * 2;
            if (GUARD) {
                int sz = (col0 + n < N) ? 16 : 0;
                asm volatile("cp.async.cg.shared.global [%0], [%1], 16, %2;"
                             :: "r"(sd), "l"(gs), "r"(sz));
            } else {
                asm volatile("cp.async.cg.shared.global [%0], [%1], 16;" :: "r"(sd), "l"(gs));
            }
        }
        asm volatile("cp.async.commit_group;" ::: "memory");
    };

    float acc[4][4][4] = {};

    issue_stage(0);
    issue_stage(1);

    for (int it = 0; it < iters; ++it) {
        if (it == iters - 1) {
            asm volatile("cp.async.wait_group 0;" ::: "memory");
        } else {
            asm volatile("cp.async.wait_group 1;" ::: "memory");
        }
        __syncthreads();
        if (it + 2 < iters) issue_stage(it + 2);

        const uint32_t stA = sb + (uint32_t)((it % 3) * H_STG) * 2;
        const uint32_t stB = stA + (uint32_t)(128 * H_AST) * 2;
        const uint32_t aBase = stA + (uint32_t)((wm * 64 + la16) * H_AST + lac8) * 2;
        const uint32_t bBase = stB + (uint32_t)((wn * 32 + lbrow) * H_AST + lbcol) * 2;
#pragma unroll
        for (int ks = 0; ks < 4; ks++) {
            uint32_t afr[4][4];
            uint32_t bfr[4][2];
#pragma unroll
            for (int mt = 0; mt < 4; mt++)
                ldsm_x4(afr[mt], aBase + (uint32_t)(mt * 16 * H_AST + ks * 16) * 2);
#pragma unroll
            for (int ntp = 0; ntp < 2; ntp++) {
                uint32_t bp[4];
                ldsm_x4(bp, bBase + (uint32_t)(ntp * 16 * H_AST + ks * 16) * 2);
                bfr[2 * ntp][0]     = bp[0]; bfr[2 * ntp][1]     = bp[1];
                bfr[2 * ntp + 1][0] = bp[2]; bfr[2 * ntp + 1][1] = bp[3];
            }
#pragma unroll
            for (int mt = 0; mt < 4; mt++)
#pragma unroll
                for (int nt = 0; nt < 4; nt++)
                    mma_f16(acc[mt][nt], afr[mt], bfr[nt]);
        }
    }

    // ---- epilogue ----
#pragma unroll
    for (int mt = 0; mt < 4; mt++) {
        int r0 = row0 + wm * 64 + mt * 16 + g;
#pragma unroll
        for (int nt = 0; nt < 4; nt++) {
            int c = col0 + wn * 32 + nt * 8 + t * 2;
#pragma unroll
            for (int half_i = 0; half_i < 2; half_i++) {
                int r = r0 + half_i * 8;
                float v0 = acc[mt][nt][half_i * 2 + 0];
                float v1 = acc[mt][nt][half_i * 2 + 1];
                if (SPLITK) {
                    float* C = (float*)Cv + (size_t)blockIdx.z * M * N;
                    *(float2*)(C + (size_t)r * N + c) = make_float2(v0, v1);
                } else if (GUARD) {
                    float* C = (float*)Cv;
                    if (c < N)     C[(size_t)r * N + c]     = v0 + bias[c];
                    if (c + 1 < N) C[(size_t)r * N + c + 1] = v1 + bias[c + 1];
                } else {
                    v0 += bias[c]; v1 += bias[c + 1];
                    if (ACT == 1) {
                        v0 = 0.5f * v0 * (1.f + erff(v0 * 0.70710678118654752f));
                        v1 = 0.5f * v1 * (1.f + erff(v1 * 0.70710678118654752f));
                    }
                    if (RES) {
                        v0 += Res[(size_t)r * N + c];
                        v1 += Res[(size_t)r * N + c + 1];
                    }
                    if (OUT_HALF) {
                        __half2 hv = __floats2half2_rn(v0, v1);
                        *(__half2*)((__half*)Cv + (size_t)r * N + c) = hv;
                    } else {
                        *(float2*)((float*)Cv + (size_t)r * N + c) = make_float2(v0, v1);
                    }
                }
            }
        }
    }

    // ---- fused per-row softmax partials (LM head) ----
    if (SMAX) {
        float* red = (float*)smh;
        __syncthreads();
        float rmax[8];
#pragma unroll
        for (int idx = 0; idx < 8; idx++) {
            int mt = idx >> 1, hi = idx & 1;
            float m = -1e30f;
#pragma unroll
            for (int nt = 0; nt < 4; nt++) {
                int c = col0 + wn * 32 + nt * 8 + t * 2;
                float v0 = (c < N)     ? acc[mt][nt][hi * 2 + 0] + bias[c]     : -1e30f;
                float v1 = (c + 1 < N) ? acc[mt][nt][hi * 2 + 1] + bias[c + 1] : -1e30f;
                m = fmaxf(m, fmaxf(v0, v1));
            }
            m = fmaxf(m, __shfl_xor_sync(0xffffffffu, m, 1));
            m = fmaxf(m, __shfl_xor_sync(0xffffffffu, m, 2));
            rmax[idx] = m;
        }
        if (t == 0) {
#pragma unroll
            for (int idx = 0; idx < 8; idx++) {
                int rc = wm * 64 + (idx >> 1) * 16 + (idx & 1) * 8 + g;
                red[rc * 4 + wn] = rmax[idx];
            }
        }
        __syncthreads();
#pragma unroll
        for (int idx = 0; idx < 8; idx++) {
            int rc = wm * 64 + (idx >> 1) * 16 + (idx & 1) * 8 + g;
            float m = fmaxf(fmaxf(red[rc * 4 + 0], red[rc * 4 + 1]),
                            fmaxf(red[rc * 4 + 2], red[rc * 4 + 3]));
            rmax[idx] = m;
        }
        __syncthreads();
        float rsum[8];
#pragma unroll
        for (int idx = 0; idx < 8; idx++) {
            int mt = idx >> 1, hi = idx & 1;
            const float mb = rmax[idx] * L2E;
            float s = 0.f;
#pragma unroll
            for (int nt = 0; nt < 4; nt++) {
                int c = col0 + wn * 32 + nt * 8 + t * 2;
                float v0 = (c < N)     ? acc[mt][nt][hi * 2 + 0] + bias[c]     : -1e30f;
                float v1 = (c + 1 < N) ? acc[mt][nt][hi * 2 + 1] + bias[c + 1] : -1e30f;
                uint32_t e = ex2_h2(fmaf(v0, L2E, -mb), fmaf(v1, L2E, -mb));
                float2 f = __half22float2(*(__half2*)&e);
                s += f.x + f.y;
            }
            s += __shfl_xor_sync(0xffffffffu, s, 1);
            s += __shfl_xor_sync(0xffffffffu, s, 2);
            rsum[idx] = s;
        }
        if (t == 0) {
#pragma unroll
            for (int idx = 0; idx < 8; idx++) {
                int rc = wm * 64 + (idx >> 1) * 16 + (idx & 1) * 8 + g;
                red[rc * 4 + wn] = rsum[idx];
            }
        }
        __syncthreads();
        if (t == 0 && wn == 0) {
#pragma unroll
            for (int idx = 0; idx < 8; idx++) {
                int rc = wm * 64 + (idx >> 1) * 16 + (idx & 1) * 8 + g;
                float L = red[rc * 4 + 0] + red[rc * 4 + 1] + red[rc * 4 + 2] + red[rc * 4 + 3];
                smM[(size_t)(row0 + rc) * NTP + blockIdx.y] = rmax[idx];
                smL[(size_t)(row0 + rc) * NTP + blockIdx.y] = L;
            }
        }
    }
}

// ---------------- Tensor-core split-KV flash attention ----------------
static constexpr int FH_PAD = 72;

__global__ __launch_bounds__(128)
void flash_attn_k(const __half* __restrict__ qkv, float* __restrict__ pO,
                  float* __restrict__ pm, float* __restrict__ pl,
                  __half* __restrict__ attnOut) {
    __shared__ __half Qh[64 * FH_PAD];
    __shared__ __half Kh[64 * FH_PAD];
    __shared__ __half Vt[64 * FH_PAD];

    const int tid  = threadIdx.x;
    const int lane = tid & 31;
    const int wid  = tid >> 5;
    const int g    = lane >> 2;
    const int t    = lane & 3;
    const int wr   = wid * 16;

    const int u  = blockIdx.x;
    const int bh = blockIdx.y;
    const int qi = c_qi[u];
    const int sp = c_sp[u];
    const int q0 = qi * 64;
    const int b = bh / HH, h = bh % HH;

    const __half* base = qkv + (size_t)b * TT * 3 * EE + h * DD;

    {
        int r = tid >> 1, cpart = tid & 1;
        const __half* qp = base + (size_t)(q0 + r) * 3 * EE + cpart * 32;
#pragma unroll
        for (int i = 0; i < 4; i++)
            *(uint4*)(Qh + r * FH_PAD + cpart * 32 + i * 8) = *(const uint4*)(qp + i * 8);
    }

    float m_old[2] = {-1e30f, -1e30f};
    float lsum[2]  = {0.f, 0.f};
    float oacc[8][4] = {};
    const int c0 = sp * 4;
    const int c1 = min(c0 + 4, qi + 1);

    for (int ch = c0; ch < c1; ch++) {
        const int kt = ch * 64;
        __syncthreads();
        {
            int r = tid >> 1, cpart = tid & 1;
            const __half* kp = base + (size_t)(kt + r) * 3 * EE + EE + cpart * 32;
            const __half* vp = base + (size_t)(kt + r) * 3 * EE + 2 * EE + cpart * 32;
#pragma unroll
            for (int i = 0; i < 4; i++) {
                *(uint4*)(Kh + r * FH_PAD + cpart * 32 + i * 8) = *(const uint4*)(kp + i * 8);
                uint4 vv = *(const uint4*)(vp + i * 8);
                const __half* hv = (const __half*)&vv;
                int d = cpart * 32 + i * 8;
#pragma unroll
                for (int j = 0; j < 8; j++)
                    Vt[(d + j) * FH_PAD + r] = hv[j];
            }
        }
        __syncthreads();

        float sacc[8][4] = {};
#pragma unroll
        for (int j = 0; j < 4; j++) {
            const int kk = j * 16 + t * 2;
            uint32_t a[4];
            a[0] = *(const uint32_t*)&Qh[(wr + g)     * FH_PAD + kk];
            a[1] = *(const uint32_t*)&Qh[(wr + g + 8) * FH_PAD + kk];
            a[2] = *(const uint32_t*)&Qh[(wr + g)     * FH_PAD + kk + 8];
            a[3] = *(const uint32_t*)&Qh[(wr + g + 8) * FH_PAD + kk + 8];
#pragma unroll
            for (int nt = 0; nt < 8; nt++) {
                uint32_t bfr[2];
                bfr[0] = *(const uint32_t*)&Kh[(nt * 8 + g) * FH_PAD + kk];
                bfr[1] = *(const uint32_t*)&Kh[(nt * 8 + g) * FH_PAD + kk + 8];
                mma_f16(sacc[nt], a, bfr);
            }
        }

        const bool diag = (ch == qi);
        uint32_t ap[4][4];
        float al[2];
#pragma unroll
        for (int rh = 0; rh < 2; rh++) {
            int row = q0 + wr + g + rh * 8;
            float pv[16];
            float lm = -1e30f;
#pragma unroll
            for (int nt = 0; nt < 8; nt++) {
#pragma unroll
                for (int jj = 0; jj < 2; jj++) {
                    float s = sacc[nt][rh * 2 + jj] * 0.125f;
                    if (diag && (kt + nt * 8 + t * 2 + jj > row)) s = -1e30f;
                    pv[nt * 2 + jj] = s;
                    lm = fmaxf(lm, s);
                }
            }
            lm = fmaxf(lm, __shfl_xor_sync(0xffffffffu, lm, 1));
            lm = fmaxf(lm, __shfl_xor_sync(0xffffffffu, lm, 2));
            float mnew = fmaxf(m_old[rh], lm);
            al[rh] = __expf(m_old[rh] - mnew);
            m_old[rh] = mnew;
            const float mb = mnew * L2E;
            float ls = 0.f;
#pragma unroll
            for (int j = 0; j < 4; j++) {
                uint32_t p01 = ex2_h2(fmaf(pv[4 * j + 0], L2E, -mb),
                                      fmaf(pv[4 * j + 1], L2E, -mb));
                uint32_t p23 = ex2_h2(fmaf(pv[4 * j + 2], L2E, -mb),
                                      fmaf(pv[4 * j + 3], L2E, -mb));
                ap[j][rh]     = p01;
                ap[j][rh + 2] = p23;
                float2 f0 = __half22float2(*(__half2*)&p01);
                float2 f1 = __half22float2(*(__half2*)&p23);
                ls += (f0.x + f0.y) + (f1.x + f1.y);
            }
            ls += __shfl_xor_sync(0xffffffffu, ls, 1);
            ls += __shfl_xor_sync(0xffffffffu, ls, 2);
            lsum[rh] = lsum[rh] * al[rh] + ls;
        }

#pragma unroll
        for (int dt = 0; dt < 8; dt++) {
            oacc[dt][0] *= al[0]; oacc[dt][1] *= al[0];
            oacc[dt][2] *= al[1]; oacc[dt][3] *= al[1];
        }
#pragma unroll
        for (int j = 0; j < 4; j++) {
            const int kk = j * 16 + t * 2;
#pragma unroll
            for (int dt = 0; dt < 8; dt++) {
                uint32_t bfr[2];
                bfr[0] = *(const uint32_t*)&Vt[(dt * 8 + g) * FH_PAD + kk];
                bfr[1] = *(const uint32_t*)&Vt[(dt * 8 + g) * FH_PAD + kk + 8];
                mma_f16(oacc[dt], ap[j], bfr);
            }
        }
    }

    int r0 = wr + g;
    if (c_ns[qi] == 1) {
        float inv0 = 1.f / lsum[0], inv1 = 1.f / lsum[1];
        size_t tok0 = (size_t)(b * TT + q0 + r0);
#pragma unroll
        for (int dt = 0; dt < 8; dt++) {
            __half2 h0 = __floats2half2_rn(oacc[dt][0] * inv0, oacc[dt][1] * inv0);
            __half2 h1 = __floats2half2_rn(oacc[dt][2] * inv1, oacc[dt][3] * inv1);
            *(__half2*)(attnOut + tok0 * EE + h * DD + dt * 8 + t * 2) = h0;
            *(__half2*)(attnOut + (tok0 + 8) * EE + h * DD + dt * 8 + t * 2) = h1;
        }
    } else {
        float* po = pO + ((size_t)(bh * NU + u) * 64) * 64;
#pragma unroll
        for (int dt = 0; dt < 8; dt++) {
            *(float2*)(po + (size_t)r0 * 64 + dt * 8 + t * 2)       = make_float2(oacc[dt][0], oacc[dt][1]);
            *(float2*)(po + (size_t)(r0 + 8) * 64 + dt * 8 + t * 2) = make_float2(oacc[dt][2], oacc[dt][3]);
        }
        if (t == 0) {
            pm[(size_t)(bh * NU + u) * 64 + r0]     = m_old[0];
            pm[(size_t)(bh * NU + u) * 64 + r0 + 8] = m_old[1];
            pl[(size_t)(bh * NU + u) * 64 + r0]     = lsum[0];
            pl[(size_t)(bh * NU + u) * 64 + r0 + 8] = lsum[1];
        }
    }
}

// Combine split partials (qi 4..15 only); half output
__global__ __launch_bounds__(256)
void fa_combine_k(const float* __restrict__ pO, const float* __restrict__ pm,
                  const float* __restrict__ pl, __half* __restrict__ out) {
    const int qi = blockIdx.x + 4;
    const int bh = blockIdx.y;
    const int b = bh / HH, h = bh % HH;
    const int ns = c_ns[qi];
    const int u0 = c_u0[qi];
    const int tid = threadIdx.x;
    const int r4 = tid >> 6;
    const int d  = tid & 63;
    for (int p = 0; p < 16; p++) {
        int row = p * 4 + r4;
        float M = -1e30f;
        for (int s = 0; s < ns; s++)
            M = fmaxf(M, pm[(size_t)(bh * NU + u0 + s) * 64 + row]);
        float L = 0.f, O = 0.f;
        for (int s = 0; s < ns; s++) {
            size_t ub = (size_t)(bh * NU + u0 + s);
            float w = __expf(pm[ub * 64 + row] - M);
            L += w * pl[ub * 64 + row];
            O += w * pO[(ub * 64 + row) * 64 + d];
        }
        out[((size_t)(b * TT + qi * 64 + row)) * EE + h * DD + d] = __float2half_rn(O / L);
    }
}

// ---------------- NLL from fused partials ----------------
__global__ __launch_bounds__(128)
void nll2_k(const float* __restrict__ logits, const float* __restrict__ smM,
            const float* __restrict__ smL, const int* __restrict__ tgt,
            float* __restrict__ nll) {
    const int row = blockIdx.x;
    const int tid = threadIdx.x;
    __shared__ float sh[128];
    float M = -1e30f;
    for (int i = tid; i < NTILE; i += 128)
        M = fmaxf(M, smM[(size_t)row * NTP + i]);
    sh[tid] = M; __syncthreads();
    for (int o = 64; o; o >>= 1) { if (tid < o) sh[tid] = fmaxf(sh[tid], sh[tid + o]); __syncthreads(); }
    M = sh[0]; __syncthreads();
    float L = 0.f;
    for (int i = tid; i < NTILE; i += 128)
        L += smL[(size_t)row * NTP + i] * __expf(smM[(size_t)row * NTP + i] - M);
    sh[tid] = L; __syncthreads();
    for (int o = 64; o; o >>= 1) { if (tid < o) sh[tid] += sh[tid + o]; __syncthreads(); }
    if (tid == 0)
        nll[row] = logf(sh[0]) + M - logits[(size_t)row * VV + tgt[row]];
}

__global__ void loss_reduce_k(const float* __restrict__ nll, float* __restrict__ dst, int count) {
    __shared__ float sh[256];
    float s = 0.f;
    for (int i = threadIdx.x; i < MM; i += 256) s += nll[i];
    sh[threadIdx.x] = s; __syncthreads();
    for (int o = 128; o; o >>= 1) { if (threadIdx.x < o) sh[threadIdx.x] += sh[threadIdx.x + o]; __syncthreads(); }
    if (threadIdx.x == 0) {
        float loss = sh[0] * (1.f / (float)MM);
        for (int i = 0; i < count; i++) dst[i] = loss;
    }
}

// ---------------- Launch ----------------
extern "C" void kernel_launch(void* const* d_in, const int* in_sizes, int n_in,
                              void* d_out, int out_size) {
    const int*   idx     = (const int*)  d_in[0];
    const int*   targets = (const int*)  d_in[1];
    const float* wte     = (const float*)d_in[2];
    const float* wpe     = (const float*)d_in[3];
    const float* ln1_g   = (const float*)d_in[4];
    const float* ln1_b   = (const float*)d_in[5];
    const float* qkv_w   = (const float*)d_in[6];
    const float* qkv_b   = (const float*)d_in[7];
    const float* o_w     = (const float*)d_in[8];
    const float* o_b     = (const float*)d_in[9];
    const float* ln2_g   = (const float*)d_in[10];
    const float* ln2_b   = (const float*)d_in[11];
    const float* up_w    = (const float*)d_in[12];
    const float* up_b    = (const float*)d_in[13];
    const float* down_w  = (const float*)d_in[14];
    const float* down_b  = (const float*)d_in[15];
    const float* lnf_g   = (const float*)d_in[16];
    const float* lnf_b   = (const float*)d_in[17];
    const float* lm_b    = (const float*)d_in[18];

    float *h, *nll, *logits_scratch, *part, *pO, *pm, *pl, *smM, *smL;
    __half *xh, *qkvh, *attnh, *mlph, *qkvT, *oT, *upT, *downT, *wteH;
    cudaGetSymbolAddress((void**)&h,    g_h);
    cudaGetSymbolAddress((void**)&xh,   g_xh);
    cudaGetSymbolAddress((void**)&qkvh, g_qkvh);
    cudaGetSymbolAddress((void**)&attnh, g_attnh);
    cudaGetSymbolAddress((void**)&mlph, g_mlph);
    cudaGetSymbolAddress((void**)&nll,  g_nll);
    cudaGetSymbolAddress((void**)&logits_scratch, g_logits);
    cudaGetSymbolAddress((void**)&part, g_part);
    cudaGetSymbolAddress((void**)&pO,   g_pO);
    cudaGetSymbolAddress((void**)&pm,   g_pm);
    cudaGetSymbolAddress((void**)&pl,   g_pl);
    cudaGetSymbolAddress((void**)&smM,  g_sm_m);
    cudaGetSymbolAddress((void**)&smL,  g_sm_l);
    cudaGetSymbolAddress((void**)&qkvT,  g_qkvT);
    cudaGetSymbolAddress((void**)&oT,    g_oT);
    cudaGetSymbolAddress((void**)&upT,   g_upT);
    cudaGetSymbolAddress((void**)&downT, g_downT);
    cudaGetSymbolAddress((void**)&wteH,  g_wteH);

    static bool attr_set = false;
    if (!attr_set) {
        cudaFuncSetAttribute(hgemm_k<0, false, false, true,  false, false>, cudaFuncAttributeMaxDynamicSharedMemorySize, HSMEM);
        cudaFuncSetAttribute(hgemm_k<0, false, false, false, false, true >, cudaFuncAttributeMaxDynamicSharedMemorySize, HSMEM);
        cudaFuncSetAttribute(hgemm_k<1, false, false, true,  false, false>, cudaFuncAttributeMaxDynamicSharedMemorySize, HSMEM);
        cudaFuncSetAttribute(hgemm_k<0, false, true,  false, true,  false>, cudaFuncAttributeMaxDynamicSharedMemorySize, HSMEM);
        attr_set = true;
    }

    float* logits = ((long long)out_size >= NBTV) ? (float*)d_out : logits_scratch;

    transh_k<<<dim3(3 * EE / 64, EE / 64, LL), 256>>>(qkv_w, qkvT, EE, 3 * EE);
    transh_k<<<dim3(EE / 64, EE / 64, LL), 256>>>(o_w, oT, EE, EE);
    transh_k<<<dim3(4 * EE / 64, EE / 64, LL), 256>>>(up_w, upT, EE, 4 * EE);
    transh_k<<<dim3(EE / 64, 4 * EE / 64, LL), 256>>>(down_w, downT, 4 * EE, EE);
    {
        int n = VV * EE / 4;
        halfcpy_k<<<(n + 255) / 256, 256>>>(wte, wteH, n);
    }

    embed_k<<<MM, 256>>>(idx, wte, wpe, h);

    for (int l = 0; l < LL; l++) {
        layernorm_k<<<MM, 256>>>(h, ln1_g + (size_t)l * EE, ln1_b + (size_t)l * EE, xh);
        hgemm_k<0, false, false, true, false, false><<<dim3(MM / 128, 3 * EE / 128), 256, HSMEM>>>(
            xh, qkvT + (size_t)l * 3 * EE * EE, qkv_b + (size_t)l * 3 * EE, nullptr,
            qkvh, MM, 3 * EE, EE, nullptr, nullptr);
        flash_attn_k<<<dim3(NU, BB * HH), 128>>>(qkvh, pO, pm, pl, attnh);
        fa_combine_k<<<dim3(12, BB * HH), 256>>>(pO, pm, pl, attnh);
        // o-proj: split-K=2 into partials, then residual-add
        hgemm_k<0, false, false, false, false, true><<<dim3(MM / 128, EE / 128, 2), 256, HSMEM>>>(
            attnh, oT + (size_t)l * EE * EE, nullptr, nullptr,
            part, MM, EE, EE, nullptr, nullptr);
        resadd_k<<<MM * EE / 1024, 256>>>(h, part, o_b + (size_t)l * EE);
        layernorm_k<<<MM, 256>>>(h, ln2_g + (size_t)l * EE, ln2_b + (size_t)l * EE, xh);
        hgemm_k<1, false, false, true, false, false><<<dim3(MM / 128, 4 * EE / 128), 256, HSMEM>>>(
            xh, upT + (size_t)l * 4 * EE * EE, up_b + (size_t)l * 4 * EE, nullptr,
            mlph, MM, 4 * EE, EE, nullptr, nullptr);
        // down-proj: split-K=2 into partials, then residual-add
        hgemm_k<0, false, false, false, false, true><<<dim3(MM / 128, EE / 128, 2), 256, HSMEM>>>(
            mlph, downT + (size_t)l * 4 * EE * EE, nullptr, nullptr,
            part, MM, EE, 4 * EE, nullptr, nullptr);
        resadd_k<<<MM * EE / 1024, 256>>>(h, part, down_b + (size_t)l * EE);
    }

    layernorm_k<<<MM, 256>>>(h, lnf_g, lnf_b, xh);
    hgemm_k<0, false, true, false, true, false><<<dim3(MM / 128, (VV + 127) / 128), 256, HSMEM>>>(
        xh, wteH, lm_b, nullptr, logits, MM, VV, EE, smM, smL);

    nll2_k<<<MM, 128>>>(logits, smM, smL, targets, nll);

    long long extra = (long long)out_size - NBTV;
    if (extra > 0) {
        loss_reduce_k<<<1, 256>>>(nll, (float*)d_out + NBTV, (int)extra);
    } else if ((long long)out_size < NBTV) {
        loss_reduce_k<<<1, 256>>>(nll, (float*)d_out, out_size);
    }
}

// round 17
// speedup vs baseline: 1.1115x; 1.0115x over previous
#include <cuda_runtime.h>
#include <cuda_fp16.h>
#include <math.h>
#include <stdint.h>

// ---------------- Problem constants ----------------
static constexpr int BB = 2;
static constexpr int TT = 1024;
static constexpr int EE = 1024;
static constexpr int HH = 16;
static constexpr int DD = 64;
static constexpr int LL = 12;
static constexpr int VV = 50257;
static constexpr int MM = BB * TT;
static constexpr long long NBTV = (long long)MM * VV;
static constexpr int NU = 40;
static constexpr float L2E = 1.44269504088896340736f;
static constexpr int NTILE = (VV + 127) / 128;
static constexpr int NTP = 400;

// ---------------- Scratch ----------------
__device__ float g_h   [(size_t)MM * EE];
__device__ __half g_xh  [(size_t)MM * EE];
__device__ __half g_qkvh[(size_t)MM * 3 * EE];
__device__ __half g_attnh[(size_t)MM * EE];
__device__ __half g_mlph [(size_t)MM * 4 * EE];
__device__ float g_nll [MM];
__device__ float g_logits[(size_t)MM * VV];
__device__ float g_part[(size_t)2 * MM * EE];
__device__ float g_pO[(size_t)BB * HH * NU * 64 * 64];
__device__ float g_pm[(size_t)BB * HH * NU * 64];
__device__ float g_pl[(size_t)BB * HH * NU * 64];
__device__ float g_sm_m[(size_t)MM * NTP];
__device__ float g_sm_l[(size_t)MM * NTP];
__device__ __half g_qkvT [(size_t)LL * 3 * EE * EE];
__device__ __half g_oT   [(size_t)LL * EE * EE];
__device__ __half g_upT  [(size_t)LL * 4 * EE * EE];
__device__ __half g_downT[(size_t)LL * 4 * EE * EE];
__device__ __half g_wteH [(size_t)VV * EE];

__constant__ int c_qi[NU] = {15,15,15,15, 14,14,14,14, 13,13,13,13, 12,12,12,12,
                             11,11,11, 10,10,10, 9,9,9, 8,8,8, 7,7, 6,6, 5,5, 4,4,
                             3, 2, 1, 0};
__constant__ int c_sp[NU] = {0,1,2,3, 0,1,2,3, 0,1,2,3, 0,1,2,3,
                             0,1,2, 0,1,2, 0,1,2, 0,1,2, 0,1, 0,1, 0,1, 0,1,
                             0, 0, 0, 0};
__constant__ int c_u0[16] = {39,38,37,36, 34,32,30,28, 25,22,19,16, 12,8,4,0};
__constant__ int c_ns[16] = {1,1,1,1, 2,2,2,2, 3,3,3,3, 4,4,4,4};

// ---------------- Helpers ----------------
__device__ __forceinline__ uint32_t smem_u32(const void* p) {
    uint32_t r;
    asm("{ .reg .u64 t; cvta.to.shared.u64 t, %1; cvt.u32.u64 %0, t; }" : "=r"(r) : "l"(p));
    return r;
}

__device__ __forceinline__ void mma_f16(float c[4], const uint32_t a[4], const uint32_t b[2]) {
    asm volatile(
        "mma.sync.aligned.m16n8k16.row.col.f32.f16.f16.f32 "
        "{%0,%1,%2,%3}, {%4,%5,%6,%7}, {%8,%9}, {%0,%1,%2,%3};"
        : "+f"(c[0]), "+f"(c[1]), "+f"(c[2]), "+f"(c[3])
        : "r"(a[0]), "r"(a[1]), "r"(a[2]), "r"(a[3]), "r"(b[0]), "r"(b[1]));
}

__device__ __forceinline__ void ldsm_x4(uint32_t r[4], uint32_t addr) {
    asm volatile("ldmatrix.sync.aligned.m8n8.x4.shared.b16 {%0,%1,%2,%3}, [%4];"
        : "=r"(r[0]), "=r"(r[1]), "=r"(r[2]), "=r"(r[3]) : "r"(addr));
}

__device__ __forceinline__ void st_half4(__half* p, float a, float b, float c, float d) {
    __half2 lo = __floats2half2_rn(a, b);
    __half2 hi = __floats2half2_rn(c, d);
    uint2 v = make_uint2(*(uint32_t*)&lo, *(uint32_t*)&hi);
    *(uint2*)p = v;
}

__device__ __forceinline__ uint32_t ex2_h2(float a, float b) {
    __half2 h = __floats2half2_rn(a, b);
    uint32_t u = *(uint32_t*)&h, o;
    asm("ex2.approx.f16x2 %0, %1;" : "=r"(o) : "r"(u));
    return o;
}

// ---------------- Weight prep ----------------
__global__ void transh_k(const float* __restrict__ W, __half* __restrict__ WT,
                         int K, int N) {
    __shared__ float tl[64][65];
    size_t off = (size_t)blockIdx.z * K * N;
    int n0 = blockIdx.x * 64, k0 = blockIdx.y * 64;
    int tid = threadIdx.x;
    int rr = tid >> 4;
    int rc = (tid & 15) << 2;
#pragma unroll
    for (int i = 0; i < 4; i++) {
        float4 v = *(const float4*)(W + off + (size_t)(k0 + rr + 16 * i) * N + n0 + rc);
        tl[rr + 16 * i][rc + 0] = v.x;
        tl[rr + 16 * i][rc + 1] = v.y;
        tl[rr + 16 * i][rc + 2] = v.z;
        tl[rr + 16 * i][rc + 3] = v.w;
    }
    __syncthreads();
    int wn = tid >> 3;
    int wk = (tid & 7) << 3;
#pragma unroll
    for (int i = 0; i < 2; i++) {
        int n = wn + 32 * i;
        __half hv[8];
#pragma unroll
        for (int j = 0; j < 8; j++) hv[j] = __float2half_rn(tl[wk + j][n]);
        *(uint4*)(WT + off + (size_t)(n0 + n) * K + k0 + wk) = *(uint4*)hv;
    }
}

__global__ void halfcpy_k(const float* __restrict__ src, __half* __restrict__ dst, int n4) {
    int i = blockIdx.x * 256 + threadIdx.x;
    if (i < n4) {
        float4 v = *(const float4*)(src + (size_t)i * 4);
        st_half4(dst + (size_t)i * 4, v.x, v.y, v.z, v.w);
    }
}

// ---------------- Embedding ----------------
__global__ void embed_k(const int* __restrict__ idx, const float* __restrict__ wte,
                        const float* __restrict__ wpe, float* __restrict__ h) {
    int bt = blockIdx.x;
    int t  = bt % TT;
    int tok = idx[bt];
    int i = threadIdx.x * 4;
    float4 a = *(const float4*)(wte + (size_t)tok * EE + i);
    float4 p = *(const float4*)(wpe + (size_t)t   * EE + i);
    a.x += p.x; a.y += p.y; a.z += p.z; a.w += p.w;
    *(float4*)(h + (size_t)bt * EE + i) = a;
}

// ---------------- LayerNorm: fp32 in, half out (standalone, layer-0 ln1 only) ----------------
__global__ void layernorm_k(const float* __restrict__ xin, const float* __restrict__ g,
                            const float* __restrict__ bb, __half* __restrict__ y) {
    __shared__ float rs[8], rq[8];
    int row = blockIdx.x, tid = threadIdx.x;
    const float* xr = xin + (size_t)row * EE;
    float4 v = *(const float4*)(xr + tid * 4);
    float s = v.x + v.y + v.z + v.w;
    float q = v.x * v.x + v.y * v.y + v.z * v.z + v.w * v.w;
#pragma unroll
    for (int o = 16; o; o >>= 1) {
        s += __shfl_xor_sync(0xffffffffu, s, o);
        q += __shfl_xor_sync(0xffffffffu, q, o);
    }
    if ((tid & 31) == 0) { rs[tid >> 5] = s; rq[tid >> 5] = q; }
    __syncthreads();
    if (tid == 0) {
        float S = 0.f, Q = 0.f;
#pragma unroll
        for (int i = 0; i < 8; i++) { S += rs[i]; Q += rq[i]; }
        rs[0] = S; rq[0] = Q;
    }
    __syncthreads();
    float mean = rs[0] * (1.f / EE);
    float var  = rq[0] * (1.f / EE) - mean * mean;
    float rstd = rsqrtf(var + 1e-5f);
    float4 gg = *(const float4*)(g  + tid * 4);
    float4 be = *(const float4*)(bb + tid * 4);
    st_half4(y + (size_t)row * EE + tid * 4,
             (v.x - mean) * rstd * gg.x + be.x,
             (v.y - mean) * rstd * gg.y + be.y,
             (v.z - mean) * rstd * gg.z + be.z,
             (v.w - mean) * rstd * gg.w + be.w);
}

// ---------------- Fused split-K combine + residual + LayerNorm ----------------
// h += p0 + p1 + bias;  y = LN(h) * g + b   (one pass, one block per row)
__global__ void resln_k(float* __restrict__ h, const float* __restrict__ p,
                        const float* __restrict__ bias,
                        const float* __restrict__ g, const float* __restrict__ bb,
                        __half* __restrict__ y) {
    __shared__ float rs[8], rq[8];
    int row = blockIdx.x, tid = threadIdx.x;
    size_t base = (size_t)row * EE + tid * 4;
    float4 hv = *(float4*)(h + base);
    float4 a  = *(const float4*)(p + base);
    float4 b2 = *(const float4*)(p + (size_t)MM * EE + base);
    float4 bv = *(const float4*)(bias + tid * 4);
    hv.x += a.x + b2.x + bv.x;
    hv.y += a.y + b2.y + bv.y;
    hv.z += a.z + b2.z + bv.z;
    hv.w += a.w + b2.w + bv.w;
    *(float4*)(h + base) = hv;
    float s = hv.x + hv.y + hv.z + hv.w;
    float q = hv.x * hv.x + hv.y * hv.y + hv.z * hv.z + hv.w * hv.w;
#pragma unroll
    for (int o = 16; o; o >>= 1) {
        s += __shfl_xor_sync(0xffffffffu, s, o);
        q += __shfl_xor_sync(0xffffffffu, q, o);
    }
    if ((tid & 31) == 0) { rs[tid >> 5] = s; rq[tid >> 5] = q; }
    __syncthreads();
    if (tid == 0) {
        float S = 0.f, Q = 0.f;
#pragma unroll
        for (int i = 0; i < 8; i++) { S += rs[i]; Q += rq[i]; }
        rs[0] = S; rq[0] = Q;
    }
    __syncthreads();
    float mean = rs[0] * (1.f / EE);
    float var  = rq[0] * (1.f / EE) - mean * mean;
    float rstd = rsqrtf(var + 1e-5f);
    float4 gg = *(const float4*)(g  + tid * 4);
    float4 be = *(const float4*)(bb + tid * 4);
    st_half4(y + (size_t)row * EE + tid * 4,
             (hv.x - mean) * rstd * gg.x + be.x,
             (hv.y - mean) * rstd * gg.y + be.y,
             (hv.z - mean) * rstd * gg.z + be.z,
             (hv.w - mean) * rstd * gg.w + be.w);
}

// ---------------- cp.async 3-stage fp16 GEMM with ldmatrix (MT=128) ----------------
static constexpr int H_AST = 72;
static constexpr int H_STG = 2 * 128 * H_AST;
static constexpr int HSMEM = 3 * H_STG * 2;

template<int ACT, bool RES, bool GUARD, bool OUT_HALF, bool SMAX, bool SPLITK>
__global__ __launch_bounds__(256, 2)
void hgemm_k(const __half* __restrict__ A, const __half* __restrict__ Bw,
             const float* __restrict__ bias, const float* __restrict__ Res,
             void* __restrict__ Cv, int M, int N, int K,
             float* __restrict__ smM, float* __restrict__ smL) {
    extern __shared__ __half smh[];
    const uint32_t sb = smem_u32(smh);
    const int tid  = threadIdx.x;
    const int lane = tid & 31;
    const int wid  = tid >> 5;
    const int wm   = wid >> 2;
    const int wn   = wid & 3;
    const int g    = lane >> 2;
    const int t    = lane & 3;
    const int la16  = lane & 15;
    const int lac8  = (lane >> 4) << 3;
    const int lbrow = ((lane >> 4) << 3) + (lane & 7);
    const int lbcol = ((lane >> 3) & 1) << 3;

    const int row0 = blockIdx.x * 128;
    const int col0 = blockIdx.y * 128;
    const int kbase = SPLITK ? blockIdx.z * (K >> 1) : 0;
    const int iters = (SPLITK ? (K >> 1) : K) >> 6;

    auto issue_stage = [&](int it) {
        const int k0 = kbase + (it << 6);
        const int s = it % 3;
        const uint32_t stA = sb + (uint32_t)(s * H_STG) * 2;
        const uint32_t stB = stA + (uint32_t)(128 * H_AST) * 2;
#pragma unroll
        for (int u = 0; u < 4; u++) {
            int ca = u * 256 + tid;
            int r = ca >> 3, c16 = ca & 7;
            const __half* gs = A + (size_t)(row0 + r) * K + k0 + c16 * 8;
            uint32_t sd = stA + (uint32_t)(r * H_AST + c16 * 8) * 2;
            asm volatile("cp.async.cg.shared.global [%0], [%1], 16;" :: "r"(sd), "l"(gs));
        }
#pragma unroll
        for (int u = 0; u < 4; u++) {
            int cb = u * 256 + tid;
            int n = cb >> 3, c16 = cb & 7;
            const __half* gs = Bw + (size_t)(col0 + n) * K + k0 + c16 * 8;
            uint32_t sd = stB + (uint32_t)(n * H_AST + c16 * 8) * 2;
            if (GUARD) {
                int sz = (col0 + n < N) ? 16 : 0;
                asm volatile("cp.async.cg.shared.global [%0], [%1], 16, %2;"
                             :: "r"(sd), "l"(gs), "r"(sz));
            } else {
                asm volatile("cp.async.cg.shared.global [%0], [%1], 16;" :: "r"(sd), "l"(gs));
            }
        }
        asm volatile("cp.async.commit_group;" ::: "memory");
    };

    float acc[4][4][4] = {};

    issue_stage(0);
    issue_stage(1);

    for (int it = 0; it < iters; ++it) {
        if (it == iters - 1) {
            asm volatile("cp.async.wait_group 0;" ::: "memory");
        } else {
            asm volatile("cp.async.wait_group 1;" ::: "memory");
        }
        __syncthreads();
        if (it + 2 < iters) issue_stage(it + 2);

        const uint32_t stA = sb + (uint32_t)((it % 3) * H_STG) * 2;
        const uint32_t stB = stA + (uint32_t)(128 * H_AST) * 2;
        const uint32_t aBase = stA + (uint32_t)((wm * 64 + la16) * H_AST + lac8) * 2;
        const uint32_t bBase = stB + (uint32_t)((wn * 32 + lbrow) * H_AST + lbcol) * 2;
#pragma unroll
        for (int ks = 0; ks < 4; ks++) {
            uint32_t afr[4][4];
            uint32_t bfr[4][2];
#pragma unroll
            for (int mt = 0; mt < 4; mt++)
                ldsm_x4(afr[mt], aBase + (uint32_t)(mt * 16 * H_AST + ks * 16) * 2);
#pragma unroll
            for (int ntp = 0; ntp < 2; ntp++) {
                uint32_t bp[4];
                ldsm_x4(bp, bBase + (uint32_t)(ntp * 16 * H_AST + ks * 16) * 2);
                bfr[2 * ntp][0]     = bp[0]; bfr[2 * ntp][1]     = bp[1];
                bfr[2 * ntp + 1][0] = bp[2]; bfr[2 * ntp + 1][1] = bp[3];
            }
#pragma unroll
            for (int mt = 0; mt < 4; mt++)
#pragma unroll
                for (int nt = 0; nt < 4; nt++)
                    mma_f16(acc[mt][nt], afr[mt], bfr[nt]);
        }
    }

    // ---- epilogue ----
#pragma unroll
    for (int mt = 0; mt < 4; mt++) {
        int r0 = row0 + wm * 64 + mt * 16 + g;
#pragma unroll
        for (int nt = 0; nt < 4; nt++) {
            int c = col0 + wn * 32 + nt * 8 + t * 2;
#pragma unroll
            for (int half_i = 0; half_i < 2; half_i++) {
                int r = r0 + half_i * 8;
                float v0 = acc[mt][nt][half_i * 2 + 0];
                float v1 = acc[mt][nt][half_i * 2 + 1];
                if (SPLITK) {
                    float* C = (float*)Cv + (size_t)blockIdx.z * M * N;
                    *(float2*)(C + (size_t)r * N + c) = make_float2(v0, v1);
                } else if (GUARD) {
                    float* C = (float*)Cv;
                    if (c < N)     C[(size_t)r * N + c]     = v0 + bias[c];
                    if (c + 1 < N) C[(size_t)r * N + c + 1] = v1 + bias[c + 1];
                } else {
                    v0 += bias[c]; v1 += bias[c + 1];
                    if (ACT == 1) {
                        v0 = 0.5f * v0 * (1.f + erff(v0 * 0.70710678118654752f));
                        v1 = 0.5f * v1 * (1.f + erff(v1 * 0.70710678118654752f));
                    }
                    if (RES) {
                        v0 += Res[(size_t)r * N + c];
                        v1 += Res[(size_t)r * N + c + 1];
                    }
                    if (OUT_HALF) {
                        __half2 hv = __floats2half2_rn(v0, v1);
                        *(__half2*)((__half*)Cv + (size_t)r * N + c) = hv;
                    } else {
                        *(float2*)((float*)Cv + (size_t)r * N + c) = make_float2(v0, v1);
                    }
                }
            }
        }
    }

    // ---- fused per-row softmax partials (LM head) ----
    if (SMAX) {
        float* red = (float*)smh;
        __syncthreads();
        float rmax[8];
#pragma unroll
        for (int idx = 0; idx < 8; idx++) {
            int mt = idx >> 1, hi = idx & 1;
            float m = -1e30f;
#pragma unroll
            for (int nt = 0; nt < 4; nt++) {
                int c = col0 + wn * 32 + nt * 8 + t * 2;
                float v0 = (c < N)     ? acc[mt][nt][hi * 2 + 0] + bias[c]     : -1e30f;
                float v1 = (c + 1 < N) ? acc[mt][nt][hi * 2 + 1] + bias[c + 1] : -1e30f;
                m = fmaxf(m, fmaxf(v0, v1));
            }
            m = fmaxf(m, __shfl_xor_sync(0xffffffffu, m, 1));
            m = fmaxf(m, __shfl_xor_sync(0xffffffffu, m, 2));
            rmax[idx] = m;
        }
        if (t == 0) {
#pragma unroll
            for (int idx = 0; idx < 8; idx++) {
                int rc = wm * 64 + (idx >> 1) * 16 + (idx & 1) * 8 + g;
                red[rc * 4 + wn] = rmax[idx];
            }
        }
        __syncthreads();
#pragma unroll
        for (int idx = 0; idx < 8; idx++) {
            int rc = wm * 64 + (idx >> 1) * 16 + (idx & 1) * 8 + g;
            float m = fmaxf(fmaxf(red[rc * 4 + 0], red[rc * 4 + 1]),
                            fmaxf(red[rc * 4 + 2], red[rc * 4 + 3]));
            rmax[idx] = m;
        }
        __syncthreads();
        float rsum[8];
#pragma unroll
        for (int idx = 0; idx < 8; idx++) {
            int mt = idx >> 1, hi = idx & 1;
            const float mb = rmax[idx] * L2E;
            float s = 0.f;
#pragma unroll
            for (int nt = 0; nt < 4; nt++) {
                int c = col0 + wn * 32 + nt * 8 + t * 2;
                float v0 = (c < N)     ? acc[mt][nt][hi * 2 + 0] + bias[c]     : -1e30f;
                float v1 = (c + 1 < N) ? acc[mt][nt][hi * 2 + 1] + bias[c + 1] : -1e30f;
                uint32_t e = ex2_h2(fmaf(v0, L2E, -mb), fmaf(v1, L2E, -mb));
                float2 f = __half22float2(*(__half2*)&e);
                s += f.x + f.y;
            }
            s += __shfl_xor_sync(0xffffffffu, s, 1);
            s += __shfl_xor_sync(0xffffffffu, s, 2);
            rsum[idx] = s;
        }
        if (t == 0) {
#pragma unroll
            for (int idx = 0; idx < 8; idx++) {
                int rc = wm * 64 + (idx >> 1) * 16 + (idx & 1) * 8 + g;
                red[rc * 4 + wn] = rsum[idx];
            }
        }
        __syncthreads();
        if (t == 0 && wn == 0) {
#pragma unroll
            for (int idx = 0; idx < 8; idx++) {
                int rc = wm * 64 + (idx >> 1) * 16 + (idx & 1) * 8 + g;
                float L = red[rc * 4 + 0] + red[rc * 4 + 1] + red[rc * 4 + 2] + red[rc * 4 + 3];
                smM[(size_t)(row0 + rc) * NTP + blockIdx.y] = rmax[idx];
                smL[(size_t)(row0 + rc) * NTP + blockIdx.y] = L;
            }
        }
    }
}

// ---------------- Tensor-core split-KV flash attention ----------------
static constexpr int FH_PAD = 72;

__global__ __launch_bounds__(128)
void flash_attn_k(const __half* __restrict__ qkv, float* __restrict__ pO,
                  float* __restrict__ pm, float* __restrict__ pl,
                  __half* __restrict__ attnOut) {
    __shared__ __half Qh[64 * FH_PAD];
    __shared__ __half Kh[64 * FH_PAD];
    __shared__ __half Vt[64 * FH_PAD];

    const int tid  = threadIdx.x;
    const int lane = tid & 31;
    const int wid  = tid >> 5;
    const int g    = lane >> 2;
    const int t    = lane & 3;
    const int wr   = wid * 16;

    const int u  = blockIdx.x;
    const int bh = blockIdx.y;
    const int qi = c_qi[u];
    const int sp = c_sp[u];
    const int q0 = qi * 64;
    const int b = bh / HH, h = bh % HH;

    const __half* base = qkv + (size_t)b * TT * 3 * EE + h * DD;

    {
        int r = tid >> 1, cpart = tid & 1;
        const __half* qp = base + (size_t)(q0 + r) * 3 * EE + cpart * 32;
#pragma unroll
        for (int i = 0; i < 4; i++)
            *(uint4*)(Qh + r * FH_PAD + cpart * 32 + i * 8) = *(const uint4*)(qp + i * 8);
    }

    float m_old[2] = {-1e30f, -1e30f};
    float lsum[2]  = {0.f, 0.f};
    float oacc[8][4] = {};
    const int c0 = sp * 4;
    const int c1 = min(c0 + 4, qi + 1);

    for (int ch = c0; ch < c1; ch++) {
        const int kt = ch * 64;
        __syncthreads();
        {
            int r = tid >> 1, cpart = tid & 1;
            const __half* kp = base + (size_t)(kt + r) * 3 * EE + EE + cpart * 32;
            const __half* vp = base + (size_t)(kt + r) * 3 * EE + 2 * EE + cpart * 32;
#pragma unroll
            for (int i = 0; i < 4; i++) {
                *(uint4*)(Kh + r * FH_PAD + cpart * 32 + i * 8) = *(const uint4*)(kp + i * 8);
                uint4 vv = *(const uint4*)(vp + i * 8);
                const __half* hv = (const __half*)&vv;
                int d = cpart * 32 + i * 8;
#pragma unroll
                for (int j = 0; j < 8; j++)
                    Vt[(d + j) * FH_PAD + r] = hv[j];
            }
        }
        __syncthreads();

        float sacc[8][4] = {};
#pragma unroll
        for (int j = 0; j < 4; j++) {
            const int kk = j * 16 + t * 2;
            uint32_t a[4];
            a[0] = *(const uint32_t*)&Qh[(wr + g)     * FH_PAD + kk];
            a[1] = *(const uint32_t*)&Qh[(wr + g + 8) * FH_PAD + kk];
            a[2] = *(const uint32_t*)&Qh[(wr + g)     * FH_PAD + kk + 8];
            a[3] = *(const uint32_t*)&Qh[(wr + g + 8) * FH_PAD + kk + 8];
#pragma unroll
            for (int nt = 0; nt < 8; nt++) {
                uint32_t bfr[2];
                bfr[0] = *(const uint32_t*)&Kh[(nt * 8 + g) * FH_PAD + kk];
                bfr[1] = *(const uint32_t*)&Kh[(nt * 8 + g) * FH_PAD + kk + 8];
                mma_f16(sacc[nt], a, bfr);
            }
        }

        const bool diag = (ch == qi);
        uint32_t ap[4][4];
        float al[2];
#pragma unroll
        for (int rh = 0; rh < 2; rh++) {
            int row = q0 + wr + g + rh * 8;
            float pv[16];
            float lm = -1e30f;
#pragma unroll
            for (int nt = 0; nt < 8; nt++) {
#pragma unroll
                for (int jj = 0; jj < 2; jj++) {
                    float s = sacc[nt][rh * 2 + jj] * 0.125f;
                    if (diag && (kt + nt * 8 + t * 2 + jj > row)) s = -1e30f;
                    pv[nt * 2 + jj] = s;
                    lm = fmaxf(lm, s);
                }
            }
            lm = fmaxf(lm, __shfl_xor_sync(0xffffffffu, lm, 1));
            lm = fmaxf(lm, __shfl_xor_sync(0xffffffffu, lm, 2));
            float mnew = fmaxf(m_old[rh], lm);
            al[rh] = __expf(m_old[rh] - mnew);
            m_old[rh] = mnew;
            const float mb = mnew * L2E;
            float ls = 0.f;
#pragma unroll
            for (int j = 0; j < 4; j++) {
                uint32_t p01 = ex2_h2(fmaf(pv[4 * j + 0], L2E, -mb),
                                      fmaf(pv[4 * j + 1], L2E, -mb));
                uint32_t p23 = ex2_h2(fmaf(pv[4 * j + 2], L2E, -mb),
                                      fmaf(pv[4 * j + 3], L2E, -mb));
                ap[j][rh]     = p01;
                ap[j][rh + 2] = p23;
                float2 f0 = __half22float2(*(__half2*)&p01);
                float2 f1 = __half22float2(*(__half2*)&p23);
                ls += (f0.x + f0.y) + (f1.x + f1.y);
            }
            ls += __shfl_xor_sync(0xffffffffu, ls, 1);
            ls += __shfl_xor_sync(0xffffffffu, ls, 2);
            lsum[rh] = lsum[rh] * al[rh] + ls;
        }

#pragma unroll
        for (int dt = 0; dt < 8; dt++) {
            oacc[dt][0] *= al[0]; oacc[dt][1] *= al[0];
            oacc[dt][2] *= al[1]; oacc[dt][3] *= al[1];
        }
#pragma unroll
        for (int j = 0; j < 4; j++) {
            const int kk = j * 16 + t * 2;
#pragma unroll
            for (int dt = 0; dt < 8; dt++) {
                uint32_t bfr[2];
                bfr[0] = *(const uint32_t*)&Vt[(dt * 8 + g) * FH_PAD + kk];
                bfr[1] = *(const uint32_t*)&Vt[(dt * 8 + g) * FH_PAD + kk + 8];
                mma_f16(oacc[dt], ap[j], bfr);
            }
        }
    }

    int r0 = wr + g;
    if (c_ns[qi] == 1) {
        float inv0 = 1.f / lsum[0], inv1 = 1.f / lsum[1];
        size_t tok0 = (size_t)(b * TT + q0 + r0);
#pragma unroll
        for (int dt = 0; dt < 8; dt++) {
            __half2 h0 = __floats2half2_rn(oacc[dt][0] * inv0, oacc[dt][1] * inv0);
            __half2 h1 = __floats2half2_rn(oacc[dt][2] * inv1, oacc[dt][3] * inv1);
            *(__half2*)(attnOut + tok0 * EE + h * DD + dt * 8 + t * 2) = h0;
            *(__half2*)(attnOut + (tok0 + 8) * EE + h * DD + dt * 8 + t * 2) = h1;
        }
    } else {
        float* po = pO + ((size_t)(bh * NU + u) * 64) * 64;
#pragma unroll
        for (int dt = 0; dt < 8; dt++) {
            *(float2*)(po + (size_t)r0 * 64 + dt * 8 + t * 2)       = make_float2(oacc[dt][0], oacc[dt][1]);
            *(float2*)(po + (size_t)(r0 + 8) * 64 + dt * 8 + t * 2) = make_float2(oacc[dt][2], oacc[dt][3]);
        }
        if (t == 0) {
            pm[(size_t)(bh * NU + u) * 64 + r0]     = m_old[0];
            pm[(size_t)(bh * NU + u) * 64 + r0 + 8] = m_old[1];
            pl[(size_t)(bh * NU + u) * 64 + r0]     = lsum[0];
            pl[(size_t)(bh * NU + u) * 64 + r0 + 8] = lsum[1];
        }
    }
}

// Combine split partials (qi 4..15 only); half output
__global__ __launch_bounds__(256)
void fa_combine_k(const float* __restrict__ pO, const float* __restrict__ pm,
                  const float* __restrict__ pl, __half* __restrict__ out) {
    const int qi = blockIdx.x + 4;
    const int bh = blockIdx.y;
    const int b = bh / HH, h = bh % HH;
    const int ns = c_ns[qi];
    const int u0 = c_u0[qi];
    const int tid = threadIdx.x;
    const int r4 = tid >> 6;
    const int d  = tid & 63;
    for (int p = 0; p < 16; p++) {
        int row = p * 4 + r4;
        float M = -1e30f;
        for (int s = 0; s < ns; s++)
            M = fmaxf(M, pm[(size_t)(bh * NU + u0 + s) * 64 + row]);
        float L = 0.f, O = 0.f;
        for (int s = 0; s < ns; s++) {
            size_t ub = (size_t)(bh * NU + u0 + s);
            float w = __expf(pm[ub * 64 + row] - M);
            L += w * pl[ub * 64 + row];
            O += w * pO[(ub * 64 + row) * 64 + d];
        }
        out[((size_t)(b * TT + qi * 64 + row)) * EE + h * DD + d] = __float2half_rn(O / L);
    }
}

// ---------------- NLL from fused partials ----------------
__global__ __launch_bounds__(128)
void nll2_k(const float* __restrict__ logits, const float* __restrict__ smM,
            const float* __restrict__ smL, const int* __restrict__ tgt,
            float* __restrict__ nll) {
    const int row = blockIdx.x;
    const int tid = threadIdx.x;
    __shared__ float sh[128];
    float M = -1e30f;
    for (int i = tid; i < NTILE; i += 128)
        M = fmaxf(M, smM[(size_t)row * NTP + i]);
    sh[tid] = M; __syncthreads();
    for (int o = 64; o; o >>= 1) { if (tid < o) sh[tid] = fmaxf(sh[tid], sh[tid + o]); __syncthreads(); }
    M = sh[0]; __syncthreads();
    float L = 0.f;
    for (int i = tid; i < NTILE; i += 128)
        L += smL[(size_t)row * NTP + i] * __expf(smM[(size_t)row * NTP + i] - M);
    sh[tid] = L; __syncthreads();
    for (int o = 64; o; o >>= 1) { if (tid < o) sh[tid] += sh[tid + o]; __syncthreads(); }
    if (tid == 0)
        nll[row] = logf(sh[0]) + M - logits[(size_t)row * VV + tgt[row]];
}

__global__ void loss_reduce_k(const float* __restrict__ nll, float* __restrict__ dst, int count) {
    __shared__ float sh[256];
    float s = 0.f;
    for (int i = threadIdx.x; i < MM; i += 256) s += nll[i];
    sh[threadIdx.x] = s; __syncthreads();
    for (int o = 128; o; o >>= 1) { if (threadIdx.x < o) sh[threadIdx.x] += sh[threadIdx.x + o]; __syncthreads(); }
    if (threadIdx.x == 0) {
        float loss = sh[0] * (1.f / (float)MM);
        for (int i = 0; i < count; i++) dst[i] = loss;
    }
}

// ---------------- Launch ----------------
extern "C" void kernel_launch(void* const* d_in, const int* in_sizes, int n_in,
                              void* d_out, int out_size) {
    const int*   idx     = (const int*)  d_in[0];
    const int*   targets = (const int*)  d_in[1];
    const float* wte     = (const float*)d_in[2];
    const float* wpe     = (const float*)d_in[3];
    const float* ln1_g   = (const float*)d_in[4];
    const float* ln1_b   = (const float*)d_in[5];
    const float* qkv_w   = (const float*)d_in[6];
    const float* qkv_b   = (const float*)d_in[7];
    const float* o_w     = (const float*)d_in[8];
    const float* o_b     = (const float*)d_in[9];
    const float* ln2_g   = (const float*)d_in[10];
    const float* ln2_b   = (const float*)d_in[11];
    const float* up_w    = (const float*)d_in[12];
    const float* up_b    = (const float*)d_in[13];
    const float* down_w  = (const float*)d_in[14];
    const float* down_b  = (const float*)d_in[15];
    const float* lnf_g   = (const float*)d_in[16];
    const float* lnf_b   = (const float*)d_in[17];
    const float* lm_b    = (const float*)d_in[18];

    float *h, *nll, *logits_scratch, *part, *pO, *pm, *pl, *smM, *smL;
    __half *xh, *qkvh, *attnh, *mlph, *qkvT, *oT, *upT, *downT, *wteH;
    cudaGetSymbolAddress((void**)&h,    g_h);
    cudaGetSymbolAddress((void**)&xh,   g_xh);
    cudaGetSymbolAddress((void**)&qkvh, g_qkvh);
    cudaGetSymbolAddress((void**)&attnh, g_attnh);
    cudaGetSymbolAddress((void**)&mlph, g_mlph);
    cudaGetSymbolAddress((void**)&nll,  g_nll);
    cudaGetSymbolAddress((void**)&logits_scratch, g_logits);
    cudaGetSymbolAddress((void**)&part, g_part);
    cudaGetSymbolAddress((void**)&pO,   g_pO);
    cudaGetSymbolAddress((void**)&pm,   g_pm);
    cudaGetSymbolAddress((void**)&pl,   g_pl);
    cudaGetSymbolAddress((void**)&smM,  g_sm_m);
    cudaGetSymbolAddress((void**)&smL,  g_sm_l);
    cudaGetSymbolAddress((void**)&qkvT,  g_qkvT);
    cudaGetSymbolAddress((void**)&oT,    g_oT);
    cudaGetSymbolAddress((void**)&upT,   g_upT);
    cudaGetSymbolAddress((void**)&downT, g_downT);
    cudaGetSymbolAddress((void**)&wteH,  g_wteH);

    static bool attr_set = false;
    if (!attr_set) {
        cudaFuncSetAttribute(hgemm_k<0, false, false, true,  false, false>, cudaFuncAttributeMaxDynamicSharedMemorySize, HSMEM);
        cudaFuncSetAttribute(hgemm_k<0, false, false, false, false, true >, cudaFuncAttributeMaxDynamicSharedMemorySize, HSMEM);
        cudaFuncSetAttribute(hgemm_k<1, false, false, true,  false, false>, cudaFuncAttributeMaxDynamicSharedMemorySize, HSMEM);
        cudaFuncSetAttribute(hgemm_k<0, false, true,  false, true,  false>, cudaFuncAttributeMaxDynamicSharedMemorySize, HSMEM);
        attr_set = true;
    }

    float* logits = ((long long)out_size >= NBTV) ? (float*)d_out : logits_scratch;

    transh_k<<<dim3(3 * EE / 64, EE / 64, LL), 256>>>(qkv_w, qkvT, EE, 3 * EE);
    transh_k<<<dim3(EE / 64, EE / 64, LL), 256>>>(o_w, oT, EE, EE);
    transh_k<<<dim3(4 * EE / 64, EE / 64, LL), 256>>>(up_w, upT, EE, 4 * EE);
    transh_k<<<dim3(EE / 64, 4 * EE / 64, LL), 256>>>(down_w, downT, 4 * EE, EE);
    {
        int n = VV * EE / 4;
        halfcpy_k<<<(n + 255) / 256, 256>>>(wte, wteH, n);
    }

    embed_k<<<MM, 256>>>(idx, wte, wpe, h);
    layernorm_k<<<MM, 256>>>(h, ln1_g, ln1_b, xh);   // layer-0 ln1

    for (int l = 0; l < LL; l++) {
        hgemm_k<0, false, false, true, false, false><<<dim3(MM / 128, 3 * EE / 128), 256, HSMEM>>>(
            xh, qkvT + (size_t)l * 3 * EE * EE, qkv_b + (size_t)l * 3 * EE, nullptr,
            qkvh, MM, 3 * EE, EE, nullptr, nullptr);
        flash_attn_k<<<dim3(NU, BB * HH), 128>>>(qkvh, pO, pm, pl, attnh);
        fa_combine_k<<<dim3(12, BB * HH), 256>>>(pO, pm, pl, attnh);
        // o-proj split-K, then fused combine + residual + ln2
        hgemm_k<0, false, false, false, false, true><<<dim3(MM / 128, EE / 128, 2), 256, HSMEM>>>(
            attnh, oT + (size_t)l * EE * EE, nullptr, nullptr,
            part, MM, EE, EE, nullptr, nullptr);
        resln_k<<<MM, 256>>>(h, part, o_b + (size_t)l * EE,
                             ln2_g + (size_t)l * EE, ln2_b + (size_t)l * EE, xh);
        hgemm_k<1, false, false, true, false, false><<<dim3(MM / 128, 4 * EE / 128), 256, HSMEM>>>(
            xh, upT + (size_t)l * 4 * EE * EE, up_b + (size_t)l * 4 * EE, nullptr,
            mlph, MM, 4 * EE, EE, nullptr, nullptr);
        // down-proj split-K, then fused combine + residual + (next ln1 | lnf)
        hgemm_k<0, false, false, false, false, true><<<dim3(MM / 128, EE / 128, 2), 256, HSMEM>>>(
            mlph, downT + (size_t)l * 4 * EE * EE, nullptr, nullptr,
            part, MM, EE, 4 * EE, nullptr, nullptr);
        const float* ng = (l + 1 < LL) ? ln1_g + (size_t)(l + 1) * EE : lnf_g;
        const float* nb = (l + 1 < LL) ? ln1_b + (size_t)(l + 1) * EE : lnf_b;
        resln_k<<<MM, 256>>>(h, part, down_b + (size_t)l * EE, ng, nb, xh);
    }

    hgemm_k<0, false, true, false, true, false><<<dim3(MM / 128, (VV + 127) / 128), 256, HSMEM>>>(
        xh, wteH, lm_b, nullptr, logits, MM, VV, EE, smM, smL);

    nll2_k<<<MM, 128>>>(logits, smM, smL, targets, nll);

    long long extra = (long long)out_size - NBTV;
    if (extra > 0) {
        loss_reduce_k<<<1, 256>>>(nll, (float*)d_out + NBTV, (int)extra);
    } else if ((long long)out_size < NBTV) {
        loss_reduce_k<<<1, 256>>>(nll, (float*)d_out, out_size);
    }
}